// round 2
// baseline (speedup 1.0000x reference)
#include <cuda_runtime.h>
#include <math_constants.h>

// ---------------- problem constants ----------------
#define DM    2048              // d_model
#define QH    32                // q heads
#define KVH   8                 // kv heads
#define HD    64                // head dim
#define GRP   4                 // q heads per kv head
#define BB    2                 // batch
#define TT    2048              // seq len
#define MROWS (BB * TT)         // 4096 rows for all GEMMs

// ---------------- scratch (device globals; no allocation allowed) ----------------
__device__ __align__(16) float g_q[(size_t)MROWS * DM];          // 33.5 MB
__device__ __align__(16) float g_k[(size_t)MROWS * (KVH * HD)];  // 8.4 MB
__device__ __align__(16) float g_v[(size_t)MROWS * (KVH * HD)];  // 8.4 MB
__device__ __align__(16) float g_att[(size_t)MROWS * DM];        // 33.5 MB

// ============================================================================
// Tiled SGEMM: C[M,N] = A[M,K] @ B[K,N] + bias[N]
// BM=BN=128, BK=16, 256 threads, 8x8 per-thread microtile (4+4 split halves).
// M,N,K assumed multiples of tile sizes (true for all our shapes).
// ============================================================================
__global__ void __launch_bounds__(256) sgemm_bias_kernel(
    const float* __restrict__ A, const float* __restrict__ Bm,
    const float* __restrict__ bias, float* __restrict__ C,
    int M, int N, int K)
{
    constexpr int BK = 16;
    __shared__ __align__(16) float As[BK][128];   // transposed A tile
    __shared__ __align__(16) float Bs[BK][128];

    const int tid   = threadIdx.x;
    const int bRow0 = blockIdx.y * 128;
    const int bCol0 = blockIdx.x * 128;

    // A tile loads: 128 rows x 16 k = 512 float4, 2 per thread
    const int aR = tid >> 2;              // 0..63 (and +64)
    const int aC = (tid & 3) * 4;         // 0,4,8,12
    // B tile loads: 16 rows x 128 cols = 512 float4, 2 per thread
    const int bR = tid >> 5;              // 0..7 (and +8)
    const int bC = (tid & 31) * 4;        // 0..124

    const int tx   = tid & 15;
    const int ty   = tid >> 4;
    const int rowA = ty * 4;              // halves: rowA, rowA+64
    const int colB = tx * 4;              // halves: colB, colB+64

    float acc[8][8];
    #pragma unroll
    for (int i = 0; i < 8; i++)
        #pragma unroll
        for (int j = 0; j < 8; j++) acc[i][j] = 0.f;

    for (int k0 = 0; k0 < K; k0 += BK) {
        #pragma unroll
        for (int i = 0; i < 2; i++) {
            int r = aR + i * 64;
            float4 v = *(const float4*)(A + (size_t)(bRow0 + r) * K + k0 + aC);
            As[aC + 0][r] = v.x;
            As[aC + 1][r] = v.y;
            As[aC + 2][r] = v.z;
            As[aC + 3][r] = v.w;
        }
        #pragma unroll
        for (int i = 0; i < 2; i++) {
            int r = bR + i * 8;
            *(float4*)&Bs[r][bC] =
                *(const float4*)(Bm + (size_t)(k0 + r) * N + bCol0 + bC);
        }
        __syncthreads();

        #pragma unroll
        for (int k = 0; k < BK; k++) {
            float ra[8], rb[8];
            *(float4*)&ra[0] = *(const float4*)&As[k][rowA];
            *(float4*)&ra[4] = *(const float4*)&As[k][rowA + 64];
            *(float4*)&rb[0] = *(const float4*)&Bs[k][colB];
            *(float4*)&rb[4] = *(const float4*)&Bs[k][colB + 64];
            #pragma unroll
            for (int i = 0; i < 8; i++)
                #pragma unroll
                for (int j = 0; j < 8; j++)
                    acc[i][j] += ra[i] * rb[j];
        }
        __syncthreads();
    }

    // epilogue: add bias, vectorized store
    #pragma unroll
    for (int ih = 0; ih < 2; ih++) {
        #pragma unroll
        for (int i = 0; i < 4; i++) {
            int r = bRow0 + rowA + ih * 64 + i;
            #pragma unroll
            for (int jh = 0; jh < 2; jh++) {
                int c = bCol0 + colB + jh * 64;
                float4 o;
                o.x = acc[ih * 4 + i][jh * 4 + 0] + bias[c + 0];
                o.y = acc[ih * 4 + i][jh * 4 + 1] + bias[c + 1];
                o.z = acc[ih * 4 + i][jh * 4 + 2] + bias[c + 2];
                o.w = acc[ih * 4 + i][jh * 4 + 3] + bias[c + 3];
                *(float4*)(C + (size_t)r * N + c) = o;
            }
        }
    }
}

// ============================================================================
// Flash-attention (fp32, online softmax), causal, GQA.
// Grid: (T/64 q-tiles, QH heads, B batch). 256 threads.
// Q tile 64x64 in smem; KV streamed in 32-row tiles.
// ============================================================================
__global__ void __launch_bounds__(256) attn_kernel(
    const float* __restrict__ Q, const float* __restrict__ Kg,
    const float* __restrict__ Vg, float* __restrict__ Og)
{
    __shared__ float sQ[64][65];                  // padded: conflict-free by-row reads
    __shared__ float sK[32][65];
    __shared__ __align__(16) float sV[32][64];    // float4 reads, c fixed per iter
    __shared__ float sS[64][33];                  // padded: conflict-free by-row reads
    __shared__ float s_m[64], s_a[64], s_l[64];

    const int qi  = blockIdx.x;
    const int h   = blockIdx.y;
    const int b   = blockIdx.z;
    const int kvh = h >> 2;                       // repeat_interleave: h // GROUP
    const int tid = threadIdx.x;
    const int q0  = qi * 64;

    // load Q tile (columns h*HD .. h*HD+63 of g_q)
    for (int i = tid; i < 64 * 64; i += 256) {
        int r = i >> 6, d = i & 63;
        sQ[r][d] = Q[(size_t)(b * TT + q0 + r) * DM + h * HD + d];
    }

    float row_m = -CUDART_INF_F, row_l = 0.f;     // valid for tid < 64 (row owner)
    float o[16];
    #pragma unroll
    for (int j = 0; j < 16; j++) o[j] = 0.f;

    const int orow = tid >> 2;                    // O partition: 4 threads/row x 16 d
    const int od0  = (tid & 3) * 16;
    const int sr0  = (tid >> 3) * 2;              // S partition: 2 rows x 4 cols
    const int sc0  = (tid & 7) * 4;

    __syncthreads();

    const int kend = (qi + 1) * 64;               // causal: k < q0 + 64
    for (int k0 = 0; k0 < kend; k0 += 32) {
        // load K,V tiles (kv head kvh)
        for (int i = tid; i < 32 * 64; i += 256) {
            int r = i >> 6, d = i & 63;
            size_t g = (size_t)(b * TT + k0 + r) * (KVH * HD) + kvh * HD + d;
            sK[r][d] = Kg[g];
            sV[r][d] = Vg[g];
        }
        __syncthreads();

        // S = (Q K^T) * scale with causal mask
        {
            float acc2[2][4];
            #pragma unroll
            for (int i = 0; i < 2; i++)
                #pragma unroll
                for (int j = 0; j < 4; j++) acc2[i][j] = 0.f;
            #pragma unroll 4
            for (int d = 0; d < 64; d++) {
                float qa = sQ[sr0][d];
                float qb = sQ[sr0 + 1][d];
                #pragma unroll
                for (int j = 0; j < 4; j++) {
                    float kv = sK[sc0 + j][d];
                    acc2[0][j] += qa * kv;
                    acc2[1][j] += qb * kv;
                }
            }
            #pragma unroll
            for (int i = 0; i < 2; i++)
                #pragma unroll
                for (int j = 0; j < 4; j++) {
                    int qg = q0 + sr0 + i, kg = k0 + sc0 + j;
                    sS[sr0 + i][sc0 + j] =
                        (kg <= qg) ? acc2[i][j] * 0.125f : -CUDART_INF_F;
                }
        }
        __syncthreads();

        // phase A: per-row running max + rescale factor (one owner thread per row)
        if (tid < 64) {
            float m = row_m;
            #pragma unroll 8
            for (int c = 0; c < 32; c++) m = fmaxf(m, sS[tid][c]);
            s_a[tid] = __expf(row_m - m);   // -inf -> 0 on first tile; fully-masked tile -> 1
            s_m[tid] = m;
            row_m = m;
        }
        __syncthreads();

        // phase B: exponentiate in parallel (256 threads, 8 elems each)
        {
            const int r  = tid >> 2;
            const int cb = (tid & 3) * 8;
            const float m = s_m[r];
            #pragma unroll
            for (int j = 0; j < 8; j++)
                sS[r][cb + j] = __expf(sS[r][cb + j] - m);   // masked: exp(-inf)=0
        }
        __syncthreads();

        // phase C: l update (row owner) — concurrent with O update (both read-only on sS)
        if (tid < 64) {
            float s = 0.f;
            #pragma unroll 8
            for (int c = 0; c < 32; c++) s += sS[tid][c];
            row_l = row_l * s_a[tid] + s;
        }
        // O update: o = o * alpha + P @ V (each thread: 1 row x 16 d-cols)
        {
            const float a = s_a[orow];
            #pragma unroll
            for (int j = 0; j < 16; j++) o[j] *= a;
            #pragma unroll 4
            for (int c = 0; c < 32; c++) {
                const float p = sS[orow][c];
                const float4* vp = (const float4*)&sV[c][od0];
                #pragma unroll
                for (int jj = 0; jj < 4; jj++) {
                    float4 v4 = vp[jj];
                    o[jj * 4 + 0] += p * v4.x;
                    o[jj * 4 + 1] += p * v4.y;
                    o[jj * 4 + 2] += p * v4.z;
                    o[jj * 4 + 3] += p * v4.w;
                }
            }
        }
        __syncthreads();   // protect sS/sK/sV for next iteration
    }

    if (tid < 64) s_l[tid] = row_l;
    __syncthreads();

    // normalize and write [B,T,QH*HD]
    {
        const float inv = 1.0f / s_l[orow];
        float* dst = &Og[(size_t)(b * TT + q0 + orow) * DM + h * HD + od0];
        #pragma unroll
        for (int jj = 0; jj < 4; jj++) {
            float4 v4;
            v4.x = o[jj * 4 + 0] * inv;
            v4.y = o[jj * 4 + 1] * inv;
            v4.z = o[jj * 4 + 2] * inv;
            v4.w = o[jj * 4 + 3] * inv;
            *(float4*)(dst + jj * 4) = v4;
        }
    }
}

// ============================================================================
// kernel_launch: 5 graph-capturable launches, no allocations, no syncs.
// ============================================================================
extern "C" void kernel_launch(void* const* d_in, const int* in_sizes, int n_in,
                              void* d_out, int out_size)
{
    const float* x  = (const float*)d_in[0];
    const float* Wq = (const float*)d_in[1];
    const float* bq = (const float*)d_in[2];
    const float* Wk = (const float*)d_in[3];
    const float* bk = (const float*)d_in[4];
    const float* Wv = (const float*)d_in[5];
    const float* bv = (const float*)d_in[6];
    const float* Wo = (const float*)d_in[7];
    const float* bo = (const float*)d_in[8];
    float* out = (float*)d_out;

    float *q, *k, *v, *att;
    cudaGetSymbolAddress((void**)&q,   g_q);
    cudaGetSymbolAddress((void**)&k,   g_k);
    cudaGetSymbolAddress((void**)&v,   g_v);
    cudaGetSymbolAddress((void**)&att, g_att);

    dim3 blk(256);

    // Q/K/V projections
    sgemm_bias_kernel<<<dim3(DM / 128, MROWS / 128), blk>>>(
        x, Wq, bq, q, MROWS, DM, DM);
    sgemm_bias_kernel<<<dim3((KVH * HD) / 128, MROWS / 128), blk>>>(
        x, Wk, bk, k, MROWS, KVH * HD, DM);
    sgemm_bias_kernel<<<dim3((KVH * HD) / 128, MROWS / 128), blk>>>(
        x, Wv, bv, v, MROWS, KVH * HD, DM);

    // causal GQA attention
    attn_kernel<<<dim3(TT / 64, QH, BB), blk>>>(q, k, v, att);

    // output projection
    sgemm_bias_kernel<<<dim3(DM / 128, MROWS / 128), blk>>>(
        att, Wo, bo, out, MROWS, DM, DM);
}

// round 3
// speedup vs baseline: 1.2123x; 1.2123x over previous
#include <cuda_runtime.h>
#include <math_constants.h>
#include <stdint.h>

// ---------------- problem constants ----------------
#define DM    2048              // d_model
#define QH    32                // q heads
#define KVH   8                 // kv heads
#define HD    64                // head dim
#define BB    2                 // batch
#define TT    2048              // seq len
#define MROWS (BB * TT)         // 4096 rows for all GEMMs

// ---------------- scratch (device globals; no allocation allowed) ----------------
__device__ __align__(16) float g_q[(size_t)MROWS * DM];
__device__ __align__(16) float g_k[(size_t)MROWS * (KVH * HD)];
__device__ __align__(16) float g_v[(size_t)MROWS * (KVH * HD)];
__device__ __align__(16) float g_att[(size_t)MROWS * DM];

// ---------------- tf32 helpers ----------------
__device__ __forceinline__ float f2t(float x) {          // round-to-nearest tf32, as float
    uint32_t u;
    asm("cvt.rna.tf32.f32 %0, %1;" : "=r"(u) : "f"(x));
    return __uint_as_float(u);
}

#define MMA_TF32(cc, a0, a1, a2, a3, b0, b1)                               \
    asm volatile(                                                          \
        "mma.sync.aligned.m16n8k8.row.col.f32.tf32.tf32.f32 "              \
        "{%0,%1,%2,%3}, {%4,%5,%6,%7}, {%8,%9}, {%0,%1,%2,%3};"            \
        : "+f"(cc[0]), "+f"(cc[1]), "+f"(cc[2]), "+f"(cc[3])               \
        : "r"(a0), "r"(a1), "r"(a2), "r"(a3), "r"(b0), "r"(b1))

// ============================================================================
// 3xTF32 GEMM: C[M,N] = A[M,K] @ B[K,N] + bias[N]
// 128x128x16 block tile, 256 threads = 8 warps (4m x 2n), warp tile 32x64.
// Error-corrected: each operand split hi/lo tf32; D += Ah*Bh + Ah*Bl + Al*Bh.
// ============================================================================
__global__ void __launch_bounds__(256) gemm3t_bias_kernel(
    const float* __restrict__ A, const float* __restrict__ Bm,
    const float* __restrict__ bias, float* __restrict__ C,
    int M, int N, int K)
{
    __shared__ float Ah[16][132], Al[16][132];   // transposed A tile [k][m]
    __shared__ float Bh[16][132], Bl[16][132];   // B tile [k][n]

    const int tid  = threadIdx.x;
    const int lane = tid & 31;
    const int w    = tid >> 5;
    const int g    = lane >> 2;          // group id (0..7)
    const int t    = lane & 3;           // thread-in-group (0..3)
    const int mw   = (w >> 1) * 32;      // warp m offset within block tile
    const int nw   = (w & 1) * 64;       // warp n offset

    const int bRow0 = blockIdx.y * 128;
    const int bCol0 = blockIdx.x * 128;

    // loader indices
    const int aR = tid >> 2;             // 0..63  (rows aR, aR+64)
    const int aC = (tid & 3) * 4;        // k cols 0,4,8,12
    const int bR = tid >> 4;             // 0..15  (k row)
    const int bC = (tid & 15) * 8;       // n cols (two float4: bC, bC+4)

    float4 pa0, pa1, pb0, pb1;
    // preload first tile
    pa0 = *(const float4*)(A + (size_t)(bRow0 + aR) * K + aC);
    pa1 = *(const float4*)(A + (size_t)(bRow0 + aR + 64) * K + aC);
    pb0 = *(const float4*)(Bm + (size_t)bR * N + bCol0 + bC);
    pb1 = *(const float4*)(Bm + (size_t)bR * N + bCol0 + bC + 4);

    float acc[2][8][4];
    #pragma unroll
    for (int i = 0; i < 2; i++)
        #pragma unroll
        for (int j = 0; j < 8; j++)
            #pragma unroll
            for (int q = 0; q < 4; q++) acc[i][j][q] = 0.f;

    for (int k0 = 0; k0 < K; k0 += 16) {
        __syncthreads();                 // previous compute done; smem reusable
        // store A tile (transposed, split hi/lo)
        {
            float va[4] = {pa0.x, pa0.y, pa0.z, pa0.w};
            #pragma unroll
            for (int j = 0; j < 4; j++) {
                float h = f2t(va[j]);
                Ah[aC + j][aR] = h;
                Al[aC + j][aR] = f2t(va[j] - h);
            }
            float vb[4] = {pa1.x, pa1.y, pa1.z, pa1.w};
            #pragma unroll
            for (int j = 0; j < 4; j++) {
                float h = f2t(vb[j]);
                Ah[aC + j][aR + 64] = h;
                Al[aC + j][aR + 64] = f2t(vb[j] - h);
            }
        }
        // store B tile (split hi/lo), vectorized
        {
            float vb[8] = {pb0.x, pb0.y, pb0.z, pb0.w, pb1.x, pb1.y, pb1.z, pb1.w};
            float4 h4, l4;
            h4.x = f2t(vb[0]); l4.x = f2t(vb[0] - h4.x);
            h4.y = f2t(vb[1]); l4.y = f2t(vb[1] - h4.y);
            h4.z = f2t(vb[2]); l4.z = f2t(vb[2] - h4.z);
            h4.w = f2t(vb[3]); l4.w = f2t(vb[3] - h4.w);
            *(float4*)&Bh[bR][bC] = h4;
            *(float4*)&Bl[bR][bC] = l4;
            h4.x = f2t(vb[4]); l4.x = f2t(vb[4] - h4.x);
            h4.y = f2t(vb[5]); l4.y = f2t(vb[5] - h4.y);
            h4.z = f2t(vb[6]); l4.z = f2t(vb[6] - h4.z);
            h4.w = f2t(vb[7]); l4.w = f2t(vb[7] - h4.w);
            *(float4*)&Bh[bR][bC + 4] = h4;
            *(float4*)&Bl[bR][bC + 4] = l4;
        }
        __syncthreads();

        // prefetch next tile while computing
        if (k0 + 16 < K) {
            pa0 = *(const float4*)(A + (size_t)(bRow0 + aR) * K + k0 + 16 + aC);
            pa1 = *(const float4*)(A + (size_t)(bRow0 + aR + 64) * K + k0 + 16 + aC);
            pb0 = *(const float4*)(Bm + (size_t)(k0 + 16 + bR) * N + bCol0 + bC);
            pb1 = *(const float4*)(Bm + (size_t)(k0 + 16 + bR) * N + bCol0 + bC + 4);
        }

        #pragma unroll
        for (int ks = 0; ks < 2; ks++) {
            const int kt = ks * 8;
            uint32_t ah[2][4], alr[2][4];
            #pragma unroll
            for (int mt = 0; mt < 2; mt++) {
                int r = mw + mt * 16;
                ah[mt][0]  = __float_as_uint(Ah[kt + t][r + g]);
                ah[mt][1]  = __float_as_uint(Ah[kt + t][r + g + 8]);
                ah[mt][2]  = __float_as_uint(Ah[kt + t + 4][r + g]);
                ah[mt][3]  = __float_as_uint(Ah[kt + t + 4][r + g + 8]);
                alr[mt][0] = __float_as_uint(Al[kt + t][r + g]);
                alr[mt][1] = __float_as_uint(Al[kt + t][r + g + 8]);
                alr[mt][2] = __float_as_uint(Al[kt + t + 4][r + g]);
                alr[mt][3] = __float_as_uint(Al[kt + t + 4][r + g + 8]);
            }
            #pragma unroll
            for (int nt = 0; nt < 8; nt++) {
                int c = nw + nt * 8;
                uint32_t bh0 = __float_as_uint(Bh[kt + t][c + g]);
                uint32_t bh1 = __float_as_uint(Bh[kt + t + 4][c + g]);
                uint32_t bl0 = __float_as_uint(Bl[kt + t][c + g]);
                uint32_t bl1 = __float_as_uint(Bl[kt + t + 4][c + g]);
                #pragma unroll
                for (int mt = 0; mt < 2; mt++) {
                    MMA_TF32(acc[mt][nt], ah[mt][0], ah[mt][1], ah[mt][2], ah[mt][3], bh0, bh1);
                    MMA_TF32(acc[mt][nt], ah[mt][0], ah[mt][1], ah[mt][2], ah[mt][3], bl0, bl1);
                    MMA_TF32(acc[mt][nt], alr[mt][0], alr[mt][1], alr[mt][2], alr[mt][3], bh0, bh1);
                }
            }
        }
    }

    // epilogue: bias + float2 stores
    #pragma unroll
    for (int mt = 0; mt < 2; mt++) {
        #pragma unroll
        for (int nt = 0; nt < 8; nt++) {
            int row = bRow0 + mw + mt * 16 + g;
            int col = bCol0 + nw + nt * 8 + 2 * t;
            float b0v = bias[col], b1v = bias[col + 1];
            float2 o0 = {acc[mt][nt][0] + b0v, acc[mt][nt][1] + b1v};
            float2 o1 = {acc[mt][nt][2] + b0v, acc[mt][nt][3] + b1v};
            *(float2*)(C + (size_t)row * N + col)       = o0;
            *(float2*)(C + (size_t)(row + 8) * N + col) = o1;
        }
    }
}

// ============================================================================
// Tensor-core flash attention (3xTF32 MMA), causal, GQA.
// Block: 64 q-rows x 1 head; KV streamed 32 rows/tile. 256 threads = 8 warps.
// Warps: mw = w>>1 (m16), nw = w&1.  S tile: warp m16 x n16. O: warp m16 x n32.
// Softmax phases identical in structure to the validated fp32 kernel.
// Dynamic smem layout (floats):
//   sQh[64][65], sQl[64][65], sKh[32][65], sKl[32][65], sVh[32][65], sVl[32][65],
//   sS[64][33] (raw S, then exp-hi in place), sSl[64][33] (exp-lo),
//   s_m[64], s_a[64], s_l[64]
// ============================================================================
#define OQH 0
#define OQL (OQH + 64 * 65)
#define OKH (OQL + 64 * 65)
#define OKL (OKH + 32 * 65)
#define OVH (OKL + 32 * 65)
#define OVL (OVH + 32 * 65)
#define OS  (OVL + 32 * 65)
#define OSL (OS + 64 * 33)
#define OM  (OSL + 64 * 33)
#define OA  (OM + 64)
#define OL  (OA + 64)
#define ATT_SMEM_FLOATS (OL + 64)
#define ATT_SMEM_BYTES  (ATT_SMEM_FLOATS * 4)

__global__ void __launch_bounds__(256) attn_mma_kernel(
    const float* __restrict__ Q, const float* __restrict__ Kg,
    const float* __restrict__ Vg, float* __restrict__ Og)
{
    extern __shared__ float sm[];
    float* sQh = sm + OQH;  float* sQl = sm + OQL;
    float* sKh = sm + OKH;  float* sKl = sm + OKL;
    float* sVh = sm + OVH;  float* sVl = sm + OVL;
    float* sS  = sm + OS;   float* sSl = sm + OSL;
    float* s_m = sm + OM;   float* s_a = sm + OA;  float* s_l = sm + OL;

    const int qi  = blockIdx.x;
    const int h   = blockIdx.y;
    const int b   = blockIdx.z;
    const int kvh = h >> 2;              // repeat_interleave: h // GROUP
    const int tid = threadIdx.x;
    const int q0  = qi * 64;

    const int lane = tid & 31;
    const int w    = tid >> 5;
    const int g    = lane >> 2;
    const int t    = lane & 3;
    const int mw16 = (w >> 1) * 16;      // warp m offset (S and O rows)
    const int nw   = (w & 1);

    // load Q tile (64x64), split hi/lo
    for (int i = tid; i < 64 * 64; i += 256) {
        int r = i >> 6, d = i & 63;
        float v = Q[(size_t)(b * TT + q0 + r) * DM + h * HD + d];
        float hv = f2t(v);
        sQh[r * 65 + d] = hv;
        sQl[r * 65 + d] = f2t(v - hv);
    }

    float row_m = -CUDART_INF_F, row_l = 0.f;   // valid for tid < 64

    float o[4][4];                        // O accum: 4 n8-tiles x 4 regs
    #pragma unroll
    for (int i = 0; i < 4; i++)
        #pragma unroll
        for (int j = 0; j < 4; j++) o[i][j] = 0.f;

    const int kend = q0 + 64;            // causal
    for (int k0 = 0; k0 < kend; k0 += 32) {
        // load K,V tiles (32 x 64), split hi/lo
        for (int i = tid; i < 32 * 64; i += 256) {
            int r = i >> 6, d = i & 63;
            size_t gidx = (size_t)(b * TT + k0 + r) * (KVH * HD) + kvh * HD + d;
            float kv = Kg[gidx];
            float vv = Vg[gidx];
            float kh = f2t(kv), vh = f2t(vv);
            sKh[r * 65 + d] = kh;  sKl[r * 65 + d] = f2t(kv - kh);
            sVh[r * 65 + d] = vh;  sVl[r * 65 + d] = f2t(vv - vh);
        }
        __syncthreads();                 // (1) tiles ready

        // S = Q @ K^T via 3xTF32 mma: warp computes m16 x n16 (2 n8 tiles)
        {
            float sc[2][4];
            #pragma unroll
            for (int tn = 0; tn < 2; tn++)
                #pragma unroll
                for (int j = 0; j < 4; j++) sc[tn][j] = 0.f;

            #pragma unroll
            for (int ks = 0; ks < 8; ks++) {
                const int kt = ks * 8;
                uint32_t a0 = __float_as_uint(sQh[(mw16 + g) * 65 + kt + t]);
                uint32_t a1 = __float_as_uint(sQh[(mw16 + g + 8) * 65 + kt + t]);
                uint32_t a2 = __float_as_uint(sQh[(mw16 + g) * 65 + kt + t + 4]);
                uint32_t a3 = __float_as_uint(sQh[(mw16 + g + 8) * 65 + kt + t + 4]);
                uint32_t l0 = __float_as_uint(sQl[(mw16 + g) * 65 + kt + t]);
                uint32_t l1 = __float_as_uint(sQl[(mw16 + g + 8) * 65 + kt + t]);
                uint32_t l2 = __float_as_uint(sQl[(mw16 + g) * 65 + kt + t + 4]);
                uint32_t l3 = __float_as_uint(sQl[(mw16 + g + 8) * 65 + kt + t + 4]);
                #pragma unroll
                for (int tn = 0; tn < 2; tn++) {
                    int n0 = nw * 16 + tn * 8;
                    uint32_t bh0 = __float_as_uint(sKh[(n0 + g) * 65 + kt + t]);
                    uint32_t bh1 = __float_as_uint(sKh[(n0 + g) * 65 + kt + t + 4]);
                    uint32_t bl0 = __float_as_uint(sKl[(n0 + g) * 65 + kt + t]);
                    uint32_t bl1 = __float_as_uint(sKl[(n0 + g) * 65 + kt + t + 4]);
                    MMA_TF32(sc[tn], a0, a1, a2, a3, bh0, bh1);
                    MMA_TF32(sc[tn], a0, a1, a2, a3, bl0, bl1);
                    MMA_TF32(sc[tn], l0, l1, l2, l3, bh0, bh1);
                }
            }
            // masked, scaled store to sS
            #pragma unroll
            for (int tn = 0; tn < 2; tn++) {
                int col = nw * 16 + tn * 8 + 2 * t;
                int r0 = mw16 + g, r1 = r0 + 8;
                int qg0 = q0 + r0, qg1 = q0 + r1;
                int kg0 = k0 + col, kg1 = kg0 + 1;
                sS[r0 * 33 + col]     = (kg0 <= qg0) ? sc[tn][0] * 0.125f : -CUDART_INF_F;
                sS[r0 * 33 + col + 1] = (kg1 <= qg0) ? sc[tn][1] * 0.125f : -CUDART_INF_F;
                sS[r1 * 33 + col]     = (kg0 <= qg1) ? sc[tn][2] * 0.125f : -CUDART_INF_F;
                sS[r1 * 33 + col + 1] = (kg1 <= qg1) ? sc[tn][3] * 0.125f : -CUDART_INF_F;
            }
        }
        __syncthreads();                 // (2) sS complete

        // phase A: per-row running max + rescale factor
        if (tid < 64) {
            float m = row_m;
            #pragma unroll 8
            for (int c = 0; c < 32; c++) m = fmaxf(m, sS[tid * 33 + c]);
            s_a[tid] = __expf(row_m - m);
            s_m[tid] = m;
            row_m = m;
        }
        __syncthreads();                 // (3)

        // phase B: exponentiate + tf32 split (hi in place, lo to sSl)
        {
            const int r  = tid >> 2;
            const int cb = (tid & 3) * 8;
            const float m = s_m[r];
            #pragma unroll
            for (int j = 0; j < 8; j++) {
                float e  = __expf(sS[r * 33 + cb + j] - m);
                float hv = f2t(e);
                sS[r * 33 + cb + j]  = hv;
                sSl[r * 33 + cb + j] = f2t(e - hv);
            }
        }
        __syncthreads();                 // (4)

        // phase C: l update (exact sum = hi + lo)
        if (tid < 64) {
            float s = 0.f;
            #pragma unroll 8
            for (int c = 0; c < 32; c++)
                s += sS[tid * 33 + c] + sSl[tid * 33 + c];
            row_l = row_l * s_a[tid] + s;
        }
        // O rescale + O += P @ V (3xTF32)
        {
            const float a0f = s_a[mw16 + g];
            const float a1f = s_a[mw16 + g + 8];
            #pragma unroll
            for (int tn = 0; tn < 4; tn++) {
                o[tn][0] *= a0f; o[tn][1] *= a0f;
                o[tn][2] *= a1f; o[tn][3] *= a1f;
            }
            #pragma unroll
            for (int ks = 0; ks < 4; ks++) {
                const int kt = ks * 8;
                uint32_t a0 = __float_as_uint(sS[(mw16 + g) * 33 + kt + t]);
                uint32_t a1 = __float_as_uint(sS[(mw16 + g + 8) * 33 + kt + t]);
                uint32_t a2 = __float_as_uint(sS[(mw16 + g) * 33 + kt + t + 4]);
                uint32_t a3 = __float_as_uint(sS[(mw16 + g + 8) * 33 + kt + t + 4]);
                uint32_t p0 = __float_as_uint(sSl[(mw16 + g) * 33 + kt + t]);
                uint32_t p1 = __float_as_uint(sSl[(mw16 + g + 8) * 33 + kt + t]);
                uint32_t p2 = __float_as_uint(sSl[(mw16 + g) * 33 + kt + t + 4]);
                uint32_t p3 = __float_as_uint(sSl[(mw16 + g + 8) * 33 + kt + t + 4]);
                #pragma unroll
                for (int tn = 0; tn < 4; tn++) {
                    int n0 = nw * 32 + tn * 8;
                    uint32_t bh0 = __float_as_uint(sVh[(kt + t) * 65 + n0 + g]);
                    uint32_t bh1 = __float_as_uint(sVh[(kt + t + 4) * 65 + n0 + g]);
                    uint32_t bl0 = __float_as_uint(sVl[(kt + t) * 65 + n0 + g]);
                    uint32_t bl1 = __float_as_uint(sVl[(kt + t + 4) * 65 + n0 + g]);
                    MMA_TF32(o[tn], a0, a1, a2, a3, bh0, bh1);
                    MMA_TF32(o[tn], a0, a1, a2, a3, bl0, bl1);
                    MMA_TF32(o[tn], p0, p1, p2, p3, bh0, bh1);
                }
            }
        }
        __syncthreads();                 // (5) PV done; smem reusable
    }

    if (tid < 64) s_l[tid] = row_l;
    __syncthreads();

    // normalize + write [B,T,QH*HD]
    {
        const int r0 = mw16 + g, r1 = r0 + 8;
        const float inv0 = 1.0f / s_l[r0];
        const float inv1 = 1.0f / s_l[r1];
        #pragma unroll
        for (int tn = 0; tn < 4; tn++) {
            int c = nw * 32 + tn * 8 + 2 * t;
            float2 v0 = {o[tn][0] * inv0, o[tn][1] * inv0};
            float2 v1 = {o[tn][2] * inv1, o[tn][3] * inv1};
            *(float2*)(Og + (size_t)(b * TT + q0 + r0) * DM + h * HD + c) = v0;
            *(float2*)(Og + (size_t)(b * TT + q0 + r1) * DM + h * HD + c) = v1;
        }
    }
}

// ============================================================================
// kernel_launch: 5 graph-capturable launches, no allocations, no syncs.
// ============================================================================
extern "C" void kernel_launch(void* const* d_in, const int* in_sizes, int n_in,
                              void* d_out, int out_size)
{
    const float* x  = (const float*)d_in[0];
    const float* Wq = (const float*)d_in[1];
    const float* bq = (const float*)d_in[2];
    const float* Wk = (const float*)d_in[3];
    const float* bk = (const float*)d_in[4];
    const float* Wv = (const float*)d_in[5];
    const float* bv = (const float*)d_in[6];
    const float* Wo = (const float*)d_in[7];
    const float* bo = (const float*)d_in[8];
    float* out = (float*)d_out;

    float *q, *k, *v, *att;
    cudaGetSymbolAddress((void**)&q,   g_q);
    cudaGetSymbolAddress((void**)&k,   g_k);
    cudaGetSymbolAddress((void**)&v,   g_v);
    cudaGetSymbolAddress((void**)&att, g_att);

    // dynamic smem opt-in (idempotent; host attribute call, not an allocation)
    cudaFuncSetAttribute(attn_mma_kernel,
                         cudaFuncAttributeMaxDynamicSharedMemorySize, ATT_SMEM_BYTES);

    dim3 blk(256);

    // Q/K/V projections (3xTF32)
    gemm3t_bias_kernel<<<dim3(DM / 128, MROWS / 128), blk>>>(
        x, Wq, bq, q, MROWS, DM, DM);
    gemm3t_bias_kernel<<<dim3((KVH * HD) / 128, MROWS / 128), blk>>>(
        x, Wk, bk, k, MROWS, KVH * HD, DM);
    gemm3t_bias_kernel<<<dim3((KVH * HD) / 128, MROWS / 128), blk>>>(
        x, Wv, bv, v, MROWS, KVH * HD, DM);

    // causal GQA attention (tensor-core)
    attn_mma_kernel<<<dim3(TT / 64, QH, BB), blk, ATT_SMEM_BYTES>>>(q, k, v, att);

    // output projection (3xTF32)
    gemm3t_bias_kernel<<<dim3(DM / 128, MROWS / 128), blk>>>(
        att, Wo, bo, out, MROWS, DM, DM);
}

// round 5
// speedup vs baseline: 1.8796x; 1.5505x over previous
#include <cuda_runtime.h>
#include <math_constants.h>
#include <stdint.h>

// ---------------- problem constants ----------------
#define DM    2048              // d_model
#define QH    32                // q heads
#define KVH   8                 // kv heads
#define HD    64                // head dim
#define BB    2                 // batch
#define TT    2048              // seq len
#define MROWS (BB * TT)         // 4096 rows for all GEMMs

// ---------------- scratch (device globals; no allocation allowed) ----------------
__device__ __align__(16) float g_q[(size_t)MROWS * DM];
__device__ __align__(16) float g_k[(size_t)MROWS * (KVH * HD)];
__device__ __align__(16) float g_v[(size_t)MROWS * (KVH * HD)];
__device__ __align__(16) float g_att[(size_t)MROWS * DM];

// ---------------- tf32 helpers ----------------
__device__ __forceinline__ float f2t(float x) {          // round-to-nearest tf32, as float
    uint32_t u;
    asm("cvt.rna.tf32.f32 %0, %1;" : "=r"(u) : "f"(x));
    return __uint_as_float(u);
}

#define MMA_TF32(cc, a0, a1, a2, a3, b0, b1)                               \
    asm volatile(                                                          \
        "mma.sync.aligned.m16n8k8.row.col.f32.tf32.tf32.f32 "              \
        "{%0,%1,%2,%3}, {%4,%5,%6,%7}, {%8,%9}, {%0,%1,%2,%3};"            \
        : "+f"(cc[0]), "+f"(cc[1]), "+f"(cc[2]), "+f"(cc[3])               \
        : "r"(a0), "r"(a1), "r"(a2), "r"(a3), "r"(b0), "r"(b1))

// ============================================================================
// 3xTF32 GEMM: C[M,N] = A[M,K] @ B[K,N] + bias[N]   (unchanged from R3)
// ============================================================================
__global__ void __launch_bounds__(256) gemm3t_bias_kernel(
    const float* __restrict__ A, const float* __restrict__ Bm,
    const float* __restrict__ bias, float* __restrict__ C,
    int M, int N, int K)
{
    __shared__ float Ah[16][132], Al[16][132];   // transposed A tile [k][m]
    __shared__ float Bh[16][132], Bl[16][132];   // B tile [k][n]

    const int tid  = threadIdx.x;
    const int lane = tid & 31;
    const int w    = tid >> 5;
    const int g    = lane >> 2;
    const int t    = lane & 3;
    const int mw   = (w >> 1) * 32;
    const int nw   = (w & 1) * 64;

    const int bRow0 = blockIdx.y * 128;
    const int bCol0 = blockIdx.x * 128;

    const int aR = tid >> 2;
    const int aC = (tid & 3) * 4;
    const int bR = tid >> 4;
    const int bC = (tid & 15) * 8;

    float4 pa0, pa1, pb0, pb1;
    pa0 = *(const float4*)(A + (size_t)(bRow0 + aR) * K + aC);
    pa1 = *(const float4*)(A + (size_t)(bRow0 + aR + 64) * K + aC);
    pb0 = *(const float4*)(Bm + (size_t)bR * N + bCol0 + bC);
    pb1 = *(const float4*)(Bm + (size_t)bR * N + bCol0 + bC + 4);

    float acc[2][8][4];
    #pragma unroll
    for (int i = 0; i < 2; i++)
        #pragma unroll
        for (int j = 0; j < 8; j++)
            #pragma unroll
            for (int q = 0; q < 4; q++) acc[i][j][q] = 0.f;

    for (int k0 = 0; k0 < K; k0 += 16) {
        __syncthreads();
        {
            float va[4] = {pa0.x, pa0.y, pa0.z, pa0.w};
            #pragma unroll
            for (int j = 0; j < 4; j++) {
                float h = f2t(va[j]);
                Ah[aC + j][aR] = h;
                Al[aC + j][aR] = f2t(va[j] - h);
            }
            float vb[4] = {pa1.x, pa1.y, pa1.z, pa1.w};
            #pragma unroll
            for (int j = 0; j < 4; j++) {
                float h = f2t(vb[j]);
                Ah[aC + j][aR + 64] = h;
                Al[aC + j][aR + 64] = f2t(vb[j] - h);
            }
        }
        {
            float vb[8] = {pb0.x, pb0.y, pb0.z, pb0.w, pb1.x, pb1.y, pb1.z, pb1.w};
            float4 h4, l4;
            h4.x = f2t(vb[0]); l4.x = f2t(vb[0] - h4.x);
            h4.y = f2t(vb[1]); l4.y = f2t(vb[1] - h4.y);
            h4.z = f2t(vb[2]); l4.z = f2t(vb[2] - h4.z);
            h4.w = f2t(vb[3]); l4.w = f2t(vb[3] - h4.w);
            *(float4*)&Bh[bR][bC] = h4;
            *(float4*)&Bl[bR][bC] = l4;
            h4.x = f2t(vb[4]); l4.x = f2t(vb[4] - h4.x);
            h4.y = f2t(vb[5]); l4.y = f2t(vb[5] - h4.y);
            h4.z = f2t(vb[6]); l4.z = f2t(vb[6] - h4.z);
            h4.w = f2t(vb[7]); l4.w = f2t(vb[7] - h4.w);
            *(float4*)&Bh[bR][bC + 4] = h4;
            *(float4*)&Bl[bR][bC + 4] = l4;
        }
        __syncthreads();

        if (k0 + 16 < K) {
            pa0 = *(const float4*)(A + (size_t)(bRow0 + aR) * K + k0 + 16 + aC);
            pa1 = *(const float4*)(A + (size_t)(bRow0 + aR + 64) * K + k0 + 16 + aC);
            pb0 = *(const float4*)(Bm + (size_t)(k0 + 16 + bR) * N + bCol0 + bC);
            pb1 = *(const float4*)(Bm + (size_t)(k0 + 16 + bR) * N + bCol0 + bC + 4);
        }

        #pragma unroll
        for (int ks = 0; ks < 2; ks++) {
            const int kt = ks * 8;
            uint32_t ah[2][4], alr[2][4];
            #pragma unroll
            for (int mt = 0; mt < 2; mt++) {
                int r = mw + mt * 16;
                ah[mt][0]  = __float_as_uint(Ah[kt + t][r + g]);
                ah[mt][1]  = __float_as_uint(Ah[kt + t][r + g + 8]);
                ah[mt][2]  = __float_as_uint(Ah[kt + t + 4][r + g]);
                ah[mt][3]  = __float_as_uint(Ah[kt + t + 4][r + g + 8]);
                alr[mt][0] = __float_as_uint(Al[kt + t][r + g]);
                alr[mt][1] = __float_as_uint(Al[kt + t][r + g + 8]);
                alr[mt][2] = __float_as_uint(Al[kt + t + 4][r + g]);
                alr[mt][3] = __float_as_uint(Al[kt + t + 4][r + g + 8]);
            }
            #pragma unroll
            for (int nt = 0; nt < 8; nt++) {
                int c = nw + nt * 8;
                uint32_t bh0 = __float_as_uint(Bh[kt + t][c + g]);
                uint32_t bh1 = __float_as_uint(Bh[kt + t + 4][c + g]);
                uint32_t bl0 = __float_as_uint(Bl[kt + t][c + g]);
                uint32_t bl1 = __float_as_uint(Bl[kt + t + 4][c + g]);
                #pragma unroll
                for (int mt = 0; mt < 2; mt++) {
                    MMA_TF32(acc[mt][nt], ah[mt][0], ah[mt][1], ah[mt][2], ah[mt][3], bh0, bh1);
                    MMA_TF32(acc[mt][nt], ah[mt][0], ah[mt][1], ah[mt][2], ah[mt][3], bl0, bl1);
                    MMA_TF32(acc[mt][nt], alr[mt][0], alr[mt][1], alr[mt][2], alr[mt][3], bh0, bh1);
                }
            }
        }
    }

    #pragma unroll
    for (int mt = 0; mt < 2; mt++) {
        #pragma unroll
        for (int nt = 0; nt < 8; nt++) {
            int row = bRow0 + mw + mt * 16 + g;
            int col = bCol0 + nw + nt * 8 + 2 * t;
            float b0v = bias[col], b1v = bias[col + 1];
            float2 o0 = {acc[mt][nt][0] + b0v, acc[mt][nt][1] + b1v};
            float2 o1 = {acc[mt][nt][2] + b0v, acc[mt][nt][3] + b1v};
            *(float2*)(C + (size_t)row * N + col)       = o0;
            *(float2*)(C + (size_t)(row + 8) * N + col) = o1;
        }
    }
}

// ============================================================================
// Tensor-core flash attention v2 (3xTF32 QK^T, 2xTF32 PV), causal, GQA.
// Q tile 64 rows (held as per-warp register fragments), KV tile 64 rows.
// 256 threads = 8 warps: mw=(w>>1)*16 (4 m-groups), nw=w&1 (2 n32-groups).
// Conflict-free smem strides: K/P/Sraw stride 68 (frag addr (4g+t)%32 distinct),
// V stride 72 (frag addr (8t+g)%32 distinct).
// ============================================================================
#define KST 68
#define VST 72
#define SKH 0
#define SKL (SKH + 64 * KST)
#define SVH (SKL + 64 * KST)
#define SVL (SVH + 64 * VST)
#define SP_ (SVL + 64 * VST)
#define SSR (SP_ + 64 * KST)
#define SM_ (SSR + 64 * KST)
#define SA_ (SM_ + 64)
#define SL_ (SA_ + 64)
#define ATT_SMEM_FLOATS (SL_ + 64)
#define ATT_SMEM_BYTES  (ATT_SMEM_FLOATS * 4)

__global__ void __launch_bounds__(256, 2) attn_mma_kernel(
    const float* __restrict__ Q, const float* __restrict__ Kg,
    const float* __restrict__ Vg, float* __restrict__ Og)
{
    extern __shared__ float sm[];
    float* sKh = sm + SKH;  float* sKl = sm + SKL;
    float* sVh = sm + SVH;  float* sVl = sm + SVL;
    float* sP  = sm + SP_;  float* sSr = sm + SSR;
    float* s_m = sm + SM_;  float* s_a = sm + SA_;  float* s_l = sm + SL_;

    const int qi  = blockIdx.x;
    const int h   = blockIdx.y;
    const int b   = blockIdx.z;
    const int kvh = h >> 2;              // repeat_interleave: h // GROUP
    const int tid = threadIdx.x;
    const int q0  = qi * 64;

    const int lane = tid & 31;
    const int w    = tid >> 5;
    const int g    = lane >> 2;
    const int t    = lane & 3;
    const int mw   = (w >> 1) * 16;      // warp m offset
    const int nw   = w & 1;              // warp n32 group
    const int r0   = mw + g;
    const int r1   = r0 + 8;

    // ---- Q fragments: load from gmem once, tf32 hi/lo split in registers ----
    uint32_t qh[8][4], ql[8][4];
    {
        const float* q0p = Q + (size_t)(b * TT + q0 + r0) * DM + h * HD;
        const float* q1p = Q + (size_t)(b * TT + q0 + r1) * DM + h * HD;
        #pragma unroll
        for (int ks = 0; ks < 8; ks++) {
            float v0 = q0p[ks * 8 + t];
            float v1 = q1p[ks * 8 + t];
            float v2 = q0p[ks * 8 + t + 4];
            float v3 = q1p[ks * 8 + t + 4];
            float h0 = f2t(v0), h1 = f2t(v1), h2 = f2t(v2), h3 = f2t(v3);
            qh[ks][0] = __float_as_uint(h0);
            qh[ks][1] = __float_as_uint(h1);
            qh[ks][2] = __float_as_uint(h2);
            qh[ks][3] = __float_as_uint(h3);
            ql[ks][0] = __float_as_uint(f2t(v0 - h0));
            ql[ks][1] = __float_as_uint(f2t(v1 - h1));
            ql[ks][2] = __float_as_uint(f2t(v2 - h2));
            ql[ks][3] = __float_as_uint(f2t(v3 - h3));
        }
    }

    float row_m = -CUDART_INF_F, row_l = 0.f;   // valid for tid < 64 (row owner)

    float o[4][4];
    #pragma unroll
    for (int i = 0; i < 4; i++)
        #pragma unroll
        for (int j = 0; j < 4; j++) o[i][j] = 0.f;

    const int nkv = qi + 1;              // causal: k0 < q0 + 64, step 64
    for (int it = 0; it < nkv; it++) {
        const int k0 = it * 64;

        // ---- load K,V tiles (64 x 64), tf32 hi/lo split ----
        for (int i = tid; i < 64 * 64; i += 256) {
            int r = i >> 6, d = i & 63;
            size_t gx = (size_t)(b * TT + k0 + r) * (KVH * HD) + kvh * HD + d;
            float kv = Kg[gx];
            float vv = Vg[gx];
            float kh_ = f2t(kv), vh_ = f2t(vv);
            sKh[r * KST + d] = kh_;  sKl[r * KST + d] = f2t(kv - kh_);
            sVh[r * VST + d] = vh_;  sVl[r * VST + d] = f2t(vv - vh_);
        }
        __syncthreads();                 // (1)

        // ---- S = Q K^T (3xTF32), warp m16 x n32 ----
        {
            float sc[4][4];
            #pragma unroll
            for (int tn = 0; tn < 4; tn++)
                #pragma unroll
                for (int j = 0; j < 4; j++) sc[tn][j] = 0.f;

            #pragma unroll
            for (int ks = 0; ks < 8; ks++) {
                const int kt = ks * 8;
                #pragma unroll
                for (int tn = 0; tn < 4; tn++) {
                    int n = nw * 32 + tn * 8 + g;
                    uint32_t bh0 = __float_as_uint(sKh[n * KST + kt + t]);
                    uint32_t bh1 = __float_as_uint(sKh[n * KST + kt + t + 4]);
                    uint32_t bl0 = __float_as_uint(sKl[n * KST + kt + t]);
                    uint32_t bl1 = __float_as_uint(sKl[n * KST + kt + t + 4]);
                    MMA_TF32(sc[tn], qh[ks][0], qh[ks][1], qh[ks][2], qh[ks][3], bh0, bh1);
                    MMA_TF32(sc[tn], qh[ks][0], qh[ks][1], qh[ks][2], qh[ks][3], bl0, bl1);
                    MMA_TF32(sc[tn], ql[ks][0], ql[ks][1], ql[ks][2], ql[ks][3], bh0, bh1);
                }
            }
            // masked, scaled store of raw S
            const int qg0 = q0 + r0, qg1 = q0 + r1;
            #pragma unroll
            for (int tn = 0; tn < 4; tn++) {
                int col = nw * 32 + tn * 8 + 2 * t;
                int kg0 = k0 + col, kg1 = kg0 + 1;
                sSr[r0 * KST + col]     = (kg0 <= qg0) ? sc[tn][0] * 0.125f : -CUDART_INF_F;
                sSr[r0 * KST + col + 1] = (kg1 <= qg0) ? sc[tn][1] * 0.125f : -CUDART_INF_F;
                sSr[r1 * KST + col]     = (kg0 <= qg1) ? sc[tn][2] * 0.125f : -CUDART_INF_F;
                sSr[r1 * KST + col + 1] = (kg1 <= qg1) ? sc[tn][3] * 0.125f : -CUDART_INF_F;
            }
        }
        __syncthreads();                 // (2)

        // ---- phase A: per-row running max + rescale factor ----
        if (tid < 64) {
            float m = row_m;
            #pragma unroll 8
            for (int c = 0; c < 64; c++) m = fmaxf(m, sSr[tid * KST + c]);
            s_a[tid] = __expf(row_m - m);
            s_m[tid] = m;
            row_m = m;
        }
        __syncthreads();                 // (3)

        // ---- phase B: exponentiate, truncate to tf32, write P ----
        {
            const int r  = tid >> 2;
            const int cb = (tid & 3) * 16;
            const float m = s_m[r];
            #pragma unroll
            for (int j = 0; j < 16; j++) {
                float e = __expf(sSr[r * KST + cb + j] - m);
                sP[r * KST + cb + j] = f2t(e);
            }
        }
        __syncthreads();                 // (4)

        // ---- phase C: l update ----
        if (tid < 64) {
            float s = 0.f;
            #pragma unroll 8
            for (int c = 0; c < 64; c++) s += sP[tid * KST + c];
            row_l = row_l * s_a[tid] + s;
        }
        // ---- O rescale + O += P @ V (2xTF32: P_h*V_h + P_h*V_l) ----
        {
            const float a0f = s_a[r0];
            const float a1f = s_a[r1];
            #pragma unroll
            for (int tn = 0; tn < 4; tn++) {
                o[tn][0] *= a0f; o[tn][1] *= a0f;
                o[tn][2] *= a1f; o[tn][3] *= a1f;
            }
            #pragma unroll
            for (int ks = 0; ks < 8; ks++) {
                const int kt = ks * 8;
                uint32_t p0 = __float_as_uint(sP[r0 * KST + kt + t]);
                uint32_t p1 = __float_as_uint(sP[r1 * KST + kt + t]);
                uint32_t p2 = __float_as_uint(sP[r0 * KST + kt + t + 4]);
                uint32_t p3 = __float_as_uint(sP[r1 * KST + kt + t + 4]);
                #pragma unroll
                for (int tn = 0; tn < 4; tn++) {
                    int n = nw * 32 + tn * 8 + g;
                    uint32_t vh0 = __float_as_uint(sVh[(kt + t) * VST + n]);
                    uint32_t vh1 = __float_as_uint(sVh[(kt + t + 4) * VST + n]);
                    uint32_t vl0 = __float_as_uint(sVl[(kt + t) * VST + n]);
                    uint32_t vl1 = __float_as_uint(sVl[(kt + t + 4) * VST + n]);
                    MMA_TF32(o[tn], p0, p1, p2, p3, vh0, vh1);
                    MMA_TF32(o[tn], p0, p1, p2, p3, vl0, vl1);
                }
            }
        }
        __syncthreads();                 // (5)
    }

    if (tid < 64) s_l[tid] = row_l;
    __syncthreads();

    // ---- normalize + write [B,T,QH*HD] ----
    {
        const float inv0 = 1.0f / s_l[r0];
        const float inv1 = 1.0f / s_l[r1];
        #pragma unroll
        for (int tn = 0; tn < 4; tn++) {
            int c = nw * 32 + tn * 8 + 2 * t;
            float2 v0 = {o[tn][0] * inv0, o[tn][1] * inv0};
            float2 v1 = {o[tn][2] * inv1, o[tn][3] * inv1};
            *(float2*)(Og + (size_t)(b * TT + q0 + r0) * DM + h * HD + c) = v0;
            *(float2*)(Og + (size_t)(b * TT + q0 + r1) * DM + h * HD + c) = v1;
        }
    }
}

// ============================================================================
// kernel_launch: 5 graph-capturable launches, no allocations, no syncs.
// ============================================================================
extern "C" void kernel_launch(void* const* d_in, const int* in_sizes, int n_in,
                              void* d_out, int out_size)
{
    const float* x  = (const float*)d_in[0];
    const float* Wq = (const float*)d_in[1];
    const float* bq = (const float*)d_in[2];
    const float* Wk = (const float*)d_in[3];
    const float* bk = (const float*)d_in[4];
    const float* Wv = (const float*)d_in[5];
    const float* bv = (const float*)d_in[6];
    const float* Wo = (const float*)d_in[7];
    const float* bo = (const float*)d_in[8];
    float* out = (float*)d_out;

    float *q, *k, *v, *att;
    cudaGetSymbolAddress((void**)&q,   g_q);
    cudaGetSymbolAddress((void**)&k,   g_k);
    cudaGetSymbolAddress((void**)&v,   g_v);
    cudaGetSymbolAddress((void**)&att, g_att);

    cudaFuncSetAttribute(attn_mma_kernel,
                         cudaFuncAttributeMaxDynamicSharedMemorySize, ATT_SMEM_BYTES);

    dim3 blk(256);

    gemm3t_bias_kernel<<<dim3(DM / 128, MROWS / 128), blk>>>(
        x, Wq, bq, q, MROWS, DM, DM);
    gemm3t_bias_kernel<<<dim3((KVH * HD) / 128, MROWS / 128), blk>>>(
        x, Wk, bk, k, MROWS, KVH * HD, DM);
    gemm3t_bias_kernel<<<dim3((KVH * HD) / 128, MROWS / 128), blk>>>(
        x, Wv, bv, v, MROWS, KVH * HD, DM);

    attn_mma_kernel<<<dim3(TT / 64, QH, BB), blk, ATT_SMEM_BYTES>>>(q, k, v, att);

    gemm3t_bias_kernel<<<dim3(DM / 128, MROWS / 128), blk>>>(
        att, Wo, bo, out, MROWS, DM, DM);
}

// round 7
// speedup vs baseline: 2.4834x; 1.3212x over previous
#include <cuda_runtime.h>
#include <cuda_bf16.h>
#include <math_constants.h>
#include <stdint.h>

// ---------------- problem constants ----------------
#define DM    2048              // d_model
#define QH    32                // q heads
#define KVH   8                 // kv heads
#define HD    64                // head dim
#define BB    2                 // batch
#define TT    2048              // seq len
#define MROWS (BB * TT)         // 4096 rows for all GEMMs
#define NKV   (KVH * HD)        // 512

// ---------------- scratch (device globals; no allocation allowed) ----------------
__device__ __align__(16) float g_q[(size_t)MROWS * DM];
__device__ __align__(16) float g_k[(size_t)MROWS * NKV];
__device__ __align__(16) float g_v[(size_t)MROWS * NKV];
__device__ __align__(16) float g_att[(size_t)MROWS * DM];
// transposed bf16 hi/lo weights: [N][K] layout, K = DM
__device__ __align__(16) __nv_bfloat16 g_wqh[(size_t)DM * DM],  g_wql[(size_t)DM * DM];
__device__ __align__(16) __nv_bfloat16 g_wkh[(size_t)NKV * DM], g_wkl[(size_t)NKV * DM];
__device__ __align__(16) __nv_bfloat16 g_wvh[(size_t)NKV * DM], g_wvl[(size_t)NKV * DM];
__device__ __align__(16) __nv_bfloat16 g_woh[(size_t)DM * DM],  g_wol[(size_t)DM * DM];

// ---------------- tf32 helpers (attention kernel) ----------------
__device__ __forceinline__ float f2t(float x) {
    uint32_t u;
    asm("cvt.rna.tf32.f32 %0, %1;" : "=r"(u) : "f"(x));
    return __uint_as_float(u);
}

#define MMA_TF32(cc, a0, a1, a2, a3, b0, b1)                               \
    asm volatile(                                                          \
        "mma.sync.aligned.m16n8k8.row.col.f32.tf32.tf32.f32 "              \
        "{%0,%1,%2,%3}, {%4,%5,%6,%7}, {%8,%9}, {%0,%1,%2,%3};"            \
        : "+f"(cc[0]), "+f"(cc[1]), "+f"(cc[2]), "+f"(cc[3])               \
        : "r"(a0), "r"(a1), "r"(a2), "r"(a3), "r"(b0), "r"(b1))

#define MMA_BF16(cc, a0, a1, a2, a3, b0, b1)                               \
    asm volatile(                                                          \
        "mma.sync.aligned.m16n8k16.row.col.f32.bf16.bf16.f32 "             \
        "{%0,%1,%2,%3}, {%4,%5,%6,%7}, {%8,%9}, {%0,%1,%2,%3};"            \
        : "+f"(cc[0]), "+f"(cc[1]), "+f"(cc[2]), "+f"(cc[3])               \
        : "r"(a0), "r"(a1), "r"(a2), "r"(a3), "r"(b0), "r"(b1))

__device__ __forceinline__ uint32_t pack_bf2(__nv_bfloat16 a, __nv_bfloat16 b) {
    return (uint32_t)__bfloat16_as_ushort(a) | ((uint32_t)__bfloat16_as_ushort(b) << 16);
}

// ============================================================================
// Pre-pass: W [K][N] fp32  ->  Wh/Wl [N][K] bf16 (hi/lo split), tiled transpose.
// Grid (N/32, K/32), block (32, 8).
// ============================================================================
__global__ void __launch_bounds__(256) convert_w_kernel(
    const float* __restrict__ W,
    __nv_bfloat16* __restrict__ Wh, __nv_bfloat16* __restrict__ Wl,
    int K, int N)
{
    __shared__ float ts[32][33];
    const int n0 = blockIdx.x * 32, k0 = blockIdx.y * 32;
    const int tx = threadIdx.x, ty = threadIdx.y;
    #pragma unroll
    for (int i = 0; i < 4; i++)
        ts[ty + i * 8][tx] = W[(size_t)(k0 + ty + i * 8) * N + n0 + tx];
    __syncthreads();
    #pragma unroll
    for (int i = 0; i < 4; i++) {
        float v = ts[tx][ty + i * 8];                  // [k_local][n_local]
        __nv_bfloat16 h = __float2bfloat16(v);
        __nv_bfloat16 l = __float2bfloat16(v - __bfloat162float(h));
        size_t o = (size_t)(n0 + ty + i * 8) * K + k0 + tx;
        Wh[o] = h;
        Wl[o] = l;
    }
}

// ============================================================================
// 3xBF16 GEMM: C[M,N] = A[M,K] @ W^T + bias, W pre-split as [N][K] bf16 hi/lo.
// 128x128x32 block tile, 256 threads = 8 warps (4m x 2n), warp tile 32x64.
// mma.m16n8k16 bf16; terms Ah*Bh + Ah*Bl + Al*Bh.
// smem pitch 40 bf16 (20 words): fragment addr (20g + t) % 32 all-distinct.
// ============================================================================
__global__ void __launch_bounds__(256) gemm_bf3_bias_kernel(
    const float* __restrict__ A,
    const __nv_bfloat16* __restrict__ Bh_g, const __nv_bfloat16* __restrict__ Bl_g,
    const float* __restrict__ bias, float* __restrict__ C,
    int M, int N, int K)
{
    __shared__ __nv_bfloat16 Ah[128][40], Al[128][40];   // [m][k]
    __shared__ __nv_bfloat16 Bh[128][40], Bl[128][40];   // [n][k]

    const int tid  = threadIdx.x;
    const int lane = tid & 31;
    const int w    = tid >> 5;
    const int g    = lane >> 2;
    const int t    = lane & 3;
    const int mw   = (w >> 1) * 32;
    const int nw   = (w & 1) * 64;

    const int bRow0 = blockIdx.y * 128;
    const int bCol0 = blockIdx.x * 128;

    const int lR = tid >> 1;             // 0..127 (row for A, n-row for B)
    const int lC = (tid & 1) * 16;       // k offset 0 or 16

    // gmem prefetch registers
    float4 pa[4];
    uint4  pbh[2], pbl[2];
    #pragma unroll
    for (int q = 0; q < 4; q++)
        pa[q] = *(const float4*)(A + (size_t)(bRow0 + lR) * K + lC + q * 4);
    {
        const __nv_bfloat16* ph = Bh_g + (size_t)(bCol0 + lR) * K + lC;
        const __nv_bfloat16* pl = Bl_g + (size_t)(bCol0 + lR) * K + lC;
        pbh[0] = *(const uint4*)(ph);  pbh[1] = *(const uint4*)(ph + 8);
        pbl[0] = *(const uint4*)(pl);  pbl[1] = *(const uint4*)(pl + 8);
    }

    float acc[2][8][4];
    #pragma unroll
    for (int i = 0; i < 2; i++)
        #pragma unroll
        for (int j = 0; j < 8; j++)
            #pragma unroll
            for (int q = 0; q < 4; q++) acc[i][j][q] = 0.f;

    for (int k0 = 0; k0 < K; k0 += 32) {
        __syncthreads();
        // stage A tile: fp32 -> bf16 hi/lo, packed uint2 stores
        #pragma unroll
        for (int q = 0; q < 4; q++) {
            float vv[4] = {pa[q].x, pa[q].y, pa[q].z, pa[q].w};
            __nv_bfloat16 h[4], l[4];
            #pragma unroll
            for (int j = 0; j < 4; j++) {
                h[j] = __float2bfloat16(vv[j]);
                l[j] = __float2bfloat16(vv[j] - __bfloat162float(h[j]));
            }
            uint2 uh = {pack_bf2(h[0], h[1]), pack_bf2(h[2], h[3])};
            uint2 ul = {pack_bf2(l[0], l[1]), pack_bf2(l[2], l[3])};
            *(uint2*)&Ah[lR][lC + q * 4] = uh;
            *(uint2*)&Al[lR][lC + q * 4] = ul;
        }
        // stage B tile (already bf16 split in gmem)
        *(uint4*)&Bh[lR][lC]     = pbh[0];
        *(uint4*)&Bh[lR][lC + 8] = pbh[1];
        *(uint4*)&Bl[lR][lC]     = pbl[0];
        *(uint4*)&Bl[lR][lC + 8] = pbl[1];
        __syncthreads();

        // prefetch next tile
        if (k0 + 32 < K) {
            #pragma unroll
            for (int q = 0; q < 4; q++)
                pa[q] = *(const float4*)(A + (size_t)(bRow0 + lR) * K + k0 + 32 + lC + q * 4);
            const __nv_bfloat16* ph = Bh_g + (size_t)(bCol0 + lR) * K + k0 + 32 + lC;
            const __nv_bfloat16* pl = Bl_g + (size_t)(bCol0 + lR) * K + k0 + 32 + lC;
            pbh[0] = *(const uint4*)(ph);  pbh[1] = *(const uint4*)(ph + 8);
            pbl[0] = *(const uint4*)(pl);  pbl[1] = *(const uint4*)(pl + 8);
        }

        #pragma unroll
        for (int ks = 0; ks < 2; ks++) {
            const int kc = ks * 16 + 2 * t;          // bf16 col of this thread's pair
            uint32_t ah[2][4], al_[2][4];
            #pragma unroll
            for (int mt = 0; mt < 2; mt++) {
                int r = mw + mt * 16 + g;
                ah[mt][0]  = *(const uint32_t*)&Ah[r][kc];
                ah[mt][1]  = *(const uint32_t*)&Ah[r + 8][kc];
                ah[mt][2]  = *(const uint32_t*)&Ah[r][kc + 8];
                ah[mt][3]  = *(const uint32_t*)&Ah[r + 8][kc + 8];
                al_[mt][0] = *(const uint32_t*)&Al[r][kc];
                al_[mt][1] = *(const uint32_t*)&Al[r + 8][kc];
                al_[mt][2] = *(const uint32_t*)&Al[r][kc + 8];
                al_[mt][3] = *(const uint32_t*)&Al[r + 8][kc + 8];
            }
            #pragma unroll
            for (int nt = 0; nt < 8; nt++) {
                int n = nw + nt * 8 + g;
                uint32_t bh0 = *(const uint32_t*)&Bh[n][kc];
                uint32_t bh1 = *(const uint32_t*)&Bh[n][kc + 8];
                uint32_t bl0 = *(const uint32_t*)&Bl[n][kc];
                uint32_t bl1 = *(const uint32_t*)&Bl[n][kc + 8];
                #pragma unroll
                for (int mt = 0; mt < 2; mt++) {
                    MMA_BF16(acc[mt][nt], ah[mt][0], ah[mt][1], ah[mt][2], ah[mt][3], bh0, bh1);
                    MMA_BF16(acc[mt][nt], ah[mt][0], ah[mt][1], ah[mt][2], ah[mt][3], bl0, bl1);
                    MMA_BF16(acc[mt][nt], al_[mt][0], al_[mt][1], al_[mt][2], al_[mt][3], bh0, bh1);
                }
            }
        }
    }

    // epilogue: bias + float2 stores (C fragment rows g/g+8, cols 2t,2t+1)
    #pragma unroll
    for (int mt = 0; mt < 2; mt++) {
        #pragma unroll
        for (int nt = 0; nt < 8; nt++) {
            int row = bRow0 + mw + mt * 16 + g;
            int col = bCol0 + nw + nt * 8 + 2 * t;
            float b0v = bias[col], b1v = bias[col + 1];
            float2 o0 = {acc[mt][nt][0] + b0v, acc[mt][nt][1] + b1v};
            float2 o1 = {acc[mt][nt][2] + b0v, acc[mt][nt][3] + b1v};
            *(float2*)(C + (size_t)row * N + col)       = o0;
            *(float2*)(C + (size_t)(row + 8) * N + col) = o1;
        }
    }
}

// ============================================================================
// Tensor-core flash attention (3xTF32 QK^T, 2xTF32 PV), causal, GQA.
// UNCHANGED from R5 (proven: 958 us, L1 58.6%, tensor 34.4%).
// ============================================================================
#define KST 68
#define VST 72
#define SKH 0
#define SKL (SKH + 64 * KST)
#define SVH (SKL + 64 * KST)
#define SVL (SVH + 64 * VST)
#define SP_ (SVL + 64 * VST)
#define SSR (SP_ + 64 * KST)
#define SM_ (SSR + 64 * KST)
#define SA_ (SM_ + 64)
#define SL_ (SA_ + 64)
#define ATT_SMEM_FLOATS (SL_ + 64)
#define ATT_SMEM_BYTES  (ATT_SMEM_FLOATS * 4)

__global__ void __launch_bounds__(256, 2) attn_mma_kernel(
    const float* __restrict__ Q, const float* __restrict__ Kg,
    const float* __restrict__ Vg, float* __restrict__ Og)
{
    extern __shared__ float sm[];
    float* sKh = sm + SKH;  float* sKl = sm + SKL;
    float* sVh = sm + SVH;  float* sVl = sm + SVL;
    float* sP  = sm + SP_;  float* sSr = sm + SSR;
    float* s_m = sm + SM_;  float* s_a = sm + SA_;  float* s_l = sm + SL_;

    const int qi  = blockIdx.x;
    const int h   = blockIdx.y;
    const int b   = blockIdx.z;
    const int kvh = h >> 2;
    const int tid = threadIdx.x;
    const int q0  = qi * 64;

    const int lane = tid & 31;
    const int w    = tid >> 5;
    const int g    = lane >> 2;
    const int t    = lane & 3;
    const int mw   = (w >> 1) * 16;
    const int nw   = w & 1;
    const int r0   = mw + g;
    const int r1   = r0 + 8;

    uint32_t qh[8][4], ql[8][4];
    {
        const float* q0p = Q + (size_t)(b * TT + q0 + r0) * DM + h * HD;
        const float* q1p = Q + (size_t)(b * TT + q0 + r1) * DM + h * HD;
        #pragma unroll
        for (int ks = 0; ks < 8; ks++) {
            float v0 = q0p[ks * 8 + t];
            float v1 = q1p[ks * 8 + t];
            float v2 = q0p[ks * 8 + t + 4];
            float v3 = q1p[ks * 8 + t + 4];
            float h0 = f2t(v0), h1 = f2t(v1), h2 = f2t(v2), h3 = f2t(v3);
            qh[ks][0] = __float_as_uint(h0);
            qh[ks][1] = __float_as_uint(h1);
            qh[ks][2] = __float_as_uint(h2);
            qh[ks][3] = __float_as_uint(h3);
            ql[ks][0] = __float_as_uint(f2t(v0 - h0));
            ql[ks][1] = __float_as_uint(f2t(v1 - h1));
            ql[ks][2] = __float_as_uint(f2t(v2 - h2));
            ql[ks][3] = __float_as_uint(f2t(v3 - h3));
        }
    }

    float row_m = -CUDART_INF_F, row_l = 0.f;

    float o[4][4];
    #pragma unroll
    for (int i = 0; i < 4; i++)
        #pragma unroll
        for (int j = 0; j < 4; j++) o[i][j] = 0.f;

    const int nkv = qi + 1;
    for (int it = 0; it < nkv; it++) {
        const int k0 = it * 64;

        for (int i = tid; i < 64 * 64; i += 256) {
            int r = i >> 6, d = i & 63;
            size_t gx = (size_t)(b * TT + k0 + r) * NKV + kvh * HD + d;
            float kv = Kg[gx];
            float vv = Vg[gx];
            float kh_ = f2t(kv), vh_ = f2t(vv);
            sKh[r * KST + d] = kh_;  sKl[r * KST + d] = f2t(kv - kh_);
            sVh[r * VST + d] = vh_;  sVl[r * VST + d] = f2t(vv - vh_);
        }
        __syncthreads();

        {
            float sc[4][4];
            #pragma unroll
            for (int tn = 0; tn < 4; tn++)
                #pragma unroll
                for (int j = 0; j < 4; j++) sc[tn][j] = 0.f;

            #pragma unroll
            for (int ks = 0; ks < 8; ks++) {
                const int kt = ks * 8;
                #pragma unroll
                for (int tn = 0; tn < 4; tn++) {
                    int n = nw * 32 + tn * 8 + g;
                    uint32_t bh0 = __float_as_uint(sKh[n * KST + kt + t]);
                    uint32_t bh1 = __float_as_uint(sKh[n * KST + kt + t + 4]);
                    uint32_t bl0 = __float_as_uint(sKl[n * KST + kt + t]);
                    uint32_t bl1 = __float_as_uint(sKl[n * KST + kt + t + 4]);
                    MMA_TF32(sc[tn], qh[ks][0], qh[ks][1], qh[ks][2], qh[ks][3], bh0, bh1);
                    MMA_TF32(sc[tn], qh[ks][0], qh[ks][1], qh[ks][2], qh[ks][3], bl0, bl1);
                    MMA_TF32(sc[tn], ql[ks][0], ql[ks][1], ql[ks][2], ql[ks][3], bh0, bh1);
                }
            }
            const int qg0 = q0 + r0, qg1 = q0 + r1;
            #pragma unroll
            for (int tn = 0; tn < 4; tn++) {
                int col = nw * 32 + tn * 8 + 2 * t;
                int kg0 = k0 + col, kg1 = kg0 + 1;
                sSr[r0 * KST + col]     = (kg0 <= qg0) ? sc[tn][0] * 0.125f : -CUDART_INF_F;
                sSr[r0 * KST + col + 1] = (kg1 <= qg0) ? sc[tn][1] * 0.125f : -CUDART_INF_F;
                sSr[r1 * KST + col]     = (kg0 <= qg1) ? sc[tn][2] * 0.125f : -CUDART_INF_F;
                sSr[r1 * KST + col + 1] = (kg1 <= qg1) ? sc[tn][3] * 0.125f : -CUDART_INF_F;
            }
        }
        __syncthreads();

        if (tid < 64) {
            float m = row_m;
            #pragma unroll 8
            for (int c = 0; c < 64; c++) m = fmaxf(m, sSr[tid * KST + c]);
            s_a[tid] = __expf(row_m - m);
            s_m[tid] = m;
            row_m = m;
        }
        __syncthreads();

        {
            const int r  = tid >> 2;
            const int cb = (tid & 3) * 16;
            const float m = s_m[r];
            #pragma unroll
            for (int j = 0; j < 16; j++) {
                float e = __expf(sSr[r * KST + cb + j] - m);
                sP[r * KST + cb + j] = f2t(e);
            }
        }
        __syncthreads();

        if (tid < 64) {
            float s = 0.f;
            #pragma unroll 8
            for (int c = 0; c < 64; c++) s += sP[tid * KST + c];
            row_l = row_l * s_a[tid] + s;
        }
        {
            const float a0f = s_a[r0];
            const float a1f = s_a[r1];
            #pragma unroll
            for (int tn = 0; tn < 4; tn++) {
                o[tn][0] *= a0f; o[tn][1] *= a0f;
                o[tn][2] *= a1f; o[tn][3] *= a1f;
            }
            #pragma unroll
            for (int ks = 0; ks < 8; ks++) {
                const int kt = ks * 8;
                uint32_t p0 = __float_as_uint(sP[r0 * KST + kt + t]);
                uint32_t p1 = __float_as_uint(sP[r1 * KST + kt + t]);
                uint32_t p2 = __float_as_uint(sP[r0 * KST + kt + t + 4]);
                uint32_t p3 = __float_as_uint(sP[r1 * KST + kt + t + 4]);
                #pragma unroll
                for (int tn = 0; tn < 4; tn++) {
                    int n = nw * 32 + tn * 8 + g;
                    uint32_t vh0 = __float_as_uint(sVh[(kt + t) * VST + n]);
                    uint32_t vh1 = __float_as_uint(sVh[(kt + t + 4) * VST + n]);
                    uint32_t vl0 = __float_as_uint(sVl[(kt + t) * VST + n]);
                    uint32_t vl1 = __float_as_uint(sVl[(kt + t + 4) * VST + n]);
                    MMA_TF32(o[tn], p0, p1, p2, p3, vh0, vh1);
                    MMA_TF32(o[tn], p0, p1, p2, p3, vl0, vl1);
                }
            }
        }
        __syncthreads();
    }

    if (tid < 64) s_l[tid] = row_l;
    __syncthreads();

    {
        const float inv0 = 1.0f / s_l[r0];
        const float inv1 = 1.0f / s_l[r1];
        #pragma unroll
        for (int tn = 0; tn < 4; tn++) {
            int c = nw * 32 + tn * 8 + 2 * t;
            float2 v0 = {o[tn][0] * inv0, o[tn][1] * inv0};
            float2 v1 = {o[tn][2] * inv1, o[tn][3] * inv1};
            *(float2*)(Og + (size_t)(b * TT + q0 + r0) * DM + h * HD + c) = v0;
            *(float2*)(Og + (size_t)(b * TT + q0 + r1) * DM + h * HD + c) = v1;
        }
    }
}

// ============================================================================
// kernel_launch: 9 graph-capturable launches, no allocations, no syncs.
// ============================================================================
extern "C" void kernel_launch(void* const* d_in, const int* in_sizes, int n_in,
                              void* d_out, int out_size)
{
    const float* x  = (const float*)d_in[0];
    const float* Wq = (const float*)d_in[1];
    const float* bq = (const float*)d_in[2];
    const float* Wk = (const float*)d_in[3];
    const float* bk = (const float*)d_in[4];
    const float* Wv = (const float*)d_in[5];
    const float* bv = (const float*)d_in[6];
    const float* Wo = (const float*)d_in[7];
    const float* bo = (const float*)d_in[8];
    float* out = (float*)d_out;

    float *q, *k, *v, *att;
    cudaGetSymbolAddress((void**)&q,   g_q);
    cudaGetSymbolAddress((void**)&k,   g_k);
    cudaGetSymbolAddress((void**)&v,   g_v);
    cudaGetSymbolAddress((void**)&att, g_att);
    __nv_bfloat16 *wqh, *wql, *wkh, *wkl, *wvh, *wvl, *woh, *wol;
    cudaGetSymbolAddress((void**)&wqh, g_wqh);
    cudaGetSymbolAddress((void**)&wql, g_wql);
    cudaGetSymbolAddress((void**)&wkh, g_wkh);
    cudaGetSymbolAddress((void**)&wkl, g_wkl);
    cudaGetSymbolAddress((void**)&wvh, g_wvh);
    cudaGetSymbolAddress((void**)&wvl, g_wvl);
    cudaGetSymbolAddress((void**)&woh, g_woh);
    cudaGetSymbolAddress((void**)&wol, g_wol);

    cudaFuncSetAttribute(attn_mma_kernel,
                         cudaFuncAttributeMaxDynamicSharedMemorySize, ATT_SMEM_BYTES);

    dim3 cblk(32, 8);

    // pre-pass: transpose + bf16 hi/lo split of weights
    convert_w_kernel<<<dim3(DM / 32, DM / 32),  cblk>>>(Wq, wqh, wql, DM, DM);
    convert_w_kernel<<<dim3(NKV / 32, DM / 32), cblk>>>(Wk, wkh, wkl, DM, NKV);
    convert_w_kernel<<<dim3(NKV / 32, DM / 32), cblk>>>(Wv, wvh, wvl, DM, NKV);
    convert_w_kernel<<<dim3(DM / 32, DM / 32),  cblk>>>(Wo, woh, wol, DM, DM);

    dim3 blk(256);

    // projections (3xBF16)
    gemm_bf3_bias_kernel<<<dim3(DM / 128, MROWS / 128), blk>>>(
        x, wqh, wql, bq, q, MROWS, DM, DM);
    gemm_bf3_bias_kernel<<<dim3(NKV / 128, MROWS / 128), blk>>>(
        x, wkh, wkl, bk, k, MROWS, NKV, DM);
    gemm_bf3_bias_kernel<<<dim3(NKV / 128, MROWS / 128), blk>>>(
        x, wvh, wvl, bv, v, MROWS, NKV, DM);

    // causal GQA attention (unchanged)
    attn_mma_kernel<<<dim3(TT / 64, QH, BB), blk, ATT_SMEM_BYTES>>>(q, k, v, att);

    // output projection (3xBF16)
    gemm_bf3_bias_kernel<<<dim3(DM / 128, MROWS / 128), blk>>>(
        att, woh, wol, bo, out, MROWS, DM, DM);
}

// round 8
// speedup vs baseline: 2.9331x; 1.1811x over previous
#include <cuda_runtime.h>
#include <cuda_bf16.h>
#include <math_constants.h>
#include <stdint.h>

// ---------------- problem constants ----------------
#define DM    2048              // d_model
#define QH    32                // q heads
#define KVH   8                 // kv heads
#define HD    64                // head dim
#define BB    2                 // batch
#define TT    2048              // seq len
#define MROWS (BB * TT)         // 4096 rows for all GEMMs
#define NKV   (KVH * HD)        // 512

// ---------------- scratch (device globals; no allocation allowed) ----------------
__device__ __align__(16) float g_q[(size_t)MROWS * DM];
__device__ __align__(16) float g_k[(size_t)MROWS * NKV];
__device__ __align__(16) float g_v[(size_t)MROWS * NKV];
__device__ __align__(16) float g_att[(size_t)MROWS * DM];
// transposed bf16 hi/lo weights: [N][K] layout, K = DM
__device__ __align__(16) __nv_bfloat16 g_wqh[(size_t)DM * DM],  g_wql[(size_t)DM * DM];
__device__ __align__(16) __nv_bfloat16 g_wkh[(size_t)NKV * DM], g_wkl[(size_t)NKV * DM];
__device__ __align__(16) __nv_bfloat16 g_wvh[(size_t)NKV * DM], g_wvl[(size_t)NKV * DM];
__device__ __align__(16) __nv_bfloat16 g_woh[(size_t)DM * DM],  g_wol[(size_t)DM * DM];
// pre-split K/V for attention: K as [b,kvh][t][d] bf16 hi/lo; V TRANSPOSED [b,kvh][d][t]
__device__ __align__(16) __nv_bfloat16 g_kbh[(size_t)BB * KVH * TT * HD], g_kbl[(size_t)BB * KVH * TT * HD];
__device__ __align__(16) __nv_bfloat16 g_vbh[(size_t)BB * KVH * TT * HD], g_vbl[(size_t)BB * KVH * TT * HD];

#define MMA_BF16(cc, a0, a1, a2, a3, b0, b1)                               \
    asm volatile(                                                          \
        "mma.sync.aligned.m16n8k16.row.col.f32.bf16.bf16.f32 "             \
        "{%0,%1,%2,%3}, {%4,%5,%6,%7}, {%8,%9}, {%0,%1,%2,%3};"            \
        : "+f"(cc[0]), "+f"(cc[1]), "+f"(cc[2]), "+f"(cc[3])               \
        : "r"(a0), "r"(a1), "r"(a2), "r"(a3), "r"(b0), "r"(b1))

__device__ __forceinline__ uint32_t pack_bf2(__nv_bfloat16 a, __nv_bfloat16 b) {
    return (uint32_t)__bfloat16_as_ushort(a) | ((uint32_t)__bfloat16_as_ushort(b) << 16);
}

// ============================================================================
// Pre-pass: W [K][N] fp32  ->  Wh/Wl [N][K] bf16 (hi/lo), tiled transpose.
// ============================================================================
__global__ void __launch_bounds__(256) convert_w_kernel(
    const float* __restrict__ W,
    __nv_bfloat16* __restrict__ Wh, __nv_bfloat16* __restrict__ Wl,
    int K, int N)
{
    __shared__ float ts[32][33];
    const int n0 = blockIdx.x * 32, k0 = blockIdx.y * 32;
    const int tx = threadIdx.x, ty = threadIdx.y;
    #pragma unroll
    for (int i = 0; i < 4; i++)
        ts[ty + i * 8][tx] = W[(size_t)(k0 + ty + i * 8) * N + n0 + tx];
    __syncthreads();
    #pragma unroll
    for (int i = 0; i < 4; i++) {
        float v = ts[tx][ty + i * 8];
        __nv_bfloat16 h = __float2bfloat16(v);
        __nv_bfloat16 l = __float2bfloat16(v - __bfloat162float(h));
        size_t o = (size_t)(n0 + ty + i * 8) * K + k0 + tx;
        Wh[o] = h;
        Wl[o] = l;
    }
}

// ============================================================================
// Pre-pass: K fp32 [b*TT+t][NKV] -> [b,kvh][t][d] bf16 hi/lo (reshape only).
// 1 thread = 4 elements. Grid: MROWS*NKV/4/256 blocks.
// ============================================================================
__global__ void __launch_bounds__(256) convert_k_kernel(
    const float* __restrict__ src,
    __nv_bfloat16* __restrict__ dh, __nv_bfloat16* __restrict__ dl)
{
    size_t e0 = ((size_t)blockIdx.x * 256 + threadIdx.x) * 4;
    int row = (int)(e0 >> 9);            // / NKV
    int c   = (int)(e0 & 511);
    int kvh = c >> 6, d = c & 63;
    int b   = row >> 11, t = row & 2047;
    float4 v = *(const float4*)(src + e0);
    float vv[4] = {v.x, v.y, v.z, v.w};
    __nv_bfloat16 h[4], l[4];
    #pragma unroll
    for (int j = 0; j < 4; j++) {
        h[j] = __float2bfloat16(vv[j]);
        l[j] = __float2bfloat16(vv[j] - __bfloat162float(h[j]));
    }
    size_t o = ((size_t)(b * KVH + kvh) * TT + t) * HD + d;
    *(uint2*)(dh + o) = make_uint2(pack_bf2(h[0], h[1]), pack_bf2(h[2], h[3]));
    *(uint2*)(dl + o) = make_uint2(pack_bf2(l[0], l[1]), pack_bf2(l[2], l[3]));
}

// ============================================================================
// Pre-pass: V fp32 [b*TT+t][NKV] -> TRANSPOSED [b,kvh][d][t] bf16 hi/lo.
// Tiled 32x32 transpose. Grid (TT/32, HD/32, BB*KVH), block (32,8).
// ============================================================================
__global__ void __launch_bounds__(256) convert_vT_kernel(
    const float* __restrict__ src,
    __nv_bfloat16* __restrict__ dh, __nv_bfloat16* __restrict__ dl)
{
    __shared__ float ts[32][33];
    const int bz  = blockIdx.z;
    const int b   = bz >> 3, kvh = bz & 7;
    const int t0  = blockIdx.x * 32, d0 = blockIdx.y * 32;
    const int tx  = threadIdx.x, ty = threadIdx.y;
    #pragma unroll
    for (int i = 0; i < 4; i++)
        ts[ty + i * 8][tx] = src[((size_t)b * TT + t0 + ty + i * 8) * NKV + kvh * HD + d0 + tx];
    __syncthreads();
    #pragma unroll
    for (int i = 0; i < 4; i++) {
        float v = ts[tx][ty + i * 8];                 // [t_local][d_local]
        __nv_bfloat16 h = __float2bfloat16(v);
        __nv_bfloat16 l = __float2bfloat16(v - __bfloat162float(h));
        size_t o = ((size_t)(b * KVH + kvh) * HD + d0 + ty + i * 8) * TT + t0 + tx;
        dh[o] = h;
        dl[o] = l;
    }
}

// ============================================================================
// 3xBF16 GEMM (unchanged, validated R7): C = A @ W^T + bias.
// ============================================================================
__global__ void __launch_bounds__(256) gemm_bf3_bias_kernel(
    const float* __restrict__ A,
    const __nv_bfloat16* __restrict__ Bh_g, const __nv_bfloat16* __restrict__ Bl_g,
    const float* __restrict__ bias, float* __restrict__ C,
    int M, int N, int K)
{
    __shared__ __nv_bfloat16 Ah[128][40], Al[128][40];
    __shared__ __nv_bfloat16 Bh[128][40], Bl[128][40];

    const int tid  = threadIdx.x;
    const int lane = tid & 31;
    const int w    = tid >> 5;
    const int g    = lane >> 2;
    const int t    = lane & 3;
    const int mw   = (w >> 1) * 32;
    const int nw   = (w & 1) * 64;

    const int bRow0 = blockIdx.y * 128;
    const int bCol0 = blockIdx.x * 128;

    const int lR = tid >> 1;
    const int lC = (tid & 1) * 16;

    float4 pa[4];
    uint4  pbh[2], pbl[2];
    #pragma unroll
    for (int q = 0; q < 4; q++)
        pa[q] = *(const float4*)(A + (size_t)(bRow0 + lR) * K + lC + q * 4);
    {
        const __nv_bfloat16* ph = Bh_g + (size_t)(bCol0 + lR) * K + lC;
        const __nv_bfloat16* pl = Bl_g + (size_t)(bCol0 + lR) * K + lC;
        pbh[0] = *(const uint4*)(ph);  pbh[1] = *(const uint4*)(ph + 8);
        pbl[0] = *(const uint4*)(pl);  pbl[1] = *(const uint4*)(pl + 8);
    }

    float acc[2][8][4];
    #pragma unroll
    for (int i = 0; i < 2; i++)
        #pragma unroll
        for (int j = 0; j < 8; j++)
            #pragma unroll
            for (int q = 0; q < 4; q++) acc[i][j][q] = 0.f;

    for (int k0 = 0; k0 < K; k0 += 32) {
        __syncthreads();
        #pragma unroll
        for (int q = 0; q < 4; q++) {
            float vv[4] = {pa[q].x, pa[q].y, pa[q].z, pa[q].w};
            __nv_bfloat16 h[4], l[4];
            #pragma unroll
            for (int j = 0; j < 4; j++) {
                h[j] = __float2bfloat16(vv[j]);
                l[j] = __float2bfloat16(vv[j] - __bfloat162float(h[j]));
            }
            uint2 uh = {pack_bf2(h[0], h[1]), pack_bf2(h[2], h[3])};
            uint2 ul = {pack_bf2(l[0], l[1]), pack_bf2(l[2], l[3])};
            *(uint2*)&Ah[lR][lC + q * 4] = uh;
            *(uint2*)&Al[lR][lC + q * 4] = ul;
        }
        *(uint4*)&Bh[lR][lC]     = pbh[0];
        *(uint4*)&Bh[lR][lC + 8] = pbh[1];
        *(uint4*)&Bl[lR][lC]     = pbl[0];
        *(uint4*)&Bl[lR][lC + 8] = pbl[1];
        __syncthreads();

        if (k0 + 32 < K) {
            #pragma unroll
            for (int q = 0; q < 4; q++)
                pa[q] = *(const float4*)(A + (size_t)(bRow0 + lR) * K + k0 + 32 + lC + q * 4);
            const __nv_bfloat16* ph = Bh_g + (size_t)(bCol0 + lR) * K + k0 + 32 + lC;
            const __nv_bfloat16* pl = Bl_g + (size_t)(bCol0 + lR) * K + k0 + 32 + lC;
            pbh[0] = *(const uint4*)(ph);  pbh[1] = *(const uint4*)(ph + 8);
            pbl[0] = *(const uint4*)(pl);  pbl[1] = *(const uint4*)(pl + 8);
        }

        #pragma unroll
        for (int ks = 0; ks < 2; ks++) {
            const int kc = ks * 16 + 2 * t;
            uint32_t ah[2][4], al_[2][4];
            #pragma unroll
            for (int mt = 0; mt < 2; mt++) {
                int r = mw + mt * 16 + g;
                ah[mt][0]  = *(const uint32_t*)&Ah[r][kc];
                ah[mt][1]  = *(const uint32_t*)&Ah[r + 8][kc];
                ah[mt][2]  = *(const uint32_t*)&Ah[r][kc + 8];
                ah[mt][3]  = *(const uint32_t*)&Ah[r + 8][kc + 8];
                al_[mt][0] = *(const uint32_t*)&Al[r][kc];
                al_[mt][1] = *(const uint32_t*)&Al[r + 8][kc];
                al_[mt][2] = *(const uint32_t*)&Al[r][kc + 8];
                al_[mt][3] = *(const uint32_t*)&Al[r + 8][kc + 8];
            }
            #pragma unroll
            for (int nt = 0; nt < 8; nt++) {
                int n = nw + nt * 8 + g;
                uint32_t bh0 = *(const uint32_t*)&Bh[n][kc];
                uint32_t bh1 = *(const uint32_t*)&Bh[n][kc + 8];
                uint32_t bl0 = *(const uint32_t*)&Bl[n][kc];
                uint32_t bl1 = *(const uint32_t*)&Bl[n][kc + 8];
                #pragma unroll
                for (int mt = 0; mt < 2; mt++) {
                    MMA_BF16(acc[mt][nt], ah[mt][0], ah[mt][1], ah[mt][2], ah[mt][3], bh0, bh1);
                    MMA_BF16(acc[mt][nt], ah[mt][0], ah[mt][1], ah[mt][2], ah[mt][3], bl0, bl1);
                    MMA_BF16(acc[mt][nt], al_[mt][0], al_[mt][1], al_[mt][2], al_[mt][3], bh0, bh1);
                }
            }
        }
    }

    #pragma unroll
    for (int mt = 0; mt < 2; mt++) {
        #pragma unroll
        for (int nt = 0; nt < 8; nt++) {
            int row = bRow0 + mw + mt * 16 + g;
            int col = bCol0 + nw + nt * 8 + 2 * t;
            float b0v = bias[col], b1v = bias[col + 1];
            float2 o0 = {acc[mt][nt][0] + b0v, acc[mt][nt][1] + b1v};
            float2 o1 = {acc[mt][nt][2] + b0v, acc[mt][nt][3] + b1v};
            *(float2*)(C + (size_t)row * N + col)       = o0;
            *(float2*)(C + (size_t)(row + 8) * N + col) = o1;
        }
    }
}

// ============================================================================
// Tensor-core flash attention v3: 3xBF16 QK^T AND 3xBF16 PV, causal, GQA.
// K/V arrive pre-split bf16 hi/lo from gmem (K: [t][d], V: transposed [d][t]).
// smem pitch KP=72 bf16: fragment addr banks (4n+t)%32 all-distinct.
// 96 MMAs/warp/iter (was 160 tf32-k8), all fragment LDS halved.
// ============================================================================
#define KP   72                          // bf16 pitch
#define SST  68                          // fp32 raw-score pitch
// byte offsets into dynamic smem
#define BKH  0
#define BKL  (BKH + 64 * KP * 2)
#define BVH  (BKL + 64 * KP * 2)
#define BVL  (BVH + 64 * KP * 2)
#define BPH  (BVL + 64 * KP * 2)
#define BPL  (BPH + 64 * KP * 2)
#define BSR  (BPL + 64 * KP * 2)
#define BM_  (BSR + 64 * SST * 4)
#define BA_  (BM_ + 64 * 4)
#define BPT  (BA_ + 64 * 4)
#define BL_  (BPT + 64 * 4 * 4)
#define ATT_SMEM_BYTES (BL_ + 64 * 4)

__global__ void __launch_bounds__(256, 2) attn_bf16_kernel(
    const float* __restrict__ Q,
    const __nv_bfloat16* __restrict__ Kbh, const __nv_bfloat16* __restrict__ Kbl,
    const __nv_bfloat16* __restrict__ Vbh, const __nv_bfloat16* __restrict__ Vbl,
    float* __restrict__ Og)
{
    extern __shared__ char smc[];
    __nv_bfloat16* sKh = (__nv_bfloat16*)(smc + BKH);
    __nv_bfloat16* sKl = (__nv_bfloat16*)(smc + BKL);
    __nv_bfloat16* sVh = (__nv_bfloat16*)(smc + BVH);
    __nv_bfloat16* sVl = (__nv_bfloat16*)(smc + BVL);
    __nv_bfloat16* sPh = (__nv_bfloat16*)(smc + BPH);
    __nv_bfloat16* sPl = (__nv_bfloat16*)(smc + BPL);
    float* sSr   = (float*)(smc + BSR);
    float* s_m   = (float*)(smc + BM_);
    float* s_a   = (float*)(smc + BA_);
    float* s_pt  = (float*)(smc + BPT);
    float* s_l   = (float*)(smc + BL_);

    const int qi  = blockIdx.x;
    const int h   = blockIdx.y;
    const int b   = blockIdx.z;
    const int kvh = h >> 2;              // repeat_interleave: h // GROUP
    const int tid = threadIdx.x;
    const int q0  = qi * 64;

    const int lane = tid & 31;
    const int w    = tid >> 5;
    const int g    = lane >> 2;
    const int t    = lane & 3;
    const int mw   = (w >> 1) * 16;
    const int nw   = w & 1;
    const int r0   = mw + g;
    const int r1   = r0 + 8;

    const __nv_bfloat16* kbh = Kbh + (size_t)(b * KVH + kvh) * TT * HD;
    const __nv_bfloat16* kbl = Kbl + (size_t)(b * KVH + kvh) * TT * HD;
    const __nv_bfloat16* vbh = Vbh + (size_t)(b * KVH + kvh) * HD * TT;
    const __nv_bfloat16* vbl = Vbl + (size_t)(b * KVH + kvh) * HD * TT;

    // ---- Q fragments: gmem load once, bf16 hi/lo packed in registers ----
    uint32_t qh[4][4], ql[4][4];
    {
        const float* q0p = Q + (size_t)(b * TT + q0 + r0) * DM + h * HD;
        const float* q1p = Q + (size_t)(b * TT + q0 + r1) * DM + h * HD;
        #pragma unroll
        for (int ks = 0; ks < 4; ks++) {
            const int kt = ks * 16;
            float v00 = q0p[kt + 2 * t],     v01 = q0p[kt + 2 * t + 1];
            float v10 = q1p[kt + 2 * t],     v11 = q1p[kt + 2 * t + 1];
            float v20 = q0p[kt + 2 * t + 8], v21 = q0p[kt + 2 * t + 9];
            float v30 = q1p[kt + 2 * t + 8], v31 = q1p[kt + 2 * t + 9];
            __nv_bfloat16 h00 = __float2bfloat16(v00), h01 = __float2bfloat16(v01);
            __nv_bfloat16 h10 = __float2bfloat16(v10), h11 = __float2bfloat16(v11);
            __nv_bfloat16 h20 = __float2bfloat16(v20), h21 = __float2bfloat16(v21);
            __nv_bfloat16 h30 = __float2bfloat16(v30), h31 = __float2bfloat16(v31);
            qh[ks][0] = pack_bf2(h00, h01);
            qh[ks][1] = pack_bf2(h10, h11);
            qh[ks][2] = pack_bf2(h20, h21);
            qh[ks][3] = pack_bf2(h30, h31);
            ql[ks][0] = pack_bf2(__float2bfloat16(v00 - __bfloat162float(h00)),
                                 __float2bfloat16(v01 - __bfloat162float(h01)));
            ql[ks][1] = pack_bf2(__float2bfloat16(v10 - __bfloat162float(h10)),
                                 __float2bfloat16(v11 - __bfloat162float(h11)));
            ql[ks][2] = pack_bf2(__float2bfloat16(v20 - __bfloat162float(h20)),
                                 __float2bfloat16(v21 - __bfloat162float(h21)));
            ql[ks][3] = pack_bf2(__float2bfloat16(v30 - __bfloat162float(h30)),
                                 __float2bfloat16(v31 - __bfloat162float(h31)));
        }
    }

    float row_m = -CUDART_INF_F, row_l = 0.f;

    float o[4][4];
    #pragma unroll
    for (int i = 0; i < 4; i++)
        #pragma unroll
        for (int j = 0; j < 4; j++) o[i][j] = 0.f;

    const int nkv = qi + 1;              // causal, 64-row KV tiles
    for (int it = 0; it < nkv; it++) {
        const int k0 = it * 64;

        // ---- stage K/V tiles: pure uint4 copies (8 bf16 each) ----
        #pragma unroll
        for (int i = tid; i < 512; i += 256) {
            const int r = i >> 3, seg = (i & 7) * 8;
            const size_t gk = (size_t)(k0 + r) * HD + seg;   // K row r = kv token
            *(uint4*)&sKh[r * KP + seg] = *(const uint4*)(kbh + gk);
            *(uint4*)&sKl[r * KP + seg] = *(const uint4*)(kbl + gk);
            const size_t gv = (size_t)r * TT + k0 + seg;     // V row r = head dim
            *(uint4*)&sVh[r * KP + seg] = *(const uint4*)(vbh + gv);
            *(uint4*)&sVl[r * KP + seg] = *(const uint4*)(vbl + gv);
        }
        __syncthreads();                 // (1)

        // ---- S = Q K^T (3xBF16), warp m16 x n32 ----
        {
            float sc[4][4];
            #pragma unroll
            for (int tn = 0; tn < 4; tn++)
                #pragma unroll
                for (int j = 0; j < 4; j++) sc[tn][j] = 0.f;

            #pragma unroll
            for (int ks = 0; ks < 4; ks++) {
                const int kt = ks * 16;
                #pragma unroll
                for (int tn = 0; tn < 4; tn++) {
                    const int n = nw * 32 + tn * 8 + g;
                    uint32_t bh0 = *(const uint32_t*)&sKh[n * KP + kt + 2 * t];
                    uint32_t bh1 = *(const uint32_t*)&sKh[n * KP + kt + 2 * t + 8];
                    uint32_t bl0 = *(const uint32_t*)&sKl[n * KP + kt + 2 * t];
                    uint32_t bl1 = *(const uint32_t*)&sKl[n * KP + kt + 2 * t + 8];
                    MMA_BF16(sc[tn], qh[ks][0], qh[ks][1], qh[ks][2], qh[ks][3], bh0, bh1);
                    MMA_BF16(sc[tn], qh[ks][0], qh[ks][1], qh[ks][2], qh[ks][3], bl0, bl1);
                    MMA_BF16(sc[tn], ql[ks][0], ql[ks][1], ql[ks][2], ql[ks][3], bh0, bh1);
                }
            }
            const int qg0 = q0 + r0, qg1 = q0 + r1;
            #pragma unroll
            for (int tn = 0; tn < 4; tn++) {
                const int col = nw * 32 + tn * 8 + 2 * t;
                const int kg0 = k0 + col, kg1 = kg0 + 1;
                sSr[r0 * SST + col]     = (kg0 <= qg0) ? sc[tn][0] * 0.125f : -CUDART_INF_F;
                sSr[r0 * SST + col + 1] = (kg1 <= qg0) ? sc[tn][1] * 0.125f : -CUDART_INF_F;
                sSr[r1 * SST + col]     = (kg0 <= qg1) ? sc[tn][2] * 0.125f : -CUDART_INF_F;
                sSr[r1 * SST + col + 1] = (kg1 <= qg1) ? sc[tn][3] * 0.125f : -CUDART_INF_F;
            }
        }
        __syncthreads();                 // (2)

        // ---- phase A: per-row running max + rescale factor ----
        if (tid < 64) {
            float m = row_m;
            #pragma unroll 8
            for (int c = 0; c < 64; c++) m = fmaxf(m, sSr[tid * SST + c]);
            s_a[tid] = __expf(row_m - m);
            s_m[tid] = m;
            row_m = m;
        }
        __syncthreads();                 // (3)

        // ---- phase B: exp, bf16 hi/lo split, packed stores + partial sums ----
        {
            const int r  = tid >> 2;
            const int cb = (tid & 3) * 16;
            const float m = s_m[r];
            __nv_bfloat16 ph[16], pl[16];
            float lsum = 0.f;
            #pragma unroll
            for (int j = 0; j < 16; j++) {
                float e = __expf(sSr[r * SST + cb + j] - m);
                lsum += e;
                ph[j] = __float2bfloat16(e);
                pl[j] = __float2bfloat16(e - __bfloat162float(ph[j]));
            }
            uint4 uh0 = {pack_bf2(ph[0], ph[1]),  pack_bf2(ph[2], ph[3]),
                         pack_bf2(ph[4], ph[5]),  pack_bf2(ph[6], ph[7])};
            uint4 uh1 = {pack_bf2(ph[8], ph[9]),  pack_bf2(ph[10], ph[11]),
                         pack_bf2(ph[12], ph[13]), pack_bf2(ph[14], ph[15])};
            uint4 ul0 = {pack_bf2(pl[0], pl[1]),  pack_bf2(pl[2], pl[3]),
                         pack_bf2(pl[4], pl[5]),  pack_bf2(pl[6], pl[7])};
            uint4 ul1 = {pack_bf2(pl[8], pl[9]),  pack_bf2(pl[10], pl[11]),
                         pack_bf2(pl[12], pl[13]), pack_bf2(pl[14], pl[15])};
            *(uint4*)&sPh[r * KP + cb]     = uh0;
            *(uint4*)&sPh[r * KP + cb + 8] = uh1;
            *(uint4*)&sPl[r * KP + cb]     = ul0;
            *(uint4*)&sPl[r * KP + cb + 8] = ul1;
            s_pt[r * 4 + (tid & 3)] = lsum;
        }
        __syncthreads();                 // (4)

        // ---- phase C: l update from partials ----
        if (tid < 64) {
            row_l = row_l * s_a[tid] +
                    s_pt[tid * 4] + s_pt[tid * 4 + 1] + s_pt[tid * 4 + 2] + s_pt[tid * 4 + 3];
        }
        // ---- O rescale + O += P @ V (3xBF16) ----
        {
            const float a0f = s_a[r0];
            const float a1f = s_a[r1];
            #pragma unroll
            for (int tn = 0; tn < 4; tn++) {
                o[tn][0] *= a0f; o[tn][1] *= a0f;
                o[tn][2] *= a1f; o[tn][3] *= a1f;
            }
            #pragma unroll
            for (int ks = 0; ks < 4; ks++) {
                const int kt = ks * 16;
                uint32_t p0h = *(const uint32_t*)&sPh[r0 * KP + kt + 2 * t];
                uint32_t p1h = *(const uint32_t*)&sPh[r1 * KP + kt + 2 * t];
                uint32_t p2h = *(const uint32_t*)&sPh[r0 * KP + kt + 2 * t + 8];
                uint32_t p3h = *(const uint32_t*)&sPh[r1 * KP + kt + 2 * t + 8];
                uint32_t p0l = *(const uint32_t*)&sPl[r0 * KP + kt + 2 * t];
                uint32_t p1l = *(const uint32_t*)&sPl[r1 * KP + kt + 2 * t];
                uint32_t p2l = *(const uint32_t*)&sPl[r0 * KP + kt + 2 * t + 8];
                uint32_t p3l = *(const uint32_t*)&sPl[r1 * KP + kt + 2 * t + 8];
                #pragma unroll
                for (int tn = 0; tn < 4; tn++) {
                    const int n = nw * 32 + tn * 8 + g;
                    uint32_t vh0 = *(const uint32_t*)&sVh[n * KP + kt + 2 * t];
                    uint32_t vh1 = *(const uint32_t*)&sVh[n * KP + kt + 2 * t + 8];
                    uint32_t vl0 = *(const uint32_t*)&sVl[n * KP + kt + 2 * t];
                    uint32_t vl1 = *(const uint32_t*)&sVl[n * KP + kt + 2 * t + 8];
                    MMA_BF16(o[tn], p0h, p1h, p2h, p3h, vh0, vh1);
                    MMA_BF16(o[tn], p0h, p1h, p2h, p3h, vl0, vl1);
                    MMA_BF16(o[tn], p0l, p1l, p2l, p3l, vh0, vh1);
                }
            }
        }
        __syncthreads();                 // (5)
    }

    if (tid < 64) s_l[tid] = row_l;
    __syncthreads();

    // ---- normalize + write [B,T,QH*HD] ----
    {
        const float inv0 = 1.0f / s_l[r0];
        const float inv1 = 1.0f / s_l[r1];
        #pragma unroll
        for (int tn = 0; tn < 4; tn++) {
            const int c = nw * 32 + tn * 8 + 2 * t;
            float2 v0 = {o[tn][0] * inv0, o[tn][1] * inv0};
            float2 v1 = {o[tn][2] * inv1, o[tn][3] * inv1};
            *(float2*)(Og + (size_t)(b * TT + q0 + r0) * DM + h * HD + c) = v0;
            *(float2*)(Og + (size_t)(b * TT + q0 + r1) * DM + h * HD + c) = v1;
        }
    }
}

// ============================================================================
// kernel_launch: graph-capturable launches, no allocations, no syncs.
// ============================================================================
extern "C" void kernel_launch(void* const* d_in, const int* in_sizes, int n_in,
                              void* d_out, int out_size)
{
    const float* x  = (const float*)d_in[0];
    const float* Wq = (const float*)d_in[1];
    const float* bq = (const float*)d_in[2];
    const float* Wk = (const float*)d_in[3];
    const float* bk = (const float*)d_in[4];
    const float* Wv = (const float*)d_in[5];
    const float* bv = (const float*)d_in[6];
    const float* Wo = (const float*)d_in[7];
    const float* bo = (const float*)d_in[8];
    float* out = (float*)d_out;

    float *q, *k, *v, *att;
    cudaGetSymbolAddress((void**)&q,   g_q);
    cudaGetSymbolAddress((void**)&k,   g_k);
    cudaGetSymbolAddress((void**)&v,   g_v);
    cudaGetSymbolAddress((void**)&att, g_att);
    __nv_bfloat16 *wqh, *wql, *wkh, *wkl, *wvh, *wvl, *woh, *wol;
    cudaGetSymbolAddress((void**)&wqh, g_wqh);
    cudaGetSymbolAddress((void**)&wql, g_wql);
    cudaGetSymbolAddress((void**)&wkh, g_wkh);
    cudaGetSymbolAddress((void**)&wkl, g_wkl);
    cudaGetSymbolAddress((void**)&wvh, g_wvh);
    cudaGetSymbolAddress((void**)&wvl, g_wvl);
    cudaGetSymbolAddress((void**)&woh, g_woh);
    cudaGetSymbolAddress((void**)&wol, g_wol);
    __nv_bfloat16 *kbh, *kbl, *vbh, *vbl;
    cudaGetSymbolAddress((void**)&kbh, g_kbh);
    cudaGetSymbolAddress((void**)&kbl, g_kbl);
    cudaGetSymbolAddress((void**)&vbh, g_vbh);
    cudaGetSymbolAddress((void**)&vbl, g_vbl);

    cudaFuncSetAttribute(attn_bf16_kernel,
                         cudaFuncAttributeMaxDynamicSharedMemorySize, ATT_SMEM_BYTES);

    dim3 cblk(32, 8);
    dim3 blk(256);

    // weight pre-pass
    convert_w_kernel<<<dim3(DM / 32, DM / 32),  cblk>>>(Wq, wqh, wql, DM, DM);
    convert_w_kernel<<<dim3(NKV / 32, DM / 32), cblk>>>(Wk, wkh, wkl, DM, NKV);
    convert_w_kernel<<<dim3(NKV / 32, DM / 32), cblk>>>(Wv, wvh, wvl, DM, NKV);
    convert_w_kernel<<<dim3(DM / 32, DM / 32),  cblk>>>(Wo, woh, wol, DM, DM);

    // projections (3xBF16)
    gemm_bf3_bias_kernel<<<dim3(DM / 128, MROWS / 128), blk>>>(
        x, wqh, wql, bq, q, MROWS, DM, DM);
    gemm_bf3_bias_kernel<<<dim3(NKV / 128, MROWS / 128), blk>>>(
        x, wkh, wkl, bk, k, MROWS, NKV, DM);
    gemm_bf3_bias_kernel<<<dim3(NKV / 128, MROWS / 128), blk>>>(
        x, wvh, wvl, bv, v, MROWS, NKV, DM);

    // K/V pre-split for attention
    convert_k_kernel<<<(MROWS * NKV / 4) / 256, blk>>>(k, kbh, kbl);
    convert_vT_kernel<<<dim3(TT / 32, HD / 32, BB * KVH), cblk>>>(v, vbh, vbl);

    // causal GQA attention (3xBF16)
    attn_bf16_kernel<<<dim3(TT / 64, QH, BB), blk, ATT_SMEM_BYTES>>>(
        q, kbh, kbl, vbh, vbl, att);

    // output projection (3xBF16)
    gemm_bf3_bias_kernel<<<dim3(DM / 128, MROWS / 128), blk>>>(
        att, woh, wol, bo, out, MROWS, DM, DM);
}

// round 12
// speedup vs baseline: 3.4875x; 1.1890x over previous
#include <cuda_runtime.h>
#include <cuda_bf16.h>
#include <math_constants.h>
#include <stdint.h>

// ---------------- problem constants ----------------
#define DM    2048              // d_model
#define QH    32                // q heads
#define KVH   8                 // kv heads
#define HD    64                // head dim
#define BB    2                 // batch
#define TT    2048              // seq len
#define MROWS (BB * TT)         // 4096 rows for all GEMMs
#define NKV   (KVH * HD)        // 512

// ---------------- scratch (device globals; no allocation allowed) ----------------
__device__ __align__(16) float g_q[(size_t)MROWS * DM];
__device__ __align__(16) float g_k[(size_t)MROWS * NKV];
__device__ __align__(16) float g_v[(size_t)MROWS * NKV];
__device__ __align__(16) float g_att[(size_t)MROWS * DM];
// transposed bf16 hi/lo weights: [N][K] layout, K = DM
__device__ __align__(16) __nv_bfloat16 g_wqh[(size_t)DM * DM],  g_wql[(size_t)DM * DM];
__device__ __align__(16) __nv_bfloat16 g_wkh[(size_t)NKV * DM], g_wkl[(size_t)NKV * DM];
__device__ __align__(16) __nv_bfloat16 g_wvh[(size_t)NKV * DM], g_wvl[(size_t)NKV * DM];
__device__ __align__(16) __nv_bfloat16 g_woh[(size_t)DM * DM],  g_wol[(size_t)DM * DM];
// pre-split GEMM A operands: [M][K] bf16 hi/lo
__device__ __align__(16) __nv_bfloat16 g_xh[(size_t)MROWS * DM],  g_xl[(size_t)MROWS * DM];
__device__ __align__(16) __nv_bfloat16 g_ath[(size_t)MROWS * DM], g_atl[(size_t)MROWS * DM];
// pre-split K/V for attention: K as [b,kvh][t][d] bf16 hi/lo; V TRANSPOSED [b,kvh][d][t]
__device__ __align__(16) __nv_bfloat16 g_kbh[(size_t)BB * KVH * TT * HD], g_kbl[(size_t)BB * KVH * TT * HD];
__device__ __align__(16) __nv_bfloat16 g_vbh[(size_t)BB * KVH * TT * HD], g_vbl[(size_t)BB * KVH * TT * HD];

#define MMA_BF16(cc, a0, a1, a2, a3, b0, b1)                               \
    asm volatile(                                                          \
        "mma.sync.aligned.m16n8k16.row.col.f32.bf16.bf16.f32 "             \
        "{%0,%1,%2,%3}, {%4,%5,%6,%7}, {%8,%9}, {%0,%1,%2,%3};"            \
        : "+f"(cc[0]), "+f"(cc[1]), "+f"(cc[2]), "+f"(cc[3])               \
        : "r"(a0), "r"(a1), "r"(a2), "r"(a3), "r"(b0), "r"(b1))

__device__ __forceinline__ uint32_t pack_bf2(__nv_bfloat16 a, __nv_bfloat16 b) {
    return (uint32_t)__bfloat16_as_ushort(a) | ((uint32_t)__bfloat16_as_ushort(b) << 16);
}

__device__ __forceinline__ uint32_t smem_u32(const void* p) {
    uint32_t a;
    asm("{ .reg .u64 t; cvta.to.shared.u64 t, %1; cvt.u32.u64 %0, t; }" : "=r"(a) : "l"(p));
    return a;
}

__device__ __forceinline__ void cp16(uint32_t saddr, const void* g) {
    asm volatile("cp.async.ca.shared.global [%0], [%1], 16;" :: "r"(saddr), "l"(g));
}
#define CP_COMMIT() asm volatile("cp.async.commit_group;" ::: "memory")
#define CP_WAIT0()  asm volatile("cp.async.wait_group 0;" ::: "memory")

// ============================================================================
// Pre-pass: W [K][N] fp32  ->  Wh/Wl [N][K] bf16 (hi/lo), tiled transpose.
// ============================================================================
__global__ void __launch_bounds__(256) convert_w_kernel(
    const float* __restrict__ W,
    __nv_bfloat16* __restrict__ Wh, __nv_bfloat16* __restrict__ Wl,
    int K, int N)
{
    __shared__ float ts[32][33];
    const int n0 = blockIdx.x * 32, k0 = blockIdx.y * 32;
    const int tx = threadIdx.x, ty = threadIdx.y;
    #pragma unroll
    for (int i = 0; i < 4; i++)
        ts[ty + i * 8][tx] = W[(size_t)(k0 + ty + i * 8) * N + n0 + tx];
    __syncthreads();
    #pragma unroll
    for (int i = 0; i < 4; i++) {
        float v = ts[tx][ty + i * 8];
        __nv_bfloat16 h = __float2bfloat16(v);
        __nv_bfloat16 l = __float2bfloat16(v - __bfloat162float(h));
        size_t o = (size_t)(n0 + ty + i * 8) * K + k0 + tx;
        Wh[o] = h;
        Wl[o] = l;
    }
}

// ============================================================================
// Pre-pass: A [M*K] fp32 -> bf16 hi/lo [M*K] (elementwise, no transpose).
// ============================================================================
__global__ void __launch_bounds__(256) convert_a_kernel(
    const float* __restrict__ src,
    __nv_bfloat16* __restrict__ dh, __nv_bfloat16* __restrict__ dl)
{
    size_t e0 = ((size_t)blockIdx.x * 256 + threadIdx.x) * 4;
    float4 v = *(const float4*)(src + e0);
    float vv[4] = {v.x, v.y, v.z, v.w};
    __nv_bfloat16 h[4], l[4];
    #pragma unroll
    for (int j = 0; j < 4; j++) {
        h[j] = __float2bfloat16(vv[j]);
        l[j] = __float2bfloat16(vv[j] - __bfloat162float(h[j]));
    }
    *(uint2*)(dh + e0) = make_uint2(pack_bf2(h[0], h[1]), pack_bf2(h[2], h[3]));
    *(uint2*)(dl + e0) = make_uint2(pack_bf2(l[0], l[1]), pack_bf2(l[2], l[3]));
}

// ============================================================================
// Pre-pass: K fp32 [b*TT+t][NKV] -> [b,kvh][t][d] bf16 hi/lo (reshape only).
// ============================================================================
__global__ void __launch_bounds__(256) convert_k_kernel(
    const float* __restrict__ src,
    __nv_bfloat16* __restrict__ dh, __nv_bfloat16* __restrict__ dl)
{
    size_t e0 = ((size_t)blockIdx.x * 256 + threadIdx.x) * 4;
    int row = (int)(e0 >> 9);
    int c   = (int)(e0 & 511);
    int kvh = c >> 6, d = c & 63;
    int b   = row >> 11, t = row & 2047;
    float4 v = *(const float4*)(src + e0);
    float vv[4] = {v.x, v.y, v.z, v.w};
    __nv_bfloat16 h[4], l[4];
    #pragma unroll
    for (int j = 0; j < 4; j++) {
        h[j] = __float2bfloat16(vv[j]);
        l[j] = __float2bfloat16(vv[j] - __bfloat162float(h[j]));
    }
    size_t o = ((size_t)(b * KVH + kvh) * TT + t) * HD + d;
    *(uint2*)(dh + o) = make_uint2(pack_bf2(h[0], h[1]), pack_bf2(h[2], h[3]));
    *(uint2*)(dl + o) = make_uint2(pack_bf2(l[0], l[1]), pack_bf2(l[2], l[3]));
}

// ============================================================================
// Pre-pass: V fp32 [b*TT+t][NKV] -> TRANSPOSED [b,kvh][d][t] bf16 hi/lo.
// ============================================================================
__global__ void __launch_bounds__(256) convert_vT_kernel(
    const float* __restrict__ src,
    __nv_bfloat16* __restrict__ dh, __nv_bfloat16* __restrict__ dl)
{
    __shared__ float ts[32][33];
    const int bz  = blockIdx.z;
    const int b   = bz >> 3, kvh = bz & 7;
    const int t0  = blockIdx.x * 32, d0 = blockIdx.y * 32;
    const int tx  = threadIdx.x, ty = threadIdx.y;
    #pragma unroll
    for (int i = 0; i < 4; i++)
        ts[ty + i * 8][tx] = src[((size_t)b * TT + t0 + ty + i * 8) * NKV + kvh * HD + d0 + tx];
    __syncthreads();
    #pragma unroll
    for (int i = 0; i < 4; i++) {
        float v = ts[tx][ty + i * 8];
        __nv_bfloat16 h = __float2bfloat16(v);
        __nv_bfloat16 l = __float2bfloat16(v - __bfloat162float(h));
        size_t o = ((size_t)(b * KVH + kvh) * HD + d0 + ty + i * 8) * TT + t0 + tx;
        dh[o] = h;
        dl[o] = l;
    }
}

// ============================================================================
// 3xBF16 GEMM v2: C[M,N] = A @ W^T + bias. A and W both pre-split bf16 hi/lo
// in gmem ([M][K] and [N][K]). 128x128x32 tiles, 256 threads, 8 warps (4m x 2n).
// cp.async double-buffered staging (2 stages x 40KB), ONE sync per K-tile.
// Fragment mapping/pitch identical to the R8-validated kernel.
// ============================================================================
#define GPITCH 40                         // bf16 per smem row (80 B, 16B-aligned)
#define GARR   (128 * GPITCH * 2)         // 10240 B per array
#define GSTAGE (4 * GARR)                 // Ah,Al,Bh,Bl = 40960 B per stage
#define GEMM_SMEM_BYTES (2 * GSTAGE)      // 81920 B

__global__ void __launch_bounds__(256) gemm_bf3_cp_kernel(
    const __nv_bfloat16* __restrict__ Ah_g, const __nv_bfloat16* __restrict__ Al_g,
    const __nv_bfloat16* __restrict__ Bh_g, const __nv_bfloat16* __restrict__ Bl_g,
    const float* __restrict__ bias, float* __restrict__ C,
    int M, int N, int K)
{
    extern __shared__ char smg[];
    const uint32_t sb = smem_u32(smg);

    const int tid  = threadIdx.x;
    const int lane = tid & 31;
    const int w    = tid >> 5;
    const int g    = lane >> 2;
    const int t    = lane & 3;
    const int mw   = (w >> 1) * 32;
    const int nw   = (w & 1) * 64;
    const int bRow0 = blockIdx.y * 128;
    const int bCol0 = blockIdx.x * 128;

    // staging geometry: per array 128 rows x 32 bf16 = 512 uint4; 2 per thread
    const int r0s   = tid >> 2;            // idx = tid:      row 0..63
    const int seg0  = (tid & 3) * 8;
    const int r1s   = (tid + 256) >> 2;    // idx = tid+256:  row 64..127
    const int seg1  = seg0;                // (idx & 3) identical

    float acc[2][8][4];
    #pragma unroll
    for (int i = 0; i < 2; i++)
        #pragma unroll
        for (int j = 0; j < 8; j++)
            #pragma unroll
            for (int q = 0; q < 4; q++) acc[i][j][q] = 0.f;

    const int niter = K >> 5;              // K / 32

    // ---- issue tile 0 into stage 0 ----
    {
        const uint32_t s0 = sb;
        uint32_t so0 = s0 + (uint32_t)(r0s * 80 + seg0 * 2);
        uint32_t so1 = s0 + (uint32_t)(r1s * 80 + seg1 * 2);
        size_t ga0 = (size_t)(bRow0 + r0s) * K + seg0;
        size_t ga1 = (size_t)(bRow0 + r1s) * K + seg1;
        size_t gb0 = (size_t)(bCol0 + r0s) * K + seg0;
        size_t gb1 = (size_t)(bCol0 + r1s) * K + seg1;
        cp16(so0 + 0 * GARR, Ah_g + ga0);  cp16(so1 + 0 * GARR, Ah_g + ga1);
        cp16(so0 + 1 * GARR, Al_g + ga0);  cp16(so1 + 1 * GARR, Al_g + ga1);
        cp16(so0 + 2 * GARR, Bh_g + gb0);  cp16(so1 + 2 * GARR, Bh_g + gb1);
        cp16(so0 + 3 * GARR, Bl_g + gb0);  cp16(so1 + 3 * GARR, Bl_g + gb1);
        CP_COMMIT();
    }

    for (int it = 0; it < niter; it++) {
        const int st = it & 1;
        CP_WAIT0();                        // tile `it` landed
        __syncthreads();                   // everyone done computing stage st^1

        if (it + 1 < niter) {              // issue tile it+1 into stage st^1
            const uint32_t s0 = sb + (uint32_t)((st ^ 1) * GSTAGE);
            const int kof = (it + 1) * 32;
            uint32_t so0 = s0 + (uint32_t)(r0s * 80 + seg0 * 2);
            uint32_t so1 = s0 + (uint32_t)(r1s * 80 + seg1 * 2);
            size_t ga0 = (size_t)(bRow0 + r0s) * K + kof + seg0;
            size_t ga1 = (size_t)(bRow0 + r1s) * K + kof + seg1;
            size_t gb0 = (size_t)(bCol0 + r0s) * K + kof + seg0;
            size_t gb1 = (size_t)(bCol0 + r1s) * K + kof + seg1;
            cp16(so0 + 0 * GARR, Ah_g + ga0);  cp16(so1 + 0 * GARR, Ah_g + ga1);
            cp16(so0 + 1 * GARR, Al_g + ga0);  cp16(so1 + 1 * GARR, Al_g + ga1);
            cp16(so0 + 2 * GARR, Bh_g + gb0);  cp16(so1 + 2 * GARR, Bh_g + gb1);
            cp16(so0 + 3 * GARR, Bl_g + gb0);  cp16(so1 + 3 * GARR, Bl_g + gb1);
            CP_COMMIT();
        }

        // ---- compute from stage st (mapping identical to R8) ----
        const __nv_bfloat16* Ah = (const __nv_bfloat16*)(smg + st * GSTAGE + 0 * GARR);
        const __nv_bfloat16* Al = (const __nv_bfloat16*)(smg + st * GSTAGE + 1 * GARR);
        const __nv_bfloat16* Bh = (const __nv_bfloat16*)(smg + st * GSTAGE + 2 * GARR);
        const __nv_bfloat16* Bl = (const __nv_bfloat16*)(smg + st * GSTAGE + 3 * GARR);

        #pragma unroll
        for (int ks = 0; ks < 2; ks++) {
            const int kc = ks * 16 + 2 * t;
            uint32_t ah[2][4], al_[2][4];
            #pragma unroll
            for (int mt = 0; mt < 2; mt++) {
                int r = mw + mt * 16 + g;
                ah[mt][0]  = *(const uint32_t*)&Ah[r * GPITCH + kc];
                ah[mt][1]  = *(const uint32_t*)&Ah[(r + 8) * GPITCH + kc];
                ah[mt][2]  = *(const uint32_t*)&Ah[r * GPITCH + kc + 8];
                ah[mt][3]  = *(const uint32_t*)&Ah[(r + 8) * GPITCH + kc + 8];
                al_[mt][0] = *(const uint32_t*)&Al[r * GPITCH + kc];
                al_[mt][1] = *(const uint32_t*)&Al[(r + 8) * GPITCH + kc];
                al_[mt][2] = *(const uint32_t*)&Al[r * GPITCH + kc + 8];
                al_[mt][3] = *(const uint32_t*)&Al[(r + 8) * GPITCH + kc + 8];
            }
            #pragma unroll
            for (int nt = 0; nt < 8; nt++) {
                int n = nw + nt * 8 + g;
                uint32_t bh0 = *(const uint32_t*)&Bh[n * GPITCH + kc];
                uint32_t bh1 = *(const uint32_t*)&Bh[n * GPITCH + kc + 8];
                uint32_t bl0 = *(const uint32_t*)&Bl[n * GPITCH + kc];
                uint32_t bl1 = *(const uint32_t*)&Bl[n * GPITCH + kc + 8];
                #pragma unroll
                for (int mt = 0; mt < 2; mt++) {
                    MMA_BF16(acc[mt][nt], ah[mt][0], ah[mt][1], ah[mt][2], ah[mt][3], bh0, bh1);
                    MMA_BF16(acc[mt][nt], ah[mt][0], ah[mt][1], ah[mt][2], ah[mt][3], bl0, bl1);
                    MMA_BF16(acc[mt][nt], al_[mt][0], al_[mt][1], al_[mt][2], al_[mt][3], bh0, bh1);
                }
            }
        }
    }

    // ---- epilogue: bias + float2 stores (identical to R8) ----
    #pragma unroll
    for (int mt = 0; mt < 2; mt++) {
        #pragma unroll
        for (int nt = 0; nt < 8; nt++) {
            int row = bRow0 + mw + mt * 16 + g;
            int col = bCol0 + nw + nt * 8 + 2 * t;
            float b0v = bias[col], b1v = bias[col + 1];
            float2 o0 = {acc[mt][nt][0] + b0v, acc[mt][nt][1] + b1v};
            float2 o1 = {acc[mt][nt][2] + b0v, acc[mt][nt][3] + b1v};
            *(float2*)(C + (size_t)row * N + col)       = o0;
            *(float2*)(C + (size_t)(row + 8) * N + col) = o1;
        }
    }
}

// ============================================================================
// Tensor-core flash attention v3 (UNCHANGED from R8, validated ~600us):
// 3xBF16 QK^T AND 3xBF16 PV, causal, GQA; K/V pre-split bf16 hi/lo in gmem.
// ============================================================================
#define KP   72
#define SST  68
#define BKH  0
#define BKL  (BKH + 64 * KP * 2)
#define BVH  (BKL + 64 * KP * 2)
#define BVL  (BVH + 64 * KP * 2)
#define BPH  (BVL + 64 * KP * 2)
#define BPL  (BPH + 64 * KP * 2)
#define BSR  (BPL + 64 * KP * 2)
#define BM_  (BSR + 64 * SST * 4)
#define BA_  (BM_ + 64 * 4)
#define BPT  (BA_ + 64 * 4)
#define BL_  (BPT + 64 * 4 * 4)
#define ATT_SMEM_BYTES (BL_ + 64 * 4)

__global__ void __launch_bounds__(256, 2) attn_bf16_kernel(
    const float* __restrict__ Q,
    const __nv_bfloat16* __restrict__ Kbh, const __nv_bfloat16* __restrict__ Kbl,
    const __nv_bfloat16* __restrict__ Vbh, const __nv_bfloat16* __restrict__ Vbl,
    float* __restrict__ Og)
{
    extern __shared__ char smc[];
    __nv_bfloat16* sKh = (__nv_bfloat16*)(smc + BKH);
    __nv_bfloat16* sKl = (__nv_bfloat16*)(smc + BKL);
    __nv_bfloat16* sVh = (__nv_bfloat16*)(smc + BVH);
    __nv_bfloat16* sVl = (__nv_bfloat16*)(smc + BVL);
    __nv_bfloat16* sPh = (__nv_bfloat16*)(smc + BPH);
    __nv_bfloat16* sPl = (__nv_bfloat16*)(smc + BPL);
    float* sSr   = (float*)(smc + BSR);
    float* s_m   = (float*)(smc + BM_);
    float* s_a   = (float*)(smc + BA_);
    float* s_pt  = (float*)(smc + BPT);
    float* s_l   = (float*)(smc + BL_);

    const int qi  = blockIdx.x;
    const int h   = blockIdx.y;
    const int b   = blockIdx.z;
    const int kvh = h >> 2;
    const int tid = threadIdx.x;
    const int q0  = qi * 64;

    const int lane = tid & 31;
    const int w    = tid >> 5;
    const int g    = lane >> 2;
    const int t    = lane & 3;
    const int mw   = (w >> 1) * 16;
    const int nw   = w & 1;
    const int r0   = mw + g;
    const int r1   = r0 + 8;

    const __nv_bfloat16* kbh = Kbh + (size_t)(b * KVH + kvh) * TT * HD;
    const __nv_bfloat16* kbl = Kbl + (size_t)(b * KVH + kvh) * TT * HD;
    const __nv_bfloat16* vbh = Vbh + (size_t)(b * KVH + kvh) * HD * TT;
    const __nv_bfloat16* vbl = Vbl + (size_t)(b * KVH + kvh) * HD * TT;

    uint32_t qh[4][4], ql[4][4];
    {
        const float* q0p = Q + (size_t)(b * TT + q0 + r0) * DM + h * HD;
        const float* q1p = Q + (size_t)(b * TT + q0 + r1) * DM + h * HD;
        #pragma unroll
        for (int ks = 0; ks < 4; ks++) {
            const int kt = ks * 16;
            float v00 = q0p[kt + 2 * t],     v01 = q0p[kt + 2 * t + 1];
            float v10 = q1p[kt + 2 * t],     v11 = q1p[kt + 2 * t + 1];
            float v20 = q0p[kt + 2 * t + 8], v21 = q0p[kt + 2 * t + 9];
            float v30 = q1p[kt + 2 * t + 8], v31 = q1p[kt + 2 * t + 9];
            __nv_bfloat16 h00 = __float2bfloat16(v00), h01 = __float2bfloat16(v01);
            __nv_bfloat16 h10 = __float2bfloat16(v10), h11 = __float2bfloat16(v11);
            __nv_bfloat16 h20 = __float2bfloat16(v20), h21 = __float2bfloat16(v21);
            __nv_bfloat16 h30 = __float2bfloat16(v30), h31 = __float2bfloat16(v31);
            qh[ks][0] = pack_bf2(h00, h01);
            qh[ks][1] = pack_bf2(h10, h11);
            qh[ks][2] = pack_bf2(h20, h21);
            qh[ks][3] = pack_bf2(h30, h31);
            ql[ks][0] = pack_bf2(__float2bfloat16(v00 - __bfloat162float(h00)),
                                 __float2bfloat16(v01 - __bfloat162float(h01)));
            ql[ks][1] = pack_bf2(__float2bfloat16(v10 - __bfloat162float(h10)),
                                 __float2bfloat16(v11 - __bfloat162float(h11)));
            ql[ks][2] = pack_bf2(__float2bfloat16(v20 - __bfloat162float(h20)),
                                 __float2bfloat16(v21 - __bfloat162float(h21)));
            ql[ks][3] = pack_bf2(__float2bfloat16(v30 - __bfloat162float(h30)),
                                 __float2bfloat16(v31 - __bfloat162float(h31)));
        }
    }

    float row_m = -CUDART_INF_F, row_l = 0.f;

    float o[4][4];
    #pragma unroll
    for (int i = 0; i < 4; i++)
        #pragma unroll
        for (int j = 0; j < 4; j++) o[i][j] = 0.f;

    const int nkv = qi + 1;
    for (int it = 0; it < nkv; it++) {
        const int k0 = it * 64;

        #pragma unroll
        for (int i = tid; i < 512; i += 256) {
            const int r = i >> 3, seg = (i & 7) * 8;
            const size_t gk = (size_t)(k0 + r) * HD + seg;
            *(uint4*)&sKh[r * KP + seg] = *(const uint4*)(kbh + gk);
            *(uint4*)&sKl[r * KP + seg] = *(const uint4*)(kbl + gk);
            const size_t gv = (size_t)r * TT + k0 + seg;
            *(uint4*)&sVh[r * KP + seg] = *(const uint4*)(vbh + gv);
            *(uint4*)&sVl[r * KP + seg] = *(const uint4*)(vbl + gv);
        }
        __syncthreads();

        {
            float sc[4][4];
            #pragma unroll
            for (int tn = 0; tn < 4; tn++)
                #pragma unroll
                for (int j = 0; j < 4; j++) sc[tn][j] = 0.f;

            #pragma unroll
            for (int ks = 0; ks < 4; ks++) {
                const int kt = ks * 16;
                #pragma unroll
                for (int tn = 0; tn < 4; tn++) {
                    const int n = nw * 32 + tn * 8 + g;
                    uint32_t bh0 = *(const uint32_t*)&sKh[n * KP + kt + 2 * t];
                    uint32_t bh1 = *(const uint32_t*)&sKh[n * KP + kt + 2 * t + 8];
                    uint32_t bl0 = *(const uint32_t*)&sKl[n * KP + kt + 2 * t];
                    uint32_t bl1 = *(const uint32_t*)&sKl[n * KP + kt + 2 * t + 8];
                    MMA_BF16(sc[tn], qh[ks][0], qh[ks][1], qh[ks][2], qh[ks][3], bh0, bh1);
                    MMA_BF16(sc[tn], qh[ks][0], qh[ks][1], qh[ks][2], qh[ks][3], bl0, bl1);
                    MMA_BF16(sc[tn], ql[ks][0], ql[ks][1], ql[ks][2], ql[ks][3], bh0, bh1);
                }
            }
            const int qg0 = q0 + r0, qg1 = q0 + r1;
            #pragma unroll
            for (int tn = 0; tn < 4; tn++) {
                const int col = nw * 32 + tn * 8 + 2 * t;
                const int kg0 = k0 + col, kg1 = kg0 + 1;
                sSr[r0 * SST + col]     = (kg0 <= qg0) ? sc[tn][0] * 0.125f : -CUDART_INF_F;
                sSr[r0 * SST + col + 1] = (kg1 <= qg0) ? sc[tn][1] * 0.125f : -CUDART_INF_F;
                sSr[r1 * SST + col]     = (kg0 <= qg1) ? sc[tn][2] * 0.125f : -CUDART_INF_F;
                sSr[r1 * SST + col + 1] = (kg1 <= qg1) ? sc[tn][3] * 0.125f : -CUDART_INF_F;
            }
        }
        __syncthreads();

        if (tid < 64) {
            float m = row_m;
            #pragma unroll 8
            for (int c = 0; c < 64; c++) m = fmaxf(m, sSr[tid * SST + c]);
            s_a[tid] = __expf(row_m - m);
            s_m[tid] = m;
            row_m = m;
        }
        __syncthreads();

        {
            const int r  = tid >> 2;
            const int cb = (tid & 3) * 16;
            const float m = s_m[r];
            __nv_bfloat16 ph[16], pl[16];
            float lsum = 0.f;
            #pragma unroll
            for (int j = 0; j < 16; j++) {
                float e = __expf(sSr[r * SST + cb + j] - m);
                lsum += e;
                ph[j] = __float2bfloat16(e);
                pl[j] = __float2bfloat16(e - __bfloat162float(ph[j]));
            }
            uint4 uh0 = {pack_bf2(ph[0], ph[1]),  pack_bf2(ph[2], ph[3]),
                         pack_bf2(ph[4], ph[5]),  pack_bf2(ph[6], ph[7])};
            uint4 uh1 = {pack_bf2(ph[8], ph[9]),  pack_bf2(ph[10], ph[11]),
                         pack_bf2(ph[12], ph[13]), pack_bf2(ph[14], ph[15])};
            uint4 ul0 = {pack_bf2(pl[0], pl[1]),  pack_bf2(pl[2], pl[3]),
                         pack_bf2(pl[4], pl[5]),  pack_bf2(pl[6], pl[7])};
            uint4 ul1 = {pack_bf2(pl[8], pl[9]),  pack_bf2(pl[10], pl[11]),
                         pack_bf2(pl[12], pl[13]), pack_bf2(pl[14], pl[15])};
            *(uint4*)&sPh[r * KP + cb]     = uh0;
            *(uint4*)&sPh[r * KP + cb + 8] = uh1;
            *(uint4*)&sPl[r * KP + cb]     = ul0;
            *(uint4*)&sPl[r * KP + cb + 8] = ul1;
            s_pt[r * 4 + (tid & 3)] = lsum;
        }
        __syncthreads();

        if (tid < 64) {
            row_l = row_l * s_a[tid] +
                    s_pt[tid * 4] + s_pt[tid * 4 + 1] + s_pt[tid * 4 + 2] + s_pt[tid * 4 + 3];
        }
        {
            const float a0f = s_a[r0];
            const float a1f = s_a[r1];
            #pragma unroll
            for (int tn = 0; tn < 4; tn++) {
                o[tn][0] *= a0f; o[tn][1] *= a0f;
                o[tn][2] *= a1f; o[tn][3] *= a1f;
            }
            #pragma unroll
            for (int ks = 0; ks < 4; ks++) {
                const int kt = ks * 16;
                uint32_t p0h = *(const uint32_t*)&sPh[r0 * KP + kt + 2 * t];
                uint32_t p1h = *(const uint32_t*)&sPh[r1 * KP + kt + 2 * t];
                uint32_t p2h = *(const uint32_t*)&sPh[r0 * KP + kt + 2 * t + 8];
                uint32_t p3h = *(const uint32_t*)&sPh[r1 * KP + kt + 2 * t + 8];
                uint32_t p0l = *(const uint32_t*)&sPl[r0 * KP + kt + 2 * t];
                uint32_t p1l = *(const uint32_t*)&sPl[r1 * KP + kt + 2 * t];
                uint32_t p2l = *(const uint32_t*)&sPl[r0 * KP + kt + 2 * t + 8];
                uint32_t p3l = *(const uint32_t*)&sPl[r1 * KP + kt + 2 * t + 8];
                #pragma unroll
                for (int tn = 0; tn < 4; tn++) {
                    const int n = nw * 32 + tn * 8 + g;
                    uint32_t vh0 = *(const uint32_t*)&sVh[n * KP + kt + 2 * t];
                    uint32_t vh1 = *(const uint32_t*)&sVh[n * KP + kt + 2 * t + 8];
                    uint32_t vl0 = *(const uint32_t*)&sVl[n * KP + kt + 2 * t];
                    uint32_t vl1 = *(const uint32_t*)&sVl[n * KP + kt + 2 * t + 8];
                    MMA_BF16(o[tn], p0h, p1h, p2h, p3h, vh0, vh1);
                    MMA_BF16(o[tn], p0h, p1h, p2h, p3h, vl0, vl1);
                    MMA_BF16(o[tn], p0l, p1l, p2l, p3l, vh0, vh1);
                }
            }
        }
        __syncthreads();
    }

    if (tid < 64) s_l[tid] = row_l;
    __syncthreads();

    {
        const float inv0 = 1.0f / s_l[r0];
        const float inv1 = 1.0f / s_l[r1];
        #pragma unroll
        for (int tn = 0; tn < 4; tn++) {
            const int c = nw * 32 + tn * 8 + 2 * t;
            float2 v0 = {o[tn][0] * inv0, o[tn][1] * inv0};
            float2 v1 = {o[tn][2] * inv1, o[tn][3] * inv1};
            *(float2*)(Og + (size_t)(b * TT + q0 + r0) * DM + h * HD + c) = v0;
            *(float2*)(Og + (size_t)(b * TT + q0 + r1) * DM + h * HD + c) = v1;
        }
    }
}

// ============================================================================
// kernel_launch: graph-capturable launches, no allocations, no syncs.
// ============================================================================
extern "C" void kernel_launch(void* const* d_in, const int* in_sizes, int n_in,
                              void* d_out, int out_size)
{
    const float* x  = (const float*)d_in[0];
    const float* Wq = (const float*)d_in[1];
    const float* bq = (const float*)d_in[2];
    const float* Wk = (const float*)d_in[3];
    const float* bk = (const float*)d_in[4];
    const float* Wv = (const float*)d_in[5];
    const float* bv = (const float*)d_in[6];
    const float* Wo = (const float*)d_in[7];
    const float* bo = (const float*)d_in[8];
    float* out = (float*)d_out;

    float *q, *k, *v, *att;
    cudaGetSymbolAddress((void**)&q,   g_q);
    cudaGetSymbolAddress((void**)&k,   g_k);
    cudaGetSymbolAddress((void**)&v,   g_v);
    cudaGetSymbolAddress((void**)&att, g_att);
    __nv_bfloat16 *wqh, *wql, *wkh, *wkl, *wvh, *wvl, *woh, *wol;
    cudaGetSymbolAddress((void**)&wqh, g_wqh);
    cudaGetSymbolAddress((void**)&wql, g_wql);
    cudaGetSymbolAddress((void**)&wkh, g_wkh);
    cudaGetSymbolAddress((void**)&wkl, g_wkl);
    cudaGetSymbolAddress((void**)&wvh, g_wvh);
    cudaGetSymbolAddress((void**)&wvl, g_wvl);
    cudaGetSymbolAddress((void**)&woh, g_woh);
    cudaGetSymbolAddress((void**)&wol, g_wol);
    __nv_bfloat16 *xh, *xl, *ath, *atl;
    cudaGetSymbolAddress((void**)&xh,  g_xh);
    cudaGetSymbolAddress((void**)&xl,  g_xl);
    cudaGetSymbolAddress((void**)&ath, g_ath);
    cudaGetSymbolAddress((void**)&atl, g_atl);
    __nv_bfloat16 *kbh, *kbl, *vbh, *vbl;
    cudaGetSymbolAddress((void**)&kbh, g_kbh);
    cudaGetSymbolAddress((void**)&kbl, g_kbl);
    cudaGetSymbolAddress((void**)&vbh, g_vbh);
    cudaGetSymbolAddress((void**)&vbl, g_vbl);

    cudaFuncSetAttribute(attn_bf16_kernel,
                         cudaFuncAttributeMaxDynamicSharedMemorySize, ATT_SMEM_BYTES);
    cudaFuncSetAttribute(gemm_bf3_cp_kernel,
                         cudaFuncAttributeMaxDynamicSharedMemorySize, GEMM_SMEM_BYTES);

    dim3 cblk(32, 8);
    dim3 blk(256);

    // weight pre-pass
    convert_w_kernel<<<dim3(DM / 32, DM / 32),  cblk>>>(Wq, wqh, wql, DM, DM);
    convert_w_kernel<<<dim3(NKV / 32, DM / 32), cblk>>>(Wk, wkh, wkl, DM, NKV);
    convert_w_kernel<<<dim3(NKV / 32, DM / 32), cblk>>>(Wv, wvh, wvl, DM, NKV);
    convert_w_kernel<<<dim3(DM / 32, DM / 32),  cblk>>>(Wo, woh, wol, DM, DM);

    // x pre-split
    convert_a_kernel<<<(MROWS * DM / 4) / 256, blk>>>(x, xh, xl);

    // projections (3xBF16, cp.async double-buffered)
    gemm_bf3_cp_kernel<<<dim3(DM / 128, MROWS / 128), blk, GEMM_SMEM_BYTES>>>(
        xh, xl, wqh, wql, bq, q, MROWS, DM, DM);
    gemm_bf3_cp_kernel<<<dim3(NKV / 128, MROWS / 128), blk, GEMM_SMEM_BYTES>>>(
        xh, xl, wkh, wkl, bk, k, MROWS, NKV, DM);
    gemm_bf3_cp_kernel<<<dim3(NKV / 128, MROWS / 128), blk, GEMM_SMEM_BYTES>>>(
        xh, xl, wvh, wvl, bv, v, MROWS, NKV, DM);

    // K/V pre-split for attention
    convert_k_kernel<<<(MROWS * NKV / 4) / 256, blk>>>(k, kbh, kbl);
    convert_vT_kernel<<<dim3(TT / 32, HD / 32, BB * KVH), cblk>>>(v, vbh, vbl);

    // causal GQA attention (3xBF16 mma.sync)
    attn_bf16_kernel<<<dim3(TT / 64, QH, BB), blk, ATT_SMEM_BYTES>>>(
        q, kbh, kbl, vbh, vbl, att);

    // att pre-split + output projection
    convert_a_kernel<<<(MROWS * DM / 4) / 256, blk>>>(att, ath, atl);
    gemm_bf3_cp_kernel<<<dim3(DM / 128, MROWS / 128), blk, GEMM_SMEM_BYTES>>>(
        ath, atl, woh, wol, bo, out, MROWS, DM, DM);
}

// round 15
// speedup vs baseline: 3.5009x; 1.0038x over previous
#include <cuda_runtime.h>
#include <cuda_bf16.h>
#include <math_constants.h>
#include <stdint.h>

// ---------------- problem constants ----------------
#define DM    2048              // d_model
#define QH    32                // q heads
#define KVH   8                 // kv heads
#define HD    64                // head dim
#define BB    2                 // batch
#define TT    2048              // seq len
#define MROWS (BB * TT)         // 4096 rows for all GEMMs
#define NKV   (KVH * HD)        // 512

// ---------------- scratch (device globals; no allocation allowed) ----------------
__device__ __align__(16) float g_q[(size_t)MROWS * DM];
__device__ __align__(16) float g_k[(size_t)MROWS * NKV];
__device__ __align__(16) float g_v[(size_t)MROWS * NKV];
// transposed bf16 hi/lo weights: [N][K] layout, K = DM
__device__ __align__(16) __nv_bfloat16 g_wqh[(size_t)DM * DM],  g_wql[(size_t)DM * DM];
__device__ __align__(16) __nv_bfloat16 g_wkh[(size_t)NKV * DM], g_wkl[(size_t)NKV * DM];
__device__ __align__(16) __nv_bfloat16 g_wvh[(size_t)NKV * DM], g_wvl[(size_t)NKV * DM];
__device__ __align__(16) __nv_bfloat16 g_woh[(size_t)DM * DM],  g_wol[(size_t)DM * DM];
// pre-split GEMM A operands: [M][K] bf16 hi/lo
__device__ __align__(16) __nv_bfloat16 g_xh[(size_t)MROWS * DM],  g_xl[(size_t)MROWS * DM];
__device__ __align__(16) __nv_bfloat16 g_ath[(size_t)MROWS * DM], g_atl[(size_t)MROWS * DM];
// pre-split K/V for attention: K as [b,kvh][t][d] bf16 hi/lo; V TRANSPOSED [b,kvh][d][t]
__device__ __align__(16) __nv_bfloat16 g_kbh[(size_t)BB * KVH * TT * HD], g_kbl[(size_t)BB * KVH * TT * HD];
__device__ __align__(16) __nv_bfloat16 g_vbh[(size_t)BB * KVH * TT * HD], g_vbl[(size_t)BB * KVH * TT * HD];

#define MMA_BF16(cc, a0, a1, a2, a3, b0, b1)                               \
    asm volatile(                                                          \
        "mma.sync.aligned.m16n8k16.row.col.f32.bf16.bf16.f32 "             \
        "{%0,%1,%2,%3}, {%4,%5,%6,%7}, {%8,%9}, {%0,%1,%2,%3};"            \
        : "+f"(cc[0]), "+f"(cc[1]), "+f"(cc[2]), "+f"(cc[3])               \
        : "r"(a0), "r"(a1), "r"(a2), "r"(a3), "r"(b0), "r"(b1))

__device__ __forceinline__ uint32_t pack_bf2(__nv_bfloat16 a, __nv_bfloat16 b) {
    return (uint32_t)__bfloat16_as_ushort(a) | ((uint32_t)__bfloat16_as_ushort(b) << 16);
}

__device__ __forceinline__ uint32_t smem_u32(const void* p) {
    uint32_t a;
    asm("{ .reg .u64 t; cvta.to.shared.u64 t, %1; cvt.u32.u64 %0, t; }" : "=r"(a) : "l"(p));
    return a;
}

__device__ __forceinline__ void cp16(uint32_t saddr, const void* g) {
    asm volatile("cp.async.ca.shared.global [%0], [%1], 16;" :: "r"(saddr), "l"(g));
}
#define CP_COMMIT() asm volatile("cp.async.commit_group;" ::: "memory")
#define CP_WAIT0()  asm volatile("cp.async.wait_group 0;" ::: "memory")

// ============================================================================
// Pre-pass: W [K][N] fp32  ->  Wh/Wl [N][K] bf16 (hi/lo), tiled transpose.
// ============================================================================
__global__ void __launch_bounds__(256) convert_w_kernel(
    const float* __restrict__ W,
    __nv_bfloat16* __restrict__ Wh, __nv_bfloat16* __restrict__ Wl,
    int K, int N)
{
    __shared__ float ts[32][33];
    const int n0 = blockIdx.x * 32, k0 = blockIdx.y * 32;
    const int tx = threadIdx.x, ty = threadIdx.y;
    #pragma unroll
    for (int i = 0; i < 4; i++)
        ts[ty + i * 8][tx] = W[(size_t)(k0 + ty + i * 8) * N + n0 + tx];
    __syncthreads();
    #pragma unroll
    for (int i = 0; i < 4; i++) {
        float v = ts[tx][ty + i * 8];
        __nv_bfloat16 h = __float2bfloat16(v);
        __nv_bfloat16 l = __float2bfloat16(v - __bfloat162float(h));
        size_t o = (size_t)(n0 + ty + i * 8) * K + k0 + tx;
        Wh[o] = h;
        Wl[o] = l;
    }
}

// ============================================================================
// Pre-pass: A [M*K] fp32 -> bf16 hi/lo [M*K] (elementwise, no transpose).
// ============================================================================
__global__ void __launch_bounds__(256) convert_a_kernel(
    const float* __restrict__ src,
    __nv_bfloat16* __restrict__ dh, __nv_bfloat16* __restrict__ dl)
{
    size_t e0 = ((size_t)blockIdx.x * 256 + threadIdx.x) * 4;
    float4 v = *(const float4*)(src + e0);
    float vv[4] = {v.x, v.y, v.z, v.w};
    __nv_bfloat16 h[4], l[4];
    #pragma unroll
    for (int j = 0; j < 4; j++) {
        h[j] = __float2bfloat16(vv[j]);
        l[j] = __float2bfloat16(vv[j] - __bfloat162float(h[j]));
    }
    *(uint2*)(dh + e0) = make_uint2(pack_bf2(h[0], h[1]), pack_bf2(h[2], h[3]));
    *(uint2*)(dl + e0) = make_uint2(pack_bf2(l[0], l[1]), pack_bf2(l[2], l[3]));
}

// ============================================================================
// Pre-pass: K fp32 [b*TT+t][NKV] -> [b,kvh][t][d] bf16 hi/lo (reshape only).
// ============================================================================
__global__ void __launch_bounds__(256) convert_k_kernel(
    const float* __restrict__ src,
    __nv_bfloat16* __restrict__ dh, __nv_bfloat16* __restrict__ dl)
{
    size_t e0 = ((size_t)blockIdx.x * 256 + threadIdx.x) * 4;
    int row = (int)(e0 >> 9);
    int c   = (int)(e0 & 511);
    int kvh = c >> 6, d = c & 63;
    int b   = row >> 11, t = row & 2047;
    float4 v = *(const float4*)(src + e0);
    float vv[4] = {v.x, v.y, v.z, v.w};
    __nv_bfloat16 h[4], l[4];
    #pragma unroll
    for (int j = 0; j < 4; j++) {
        h[j] = __float2bfloat16(vv[j]);
        l[j] = __float2bfloat16(vv[j] - __bfloat162float(h[j]));
    }
    size_t o = ((size_t)(b * KVH + kvh) * TT + t) * HD + d;
    *(uint2*)(dh + o) = make_uint2(pack_bf2(h[0], h[1]), pack_bf2(h[2], h[3]));
    *(uint2*)(dl + o) = make_uint2(pack_bf2(l[0], l[1]), pack_bf2(l[2], l[3]));
}

// ============================================================================
// Pre-pass: V fp32 [b*TT+t][NKV] -> TRANSPOSED [b,kvh][d][t] bf16 hi/lo.
// ============================================================================
__global__ void __launch_bounds__(256) convert_vT_kernel(
    const float* __restrict__ src,
    __nv_bfloat16* __restrict__ dh, __nv_bfloat16* __restrict__ dl)
{
    __shared__ float ts[32][33];
    const int bz  = blockIdx.z;
    const int b   = bz >> 3, kvh = bz & 7;
    const int t0  = blockIdx.x * 32, d0 = blockIdx.y * 32;
    const int tx  = threadIdx.x, ty = threadIdx.y;
    #pragma unroll
    for (int i = 0; i < 4; i++)
        ts[ty + i * 8][tx] = src[((size_t)b * TT + t0 + ty + i * 8) * NKV + kvh * HD + d0 + tx];
    __syncthreads();
    #pragma unroll
    for (int i = 0; i < 4; i++) {
        float v = ts[tx][ty + i * 8];
        __nv_bfloat16 h = __float2bfloat16(v);
        __nv_bfloat16 l = __float2bfloat16(v - __bfloat162float(h));
        size_t o = ((size_t)(b * KVH + kvh) * HD + d0 + ty + i * 8) * TT + t0 + tx;
        dh[o] = h;
        dl[o] = l;
    }
}

// ============================================================================
// 3xBF16 GEMM (UNCHANGED from R12, validated): cp.async double-buffered.
// ============================================================================
#define GPITCH 40
#define GARR   (128 * GPITCH * 2)
#define GSTAGE (4 * GARR)
#define GEMM_SMEM_BYTES (2 * GSTAGE)

__global__ void __launch_bounds__(256) gemm_bf3_cp_kernel(
    const __nv_bfloat16* __restrict__ Ah_g, const __nv_bfloat16* __restrict__ Al_g,
    const __nv_bfloat16* __restrict__ Bh_g, const __nv_bfloat16* __restrict__ Bl_g,
    const float* __restrict__ bias, float* __restrict__ C,
    int M, int N, int K)
{
    extern __shared__ char smg[];
    const uint32_t sb = smem_u32(smg);

    const int tid  = threadIdx.x;
    const int lane = tid & 31;
    const int w    = tid >> 5;
    const int g    = lane >> 2;
    const int t    = lane & 3;
    const int mw   = (w >> 1) * 32;
    const int nw   = (w & 1) * 64;
    const int bRow0 = blockIdx.y * 128;
    const int bCol0 = blockIdx.x * 128;

    const int r0s   = tid >> 2;
    const int seg0  = (tid & 3) * 8;
    const int r1s   = (tid + 256) >> 2;
    const int seg1  = seg0;

    float acc[2][8][4];
    #pragma unroll
    for (int i = 0; i < 2; i++)
        #pragma unroll
        for (int j = 0; j < 8; j++)
            #pragma unroll
            for (int q = 0; q < 4; q++) acc[i][j][q] = 0.f;

    const int niter = K >> 5;

    {
        const uint32_t s0 = sb;
        uint32_t so0 = s0 + (uint32_t)(r0s * 80 + seg0 * 2);
        uint32_t so1 = s0 + (uint32_t)(r1s * 80 + seg1 * 2);
        size_t ga0 = (size_t)(bRow0 + r0s) * K + seg0;
        size_t ga1 = (size_t)(bRow0 + r1s) * K + seg1;
        size_t gb0 = (size_t)(bCol0 + r0s) * K + seg0;
        size_t gb1 = (size_t)(bCol0 + r1s) * K + seg1;
        cp16(so0 + 0 * GARR, Ah_g + ga0);  cp16(so1 + 0 * GARR, Ah_g + ga1);
        cp16(so0 + 1 * GARR, Al_g + ga0);  cp16(so1 + 1 * GARR, Al_g + ga1);
        cp16(so0 + 2 * GARR, Bh_g + gb0);  cp16(so1 + 2 * GARR, Bh_g + gb1);
        cp16(so0 + 3 * GARR, Bl_g + gb0);  cp16(so1 + 3 * GARR, Bl_g + gb1);
        CP_COMMIT();
    }

    for (int it = 0; it < niter; it++) {
        const int st = it & 1;
        CP_WAIT0();
        __syncthreads();

        if (it + 1 < niter) {
            const uint32_t s0 = sb + (uint32_t)((st ^ 1) * GSTAGE);
            const int kof = (it + 1) * 32;
            uint32_t so0 = s0 + (uint32_t)(r0s * 80 + seg0 * 2);
            uint32_t so1 = s0 + (uint32_t)(r1s * 80 + seg1 * 2);
            size_t ga0 = (size_t)(bRow0 + r0s) * K + kof + seg0;
            size_t ga1 = (size_t)(bRow0 + r1s) * K + kof + seg1;
            size_t gb0 = (size_t)(bCol0 + r0s) * K + kof + seg0;
            size_t gb1 = (size_t)(bCol0 + r1s) * K + kof + seg1;
            cp16(so0 + 0 * GARR, Ah_g + ga0);  cp16(so1 + 0 * GARR, Ah_g + ga1);
            cp16(so0 + 1 * GARR, Al_g + ga0);  cp16(so1 + 1 * GARR, Al_g + ga1);
            cp16(so0 + 2 * GARR, Bh_g + gb0);  cp16(so1 + 2 * GARR, Bh_g + gb1);
            cp16(so0 + 3 * GARR, Bl_g + gb0);  cp16(so1 + 3 * GARR, Bl_g + gb1);
            CP_COMMIT();
        }

        const __nv_bfloat16* Ah = (const __nv_bfloat16*)(smg + st * GSTAGE + 0 * GARR);
        const __nv_bfloat16* Al = (const __nv_bfloat16*)(smg + st * GSTAGE + 1 * GARR);
        const __nv_bfloat16* Bh = (const __nv_bfloat16*)(smg + st * GSTAGE + 2 * GARR);
        const __nv_bfloat16* Bl = (const __nv_bfloat16*)(smg + st * GSTAGE + 3 * GARR);

        #pragma unroll
        for (int ks = 0; ks < 2; ks++) {
            const int kc = ks * 16 + 2 * t;
            uint32_t ah[2][4], al_[2][4];
            #pragma unroll
            for (int mt = 0; mt < 2; mt++) {
                int r = mw + mt * 16 + g;
                ah[mt][0]  = *(const uint32_t*)&Ah[r * GPITCH + kc];
                ah[mt][1]  = *(const uint32_t*)&Ah[(r + 8) * GPITCH + kc];
                ah[mt][2]  = *(const uint32_t*)&Ah[r * GPITCH + kc + 8];
                ah[mt][3]  = *(const uint32_t*)&Ah[(r + 8) * GPITCH + kc + 8];
                al_[mt][0] = *(const uint32_t*)&Al[r * GPITCH + kc];
                al_[mt][1] = *(const uint32_t*)&Al[(r + 8) * GPITCH + kc];
                al_[mt][2] = *(const uint32_t*)&Al[r * GPITCH + kc + 8];
                al_[mt][3] = *(const uint32_t*)&Al[(r + 8) * GPITCH + kc + 8];
            }
            #pragma unroll
            for (int nt = 0; nt < 8; nt++) {
                int n = nw + nt * 8 + g;
                uint32_t bh0 = *(const uint32_t*)&Bh[n * GPITCH + kc];
                uint32_t bh1 = *(const uint32_t*)&Bh[n * GPITCH + kc + 8];
                uint32_t bl0 = *(const uint32_t*)&Bl[n * GPITCH + kc];
                uint32_t bl1 = *(const uint32_t*)&Bl[n * GPITCH + kc + 8];
                #pragma unroll
                for (int mt = 0; mt < 2; mt++) {
                    MMA_BF16(acc[mt][nt], ah[mt][0], ah[mt][1], ah[mt][2], ah[mt][3], bh0, bh1);
                    MMA_BF16(acc[mt][nt], ah[mt][0], ah[mt][1], ah[mt][2], ah[mt][3], bl0, bl1);
                    MMA_BF16(acc[mt][nt], al_[mt][0], al_[mt][1], al_[mt][2], al_[mt][3], bh0, bh1);
                }
            }
        }
    }

    #pragma unroll
    for (int mt = 0; mt < 2; mt++) {
        #pragma unroll
        for (int nt = 0; nt < 8; nt++) {
            int row = bRow0 + mw + mt * 16 + g;
            int col = bCol0 + nw + nt * 8 + 2 * t;
            float b0v = bias[col], b1v = bias[col + 1];
            float2 o0 = {acc[mt][nt][0] + b0v, acc[mt][nt][1] + b1v};
            float2 o1 = {acc[mt][nt][2] + b0v, acc[mt][nt][3] + b1v};
            *(float2*)(C + (size_t)row * N + col)       = o0;
            *(float2*)(C + (size_t)(row + 8) * N + col) = o1;
        }
    }
}

// ============================================================================
// Flash attention (R12-validated structure: 5-sync softmax, sSr buffer).
// ONLY change vs R12: epilogue writes bf16 hi/lo output directly (Oh/Ol),
// replacing the fp32 att write + separate convert_a pass.
// ============================================================================
#define KP   72
#define SST  68
#define BKH  0
#define BKL  (BKH + 64 * KP * 2)
#define BVH  (BKL + 64 * KP * 2)
#define BVL  (BVH + 64 * KP * 2)
#define BPH  (BVL + 64 * KP * 2)
#define BPL  (BPH + 64 * KP * 2)
#define BSR  (BPL + 64 * KP * 2)
#define BM_  (BSR + 64 * SST * 4)
#define BA_  (BM_ + 64 * 4)
#define BPT  (BA_ + 64 * 4)
#define BL_  (BPT + 64 * 4 * 4)
#define ATT_SMEM_BYTES (BL_ + 64 * 4)

__global__ void __launch_bounds__(256, 2) attn_bf16_kernel(
    const float* __restrict__ Q,
    const __nv_bfloat16* __restrict__ Kbh, const __nv_bfloat16* __restrict__ Kbl,
    const __nv_bfloat16* __restrict__ Vbh, const __nv_bfloat16* __restrict__ Vbl,
    __nv_bfloat16* __restrict__ Oh, __nv_bfloat16* __restrict__ Ol)
{
    extern __shared__ char smc[];
    __nv_bfloat16* sKh = (__nv_bfloat16*)(smc + BKH);
    __nv_bfloat16* sKl = (__nv_bfloat16*)(smc + BKL);
    __nv_bfloat16* sVh = (__nv_bfloat16*)(smc + BVH);
    __nv_bfloat16* sVl = (__nv_bfloat16*)(smc + BVL);
    __nv_bfloat16* sPh = (__nv_bfloat16*)(smc + BPH);
    __nv_bfloat16* sPl = (__nv_bfloat16*)(smc + BPL);
    float* sSr   = (float*)(smc + BSR);
    float* s_m   = (float*)(smc + BM_);
    float* s_a   = (float*)(smc + BA_);
    float* s_pt  = (float*)(smc + BPT);
    float* s_l   = (float*)(smc + BL_);

    const int qi  = blockIdx.x;
    const int h   = blockIdx.y;
    const int b   = blockIdx.z;
    const int kvh = h >> 2;
    const int tid = threadIdx.x;
    const int q0  = qi * 64;

    const int lane = tid & 31;
    const int w    = tid >> 5;
    const int g    = lane >> 2;
    const int t    = lane & 3;
    const int mw   = (w >> 1) * 16;
    const int nw   = w & 1;
    const int r0   = mw + g;
    const int r1   = r0 + 8;

    const __nv_bfloat16* kbh = Kbh + (size_t)(b * KVH + kvh) * TT * HD;
    const __nv_bfloat16* kbl = Kbl + (size_t)(b * KVH + kvh) * TT * HD;
    const __nv_bfloat16* vbh = Vbh + (size_t)(b * KVH + kvh) * HD * TT;
    const __nv_bfloat16* vbl = Vbl + (size_t)(b * KVH + kvh) * HD * TT;

    uint32_t qh[4][4], ql[4][4];
    {
        const float* q0p = Q + (size_t)(b * TT + q0 + r0) * DM + h * HD;
        const float* q1p = Q + (size_t)(b * TT + q0 + r1) * DM + h * HD;
        #pragma unroll
        for (int ks = 0; ks < 4; ks++) {
            const int kt = ks * 16;
            float v00 = q0p[kt + 2 * t],     v01 = q0p[kt + 2 * t + 1];
            float v10 = q1p[kt + 2 * t],     v11 = q1p[kt + 2 * t + 1];
            float v20 = q0p[kt + 2 * t + 8], v21 = q0p[kt + 2 * t + 9];
            float v30 = q1p[kt + 2 * t + 8], v31 = q1p[kt + 2 * t + 9];
            __nv_bfloat16 h00 = __float2bfloat16(v00), h01 = __float2bfloat16(v01);
            __nv_bfloat16 h10 = __float2bfloat16(v10), h11 = __float2bfloat16(v11);
            __nv_bfloat16 h20 = __float2bfloat16(v20), h21 = __float2bfloat16(v21);
            __nv_bfloat16 h30 = __float2bfloat16(v30), h31 = __float2bfloat16(v31);
            qh[ks][0] = pack_bf2(h00, h01);
            qh[ks][1] = pack_bf2(h10, h11);
            qh[ks][2] = pack_bf2(h20, h21);
            qh[ks][3] = pack_bf2(h30, h31);
            ql[ks][0] = pack_bf2(__float2bfloat16(v00 - __bfloat162float(h00)),
                                 __float2bfloat16(v01 - __bfloat162float(h01)));
            ql[ks][1] = pack_bf2(__float2bfloat16(v10 - __bfloat162float(h10)),
                                 __float2bfloat16(v11 - __bfloat162float(h11)));
            ql[ks][2] = pack_bf2(__float2bfloat16(v20 - __bfloat162float(h20)),
                                 __float2bfloat16(v21 - __bfloat162float(h21)));
            ql[ks][3] = pack_bf2(__float2bfloat16(v30 - __bfloat162float(h30)),
                                 __float2bfloat16(v31 - __bfloat162float(h31)));
        }
    }

    float row_m = -CUDART_INF_F, row_l = 0.f;

    float o[4][4];
    #pragma unroll
    for (int i = 0; i < 4; i++)
        #pragma unroll
        for (int j = 0; j < 4; j++) o[i][j] = 0.f;

    const int nkv = qi + 1;
    for (int it = 0; it < nkv; it++) {
        const int k0 = it * 64;

        #pragma unroll
        for (int i = tid; i < 512; i += 256) {
            const int r = i >> 3, seg = (i & 7) * 8;
            const size_t gk = (size_t)(k0 + r) * HD + seg;
            *(uint4*)&sKh[r * KP + seg] = *(const uint4*)(kbh + gk);
            *(uint4*)&sKl[r * KP + seg] = *(const uint4*)(kbl + gk);
            const size_t gv = (size_t)r * TT + k0 + seg;
            *(uint4*)&sVh[r * KP + seg] = *(const uint4*)(vbh + gv);
            *(uint4*)&sVl[r * KP + seg] = *(const uint4*)(vbl + gv);
        }
        __syncthreads();

        {
            float sc[4][4];
            #pragma unroll
            for (int tn = 0; tn < 4; tn++)
                #pragma unroll
                for (int j = 0; j < 4; j++) sc[tn][j] = 0.f;

            #pragma unroll
            for (int ks = 0; ks < 4; ks++) {
                const int kt = ks * 16;
                #pragma unroll
                for (int tn = 0; tn < 4; tn++) {
                    const int n = nw * 32 + tn * 8 + g;
                    uint32_t bh0 = *(const uint32_t*)&sKh[n * KP + kt + 2 * t];
                    uint32_t bh1 = *(const uint32_t*)&sKh[n * KP + kt + 2 * t + 8];
                    uint32_t bl0 = *(const uint32_t*)&sKl[n * KP + kt + 2 * t];
                    uint32_t bl1 = *(const uint32_t*)&sKl[n * KP + kt + 2 * t + 8];
                    MMA_BF16(sc[tn], qh[ks][0], qh[ks][1], qh[ks][2], qh[ks][3], bh0, bh1);
                    MMA_BF16(sc[tn], qh[ks][0], qh[ks][1], qh[ks][2], qh[ks][3], bl0, bl1);
                    MMA_BF16(sc[tn], ql[ks][0], ql[ks][1], ql[ks][2], ql[ks][3], bh0, bh1);
                }
            }
            const int qg0 = q0 + r0, qg1 = q0 + r1;
            #pragma unroll
            for (int tn = 0; tn < 4; tn++) {
                const int col = nw * 32 + tn * 8 + 2 * t;
                const int kg0 = k0 + col, kg1 = kg0 + 1;
                sSr[r0 * SST + col]     = (kg0 <= qg0) ? sc[tn][0] * 0.125f : -CUDART_INF_F;
                sSr[r0 * SST + col + 1] = (kg1 <= qg0) ? sc[tn][1] * 0.125f : -CUDART_INF_F;
                sSr[r1 * SST + col]     = (kg0 <= qg1) ? sc[tn][2] * 0.125f : -CUDART_INF_F;
                sSr[r1 * SST + col + 1] = (kg1 <= qg1) ? sc[tn][3] * 0.125f : -CUDART_INF_F;
            }
        }
        __syncthreads();

        if (tid < 64) {
            float m = row_m;
            #pragma unroll 8
            for (int c = 0; c < 64; c++) m = fmaxf(m, sSr[tid * SST + c]);
            s_a[tid] = __expf(row_m - m);
            s_m[tid] = m;
            row_m = m;
        }
        __syncthreads();

        {
            const int r  = tid >> 2;
            const int cb = (tid & 3) * 16;
            const float m = s_m[r];
            __nv_bfloat16 ph[16], pl[16];
            float lsum = 0.f;
            #pragma unroll
            for (int j = 0; j < 16; j++) {
                float e = __expf(sSr[r * SST + cb + j] - m);
                lsum += e;
                ph[j] = __float2bfloat16(e);
                pl[j] = __float2bfloat16(e - __bfloat162float(ph[j]));
            }
            uint4 uh0 = {pack_bf2(ph[0], ph[1]),  pack_bf2(ph[2], ph[3]),
                         pack_bf2(ph[4], ph[5]),  pack_bf2(ph[6], ph[7])};
            uint4 uh1 = {pack_bf2(ph[8], ph[9]),  pack_bf2(ph[10], ph[11]),
                         pack_bf2(ph[12], ph[13]), pack_bf2(ph[14], ph[15])};
            uint4 ul0 = {pack_bf2(pl[0], pl[1]),  pack_bf2(pl[2], pl[3]),
                         pack_bf2(pl[4], pl[5]),  pack_bf2(pl[6], pl[7])};
            uint4 ul1 = {pack_bf2(pl[8], pl[9]),  pack_bf2(pl[10], pl[11]),
                         pack_bf2(pl[12], pl[13]), pack_bf2(pl[14], pl[15])};
            *(uint4*)&sPh[r * KP + cb]     = uh0;
            *(uint4*)&sPh[r * KP + cb + 8] = uh1;
            *(uint4*)&sPl[r * KP + cb]     = ul0;
            *(uint4*)&sPl[r * KP + cb + 8] = ul1;
            s_pt[r * 4 + (tid & 3)] = lsum;
        }
        __syncthreads();

        if (tid < 64) {
            row_l = row_l * s_a[tid] +
                    s_pt[tid * 4] + s_pt[tid * 4 + 1] + s_pt[tid * 4 + 2] + s_pt[tid * 4 + 3];
        }
        {
            const float a0f = s_a[r0];
            const float a1f = s_a[r1];
            #pragma unroll
            for (int tn = 0; tn < 4; tn++) {
                o[tn][0] *= a0f; o[tn][1] *= a0f;
                o[tn][2] *= a1f; o[tn][3] *= a1f;
            }
            #pragma unroll
            for (int ks = 0; ks < 4; ks++) {
                const int kt = ks * 16;
                uint32_t p0h = *(const uint32_t*)&sPh[r0 * KP + kt + 2 * t];
                uint32_t p1h = *(const uint32_t*)&sPh[r1 * KP + kt + 2 * t];
                uint32_t p2h = *(const uint32_t*)&sPh[r0 * KP + kt + 2 * t + 8];
                uint32_t p3h = *(const uint32_t*)&sPh[r1 * KP + kt + 2 * t + 8];
                uint32_t p0l = *(const uint32_t*)&sPl[r0 * KP + kt + 2 * t];
                uint32_t p1l = *(const uint32_t*)&sPl[r1 * KP + kt + 2 * t];
                uint32_t p2l = *(const uint32_t*)&sPl[r0 * KP + kt + 2 * t + 8];
                uint32_t p3l = *(const uint32_t*)&sPl[r1 * KP + kt + 2 * t + 8];
                #pragma unroll
                for (int tn = 0; tn < 4; tn++) {
                    const int n = nw * 32 + tn * 8 + g;
                    uint32_t vh0 = *(const uint32_t*)&sVh[n * KP + kt + 2 * t];
                    uint32_t vh1 = *(const uint32_t*)&sVh[n * KP + kt + 2 * t + 8];
                    uint32_t vl0 = *(const uint32_t*)&sVl[n * KP + kt + 2 * t];
                    uint32_t vl1 = *(const uint32_t*)&sVl[n * KP + kt + 2 * t + 8];
                    MMA_BF16(o[tn], p0h, p1h, p2h, p3h, vh0, vh1);
                    MMA_BF16(o[tn], p0h, p1h, p2h, p3h, vl0, vl1);
                    MMA_BF16(o[tn], p0l, p1l, p2l, p3l, vh0, vh1);
                }
            }
        }
        __syncthreads();
    }

    if (tid < 64) s_l[tid] = row_l;
    __syncthreads();

    // ---- normalize + write bf16 hi/lo output directly (ONLY change vs R12) ----
    {
        const float inv0 = 1.0f / s_l[r0];
        const float inv1 = 1.0f / s_l[r1];
        const size_t row0 = (size_t)(b * TT + q0 + r0) * DM + h * HD;
        const size_t row1 = (size_t)(b * TT + q0 + r1) * DM + h * HD;
        #pragma unroll
        for (int tn = 0; tn < 4; tn++) {
            const int c = nw * 32 + tn * 8 + 2 * t;
            float v00 = o[tn][0] * inv0, v01 = o[tn][1] * inv0;
            float v10 = o[tn][2] * inv1, v11 = o[tn][3] * inv1;
            __nv_bfloat16 h00 = __float2bfloat16(v00), h01 = __float2bfloat16(v01);
            __nv_bfloat16 h10 = __float2bfloat16(v10), h11 = __float2bfloat16(v11);
            *(uint32_t*)(Oh + row0 + c) = pack_bf2(h00, h01);
            *(uint32_t*)(Oh + row1 + c) = pack_bf2(h10, h11);
            *(uint32_t*)(Ol + row0 + c) =
                pack_bf2(__float2bfloat16(v00 - __bfloat162float(h00)),
                         __float2bfloat16(v01 - __bfloat162float(h01)));
            *(uint32_t*)(Ol + row1 + c) =
                pack_bf2(__float2bfloat16(v10 - __bfloat162float(h10)),
                         __float2bfloat16(v11 - __bfloat162float(h11)));
        }
    }
}

// ============================================================================
// kernel_launch: graph-capturable launches, no allocations, no syncs.
// ============================================================================
extern "C" void kernel_launch(void* const* d_in, const int* in_sizes, int n_in,
                              void* d_out, int out_size)
{
    const float* x  = (const float*)d_in[0];
    const float* Wq = (const float*)d_in[1];
    const float* bq = (const float*)d_in[2];
    const float* Wk = (const float*)d_in[3];
    const float* bk = (const float*)d_in[4];
    const float* Wv = (const float*)d_in[5];
    const float* bv = (const float*)d_in[6];
    const float* Wo = (const float*)d_in[7];
    const float* bo = (const float*)d_in[8];
    float* out = (float*)d_out;

    float *q, *k, *v;
    cudaGetSymbolAddress((void**)&q, g_q);
    cudaGetSymbolAddress((void**)&k, g_k);
    cudaGetSymbolAddress((void**)&v, g_v);
    __nv_bfloat16 *wqh, *wql, *wkh, *wkl, *wvh, *wvl, *woh, *wol;
    cudaGetSymbolAddress((void**)&wqh, g_wqh);
    cudaGetSymbolAddress((void**)&wql, g_wql);
    cudaGetSymbolAddress((void**)&wkh, g_wkh);
    cudaGetSymbolAddress((void**)&wkl, g_wkl);
    cudaGetSymbolAddress((void**)&wvh, g_wvh);
    cudaGetSymbolAddress((void**)&wvl, g_wvl);
    cudaGetSymbolAddress((void**)&woh, g_woh);
    cudaGetSymbolAddress((void**)&wol, g_wol);
    __nv_bfloat16 *xh, *xl, *ath, *atl;
    cudaGetSymbolAddress((void**)&xh,  g_xh);
    cudaGetSymbolAddress((void**)&xl,  g_xl);
    cudaGetSymbolAddress((void**)&ath, g_ath);
    cudaGetSymbolAddress((void**)&atl, g_atl);
    __nv_bfloat16 *kbh, *kbl, *vbh, *vbl;
    cudaGetSymbolAddress((void**)&kbh, g_kbh);
    cudaGetSymbolAddress((void**)&kbl, g_kbl);
    cudaGetSymbolAddress((void**)&vbh, g_vbh);
    cudaGetSymbolAddress((void**)&vbl, g_vbl);

    cudaFuncSetAttribute(attn_bf16_kernel,
                         cudaFuncAttributeMaxDynamicSharedMemorySize, ATT_SMEM_BYTES);
    cudaFuncSetAttribute(gemm_bf3_cp_kernel,
                         cudaFuncAttributeMaxDynamicSharedMemorySize, GEMM_SMEM_BYTES);

    dim3 cblk(32, 8);
    dim3 blk(256);

    // weight pre-pass
    convert_w_kernel<<<dim3(DM / 32, DM / 32),  cblk>>>(Wq, wqh, wql, DM, DM);
    convert_w_kernel<<<dim3(NKV / 32, DM / 32), cblk>>>(Wk, wkh, wkl, DM, NKV);
    convert_w_kernel<<<dim3(NKV / 32, DM / 32), cblk>>>(Wv, wvh, wvl, DM, NKV);
    convert_w_kernel<<<dim3(DM / 32, DM / 32),  cblk>>>(Wo, woh, wol, DM, DM);

    // x pre-split
    convert_a_kernel<<<(MROWS * DM / 4) / 256, blk>>>(x, xh, xl);

    // projections (3xBF16, cp.async double-buffered)
    gemm_bf3_cp_kernel<<<dim3(DM / 128, MROWS / 128), blk, GEMM_SMEM_BYTES>>>(
        xh, xl, wqh, wql, bq, q, MROWS, DM, DM);
    gemm_bf3_cp_kernel<<<dim3(NKV / 128, MROWS / 128), blk, GEMM_SMEM_BYTES>>>(
        xh, xl, wkh, wkl, bk, k, MROWS, NKV, DM);
    gemm_bf3_cp_kernel<<<dim3(NKV / 128, MROWS / 128), blk, GEMM_SMEM_BYTES>>>(
        xh, xl, wvh, wvl, bv, v, MROWS, NKV, DM);

    // K/V pre-split for attention
    convert_k_kernel<<<(MROWS * NKV / 4) / 256, blk>>>(k, kbh, kbl);
    convert_vT_kernel<<<dim3(TT / 32, HD / 32, BB * KVH), cblk>>>(v, vbh, vbl);

    // causal GQA attention (writes bf16 hi/lo output directly)
    attn_bf16_kernel<<<dim3(TT / 64, QH, BB), blk, ATT_SMEM_BYTES>>>(
        q, kbh, kbl, vbh, vbl, ath, atl);

    // output projection
    gemm_bf3_cp_kernel<<<dim3(DM / 128, MROWS / 128), blk, GEMM_SMEM_BYTES>>>(
        ath, atl, woh, wol, bo, out, MROWS, DM, DM);
}

// round 16
// speedup vs baseline: 3.6684x; 1.0479x over previous
#include <cuda_runtime.h>
#include <cuda_bf16.h>
#include <math_constants.h>
#include <stdint.h>

// ---------------- problem constants ----------------
#define DM    2048              // d_model
#define QH    32                // q heads
#define KVH   8                 // kv heads
#define HD    64                // head dim
#define BB    2                 // batch
#define TT    2048              // seq len
#define MROWS (BB * TT)         // 4096 rows for all GEMMs
#define NKV   (KVH * HD)        // 512

// ---------------- scratch (device globals; no allocation allowed) ----------------
__device__ __align__(16) float g_q[(size_t)MROWS * DM];
__device__ __align__(16) float g_k[(size_t)MROWS * NKV];
__device__ __align__(16) float g_v[(size_t)MROWS * NKV];
// transposed bf16 hi/lo weights: [N][K] layout, K = DM
__device__ __align__(16) __nv_bfloat16 g_wqh[(size_t)DM * DM],  g_wql[(size_t)DM * DM];
__device__ __align__(16) __nv_bfloat16 g_wkh[(size_t)NKV * DM], g_wkl[(size_t)NKV * DM];
__device__ __align__(16) __nv_bfloat16 g_wvh[(size_t)NKV * DM], g_wvl[(size_t)NKV * DM];
__device__ __align__(16) __nv_bfloat16 g_woh[(size_t)DM * DM],  g_wol[(size_t)DM * DM];
// pre-split GEMM A operands: [M][K] bf16 hi/lo
__device__ __align__(16) __nv_bfloat16 g_xh[(size_t)MROWS * DM],  g_xl[(size_t)MROWS * DM];
__device__ __align__(16) __nv_bfloat16 g_ath[(size_t)MROWS * DM], g_atl[(size_t)MROWS * DM];
// pre-split K/V for attention: K as [b,kvh][t][d] bf16 hi/lo; V TRANSPOSED [b,kvh][d][t]
__device__ __align__(16) __nv_bfloat16 g_kbh[(size_t)BB * KVH * TT * HD], g_kbl[(size_t)BB * KVH * TT * HD];
__device__ __align__(16) __nv_bfloat16 g_vbh[(size_t)BB * KVH * TT * HD], g_vbl[(size_t)BB * KVH * TT * HD];

#define MMA_BF16(cc, a0, a1, a2, a3, b0, b1)                               \
    asm volatile(                                                          \
        "mma.sync.aligned.m16n8k16.row.col.f32.bf16.bf16.f32 "             \
        "{%0,%1,%2,%3}, {%4,%5,%6,%7}, {%8,%9}, {%0,%1,%2,%3};"            \
        : "+f"(cc[0]), "+f"(cc[1]), "+f"(cc[2]), "+f"(cc[3])               \
        : "r"(a0), "r"(a1), "r"(a2), "r"(a3), "r"(b0), "r"(b1))

__device__ __forceinline__ uint32_t pack_bf2(__nv_bfloat16 a, __nv_bfloat16 b) {
    return (uint32_t)__bfloat16_as_ushort(a) | ((uint32_t)__bfloat16_as_ushort(b) << 16);
}

__device__ __forceinline__ uint32_t smem_u32(const void* p) {
    uint32_t a;
    asm("{ .reg .u64 t; cvta.to.shared.u64 t, %1; cvt.u32.u64 %0, t; }" : "=r"(a) : "l"(p));
    return a;
}

__device__ __forceinline__ void cp16(uint32_t saddr, const void* g) {
    asm volatile("cp.async.ca.shared.global [%0], [%1], 16;" :: "r"(saddr), "l"(g));
}
#define CP_COMMIT() asm volatile("cp.async.commit_group;" ::: "memory")
#define CP_WAIT0()  asm volatile("cp.async.wait_group 0;" ::: "memory")

// ============================================================================
// Pre-pass: W [K][N] fp32  ->  Wh/Wl [N][K] bf16 (hi/lo), tiled transpose.
// ============================================================================
__global__ void __launch_bounds__(256) convert_w_kernel(
    const float* __restrict__ W,
    __nv_bfloat16* __restrict__ Wh, __nv_bfloat16* __restrict__ Wl,
    int K, int N)
{
    __shared__ float ts[32][33];
    const int n0 = blockIdx.x * 32, k0 = blockIdx.y * 32;
    const int tx = threadIdx.x, ty = threadIdx.y;
    #pragma unroll
    for (int i = 0; i < 4; i++)
        ts[ty + i * 8][tx] = W[(size_t)(k0 + ty + i * 8) * N + n0 + tx];
    __syncthreads();
    #pragma unroll
    for (int i = 0; i < 4; i++) {
        float v = ts[tx][ty + i * 8];
        __nv_bfloat16 h = __float2bfloat16(v);
        __nv_bfloat16 l = __float2bfloat16(v - __bfloat162float(h));
        size_t o = (size_t)(n0 + ty + i * 8) * K + k0 + tx;
        Wh[o] = h;
        Wl[o] = l;
    }
}

// ============================================================================
// Pre-pass: A [M*K] fp32 -> bf16 hi/lo [M*K] (elementwise, no transpose).
// ============================================================================
__global__ void __launch_bounds__(256) convert_a_kernel(
    const float* __restrict__ src,
    __nv_bfloat16* __restrict__ dh, __nv_bfloat16* __restrict__ dl)
{
    size_t e0 = ((size_t)blockIdx.x * 256 + threadIdx.x) * 4;
    float4 v = *(const float4*)(src + e0);
    float vv[4] = {v.x, v.y, v.z, v.w};
    __nv_bfloat16 h[4], l[4];
    #pragma unroll
    for (int j = 0; j < 4; j++) {
        h[j] = __float2bfloat16(vv[j]);
        l[j] = __float2bfloat16(vv[j] - __bfloat162float(h[j]));
    }
    *(uint2*)(dh + e0) = make_uint2(pack_bf2(h[0], h[1]), pack_bf2(h[2], h[3]));
    *(uint2*)(dl + e0) = make_uint2(pack_bf2(l[0], l[1]), pack_bf2(l[2], l[3]));
}

// ============================================================================
// Pre-pass: K fp32 [b*TT+t][NKV] -> [b,kvh][t][d] bf16 hi/lo (reshape only).
// ============================================================================
__global__ void __launch_bounds__(256) convert_k_kernel(
    const float* __restrict__ src,
    __nv_bfloat16* __restrict__ dh, __nv_bfloat16* __restrict__ dl)
{
    size_t e0 = ((size_t)blockIdx.x * 256 + threadIdx.x) * 4;
    int row = (int)(e0 >> 9);
    int c   = (int)(e0 & 511);
    int kvh = c >> 6, d = c & 63;
    int b   = row >> 11, t = row & 2047;
    float4 v = *(const float4*)(src + e0);
    float vv[4] = {v.x, v.y, v.z, v.w};
    __nv_bfloat16 h[4], l[4];
    #pragma unroll
    for (int j = 0; j < 4; j++) {
        h[j] = __float2bfloat16(vv[j]);
        l[j] = __float2bfloat16(vv[j] - __bfloat162float(h[j]));
    }
    size_t o = ((size_t)(b * KVH + kvh) * TT + t) * HD + d;
    *(uint2*)(dh + o) = make_uint2(pack_bf2(h[0], h[1]), pack_bf2(h[2], h[3]));
    *(uint2*)(dl + o) = make_uint2(pack_bf2(l[0], l[1]), pack_bf2(l[2], l[3]));
}

// ============================================================================
// Pre-pass: V fp32 [b*TT+t][NKV] -> TRANSPOSED [b,kvh][d][t] bf16 hi/lo.
// ============================================================================
__global__ void __launch_bounds__(256) convert_vT_kernel(
    const float* __restrict__ src,
    __nv_bfloat16* __restrict__ dh, __nv_bfloat16* __restrict__ dl)
{
    __shared__ float ts[32][33];
    const int bz  = blockIdx.z;
    const int b   = bz >> 3, kvh = bz & 7;
    const int t0  = blockIdx.x * 32, d0 = blockIdx.y * 32;
    const int tx  = threadIdx.x, ty = threadIdx.y;
    #pragma unroll
    for (int i = 0; i < 4; i++)
        ts[ty + i * 8][tx] = src[((size_t)b * TT + t0 + ty + i * 8) * NKV + kvh * HD + d0 + tx];
    __syncthreads();
    #pragma unroll
    for (int i = 0; i < 4; i++) {
        float v = ts[tx][ty + i * 8];
        __nv_bfloat16 h = __float2bfloat16(v);
        __nv_bfloat16 l = __float2bfloat16(v - __bfloat162float(h));
        size_t o = ((size_t)(b * KVH + kvh) * HD + d0 + ty + i * 8) * TT + t0 + tx;
        dh[o] = h;
        dl[o] = l;
    }
}

// ============================================================================
// 3xBF16 GEMM (UNCHANGED from R12/R14, validated): cp.async double-buffered.
// ============================================================================
#define GPITCH 40
#define GARR   (128 * GPITCH * 2)
#define GSTAGE (4 * GARR)
#define GEMM_SMEM_BYTES (2 * GSTAGE)

__global__ void __launch_bounds__(256) gemm_bf3_cp_kernel(
    const __nv_bfloat16* __restrict__ Ah_g, const __nv_bfloat16* __restrict__ Al_g,
    const __nv_bfloat16* __restrict__ Bh_g, const __nv_bfloat16* __restrict__ Bl_g,
    const float* __restrict__ bias, float* __restrict__ C,
    int M, int N, int K)
{
    extern __shared__ char smg[];
    const uint32_t sb = smem_u32(smg);

    const int tid  = threadIdx.x;
    const int lane = tid & 31;
    const int w    = tid >> 5;
    const int g    = lane >> 2;
    const int t    = lane & 3;
    const int mw   = (w >> 1) * 32;
    const int nw   = (w & 1) * 64;
    const int bRow0 = blockIdx.y * 128;
    const int bCol0 = blockIdx.x * 128;

    const int r0s   = tid >> 2;
    const int seg0  = (tid & 3) * 8;
    const int r1s   = (tid + 256) >> 2;
    const int seg1  = seg0;

    float acc[2][8][4];
    #pragma unroll
    for (int i = 0; i < 2; i++)
        #pragma unroll
        for (int j = 0; j < 8; j++)
            #pragma unroll
            for (int q = 0; q < 4; q++) acc[i][j][q] = 0.f;

    const int niter = K >> 5;

    {
        const uint32_t s0 = sb;
        uint32_t so0 = s0 + (uint32_t)(r0s * 80 + seg0 * 2);
        uint32_t so1 = s0 + (uint32_t)(r1s * 80 + seg1 * 2);
        size_t ga0 = (size_t)(bRow0 + r0s) * K + seg0;
        size_t ga1 = (size_t)(bRow0 + r1s) * K + seg1;
        size_t gb0 = (size_t)(bCol0 + r0s) * K + seg0;
        size_t gb1 = (size_t)(bCol0 + r1s) * K + seg1;
        cp16(so0 + 0 * GARR, Ah_g + ga0);  cp16(so1 + 0 * GARR, Ah_g + ga1);
        cp16(so0 + 1 * GARR, Al_g + ga0);  cp16(so1 + 1 * GARR, Al_g + ga1);
        cp16(so0 + 2 * GARR, Bh_g + gb0);  cp16(so1 + 2 * GARR, Bh_g + gb1);
        cp16(so0 + 3 * GARR, Bl_g + gb0);  cp16(so1 + 3 * GARR, Bl_g + gb1);
        CP_COMMIT();
    }

    for (int it = 0; it < niter; it++) {
        const int st = it & 1;
        CP_WAIT0();
        __syncthreads();

        if (it + 1 < niter) {
            const uint32_t s0 = sb + (uint32_t)((st ^ 1) * GSTAGE);
            const int kof = (it + 1) * 32;
            uint32_t so0 = s0 + (uint32_t)(r0s * 80 + seg0 * 2);
            uint32_t so1 = s0 + (uint32_t)(r1s * 80 + seg1 * 2);
            size_t ga0 = (size_t)(bRow0 + r0s) * K + kof + seg0;
            size_t ga1 = (size_t)(bRow0 + r1s) * K + kof + seg1;
            size_t gb0 = (size_t)(bCol0 + r0s) * K + kof + seg0;
            size_t gb1 = (size_t)(bCol0 + r1s) * K + kof + seg1;
            cp16(so0 + 0 * GARR, Ah_g + ga0);  cp16(so1 + 0 * GARR, Ah_g + ga1);
            cp16(so0 + 1 * GARR, Al_g + ga0);  cp16(so1 + 1 * GARR, Al_g + ga1);
            cp16(so0 + 2 * GARR, Bh_g + gb0);  cp16(so1 + 2 * GARR, Bh_g + gb1);
            cp16(so0 + 3 * GARR, Bl_g + gb0);  cp16(so1 + 3 * GARR, Bl_g + gb1);
            CP_COMMIT();
        }

        const __nv_bfloat16* Ah = (const __nv_bfloat16*)(smg + st * GSTAGE + 0 * GARR);
        const __nv_bfloat16* Al = (const __nv_bfloat16*)(smg + st * GSTAGE + 1 * GARR);
        const __nv_bfloat16* Bh = (const __nv_bfloat16*)(smg + st * GSTAGE + 2 * GARR);
        const __nv_bfloat16* Bl = (const __nv_bfloat16*)(smg + st * GSTAGE + 3 * GARR);

        #pragma unroll
        for (int ks = 0; ks < 2; ks++) {
            const int kc = ks * 16 + 2 * t;
            uint32_t ah[2][4], al_[2][4];
            #pragma unroll
            for (int mt = 0; mt < 2; mt++) {
                int r = mw + mt * 16 + g;
                ah[mt][0]  = *(const uint32_t*)&Ah[r * GPITCH + kc];
                ah[mt][1]  = *(const uint32_t*)&Ah[(r + 8) * GPITCH + kc];
                ah[mt][2]  = *(const uint32_t*)&Ah[r * GPITCH + kc + 8];
                ah[mt][3]  = *(const uint32_t*)&Ah[(r + 8) * GPITCH + kc + 8];
                al_[mt][0] = *(const uint32_t*)&Al[r * GPITCH + kc];
                al_[mt][1] = *(const uint32_t*)&Al[(r + 8) * GPITCH + kc];
                al_[mt][2] = *(const uint32_t*)&Al[r * GPITCH + kc + 8];
                al_[mt][3] = *(const uint32_t*)&Al[(r + 8) * GPITCH + kc + 8];
            }
            #pragma unroll
            for (int nt = 0; nt < 8; nt++) {
                int n = nw + nt * 8 + g;
                uint32_t bh0 = *(const uint32_t*)&Bh[n * GPITCH + kc];
                uint32_t bh1 = *(const uint32_t*)&Bh[n * GPITCH + kc + 8];
                uint32_t bl0 = *(const uint32_t*)&Bl[n * GPITCH + kc];
                uint32_t bl1 = *(const uint32_t*)&Bl[n * GPITCH + kc + 8];
                #pragma unroll
                for (int mt = 0; mt < 2; mt++) {
                    MMA_BF16(acc[mt][nt], ah[mt][0], ah[mt][1], ah[mt][2], ah[mt][3], bh0, bh1);
                    MMA_BF16(acc[mt][nt], ah[mt][0], ah[mt][1], ah[mt][2], ah[mt][3], bl0, bl1);
                    MMA_BF16(acc[mt][nt], al_[mt][0], al_[mt][1], al_[mt][2], al_[mt][3], bh0, bh1);
                }
            }
        }
    }

    #pragma unroll
    for (int mt = 0; mt < 2; mt++) {
        #pragma unroll
        for (int nt = 0; nt < 8; nt++) {
            int row = bRow0 + mw + mt * 16 + g;
            int col = bCol0 + nw + nt * 8 + 2 * t;
            float b0v = bias[col], b1v = bias[col + 1];
            float2 o0 = {acc[mt][nt][0] + b0v, acc[mt][nt][1] + b1v};
            float2 o1 = {acc[mt][nt][2] + b0v, acc[mt][nt][3] + b1v};
            *(float2*)(C + (size_t)row * N + col)       = o0;
            *(float2*)(C + (size_t)(row + 8) * N + col) = o1;
        }
    }
}

// ============================================================================
// Flash attention v4 (bisect step 2 on R14 base): register-resident softmax.
// Per-thread chunk max/sum via __shfl_xor over the 4-lane row group; cross-
// warp exchange through s_mx/s_lx; replicated (m,l) state; 3 syncs/tile;
// sSr eliminated. Epilogue: direct bf16 hi/lo output (validated in R14).
// ============================================================================
#define KP   72
#define BKH  0
#define BKL  (BKH + 64 * KP * 2)
#define BVH  (BKL + 64 * KP * 2)
#define BVL  (BVH + 64 * KP * 2)
#define BPH  (BVL + 64 * KP * 2)
#define BPL  (BPH + 64 * KP * 2)
#define BMX  (BPL + 64 * KP * 2)
#define BLX  (BMX + 64 * 2 * 4)
#define ATT_SMEM_BYTES (BLX + 64 * 2 * 4)

__global__ void __launch_bounds__(256, 2) attn_bf16_kernel(
    const float* __restrict__ Q,
    const __nv_bfloat16* __restrict__ Kbh, const __nv_bfloat16* __restrict__ Kbl,
    const __nv_bfloat16* __restrict__ Vbh, const __nv_bfloat16* __restrict__ Vbl,
    __nv_bfloat16* __restrict__ Oh, __nv_bfloat16* __restrict__ Ol)
{
    extern __shared__ char smc[];
    __nv_bfloat16* sKh = (__nv_bfloat16*)(smc + BKH);
    __nv_bfloat16* sKl = (__nv_bfloat16*)(smc + BKL);
    __nv_bfloat16* sVh = (__nv_bfloat16*)(smc + BVH);
    __nv_bfloat16* sVl = (__nv_bfloat16*)(smc + BVL);
    __nv_bfloat16* sPh = (__nv_bfloat16*)(smc + BPH);
    __nv_bfloat16* sPl = (__nv_bfloat16*)(smc + BPL);
    float* s_mx = (float*)(smc + BMX);    // [row][nw]
    float* s_lx = (float*)(smc + BLX);    // [row][nw]

    const int qi  = blockIdx.x;
    const int h   = blockIdx.y;
    const int b   = blockIdx.z;
    const int kvh = h >> 2;               // repeat_interleave: h // GROUP
    const int tid = threadIdx.x;
    const int q0  = qi * 64;

    const int lane = tid & 31;
    const int w    = tid >> 5;
    const int g    = lane >> 2;
    const int t    = lane & 3;
    const int mw   = (w >> 1) * 16;
    const int nw   = w & 1;
    const int r0   = mw + g;
    const int r1   = r0 + 8;

    const __nv_bfloat16* kbh = Kbh + (size_t)(b * KVH + kvh) * TT * HD;
    const __nv_bfloat16* kbl = Kbl + (size_t)(b * KVH + kvh) * TT * HD;
    const __nv_bfloat16* vbh = Vbh + (size_t)(b * KVH + kvh) * HD * TT;
    const __nv_bfloat16* vbl = Vbl + (size_t)(b * KVH + kvh) * HD * TT;

    // ---- Q fragments (unchanged) ----
    uint32_t qh[4][4], ql[4][4];
    {
        const float* q0p = Q + (size_t)(b * TT + q0 + r0) * DM + h * HD;
        const float* q1p = Q + (size_t)(b * TT + q0 + r1) * DM + h * HD;
        #pragma unroll
        for (int ks = 0; ks < 4; ks++) {
            const int kt = ks * 16;
            float v00 = q0p[kt + 2 * t],     v01 = q0p[kt + 2 * t + 1];
            float v10 = q1p[kt + 2 * t],     v11 = q1p[kt + 2 * t + 1];
            float v20 = q0p[kt + 2 * t + 8], v21 = q0p[kt + 2 * t + 9];
            float v30 = q1p[kt + 2 * t + 8], v31 = q1p[kt + 2 * t + 9];
            __nv_bfloat16 h00 = __float2bfloat16(v00), h01 = __float2bfloat16(v01);
            __nv_bfloat16 h10 = __float2bfloat16(v10), h11 = __float2bfloat16(v11);
            __nv_bfloat16 h20 = __float2bfloat16(v20), h21 = __float2bfloat16(v21);
            __nv_bfloat16 h30 = __float2bfloat16(v30), h31 = __float2bfloat16(v31);
            qh[ks][0] = pack_bf2(h00, h01);
            qh[ks][1] = pack_bf2(h10, h11);
            qh[ks][2] = pack_bf2(h20, h21);
            qh[ks][3] = pack_bf2(h30, h31);
            ql[ks][0] = pack_bf2(__float2bfloat16(v00 - __bfloat162float(h00)),
                                 __float2bfloat16(v01 - __bfloat162float(h01)));
            ql[ks][1] = pack_bf2(__float2bfloat16(v10 - __bfloat162float(h10)),
                                 __float2bfloat16(v11 - __bfloat162float(h11)));
            ql[ks][2] = pack_bf2(__float2bfloat16(v20 - __bfloat162float(h20)),
                                 __float2bfloat16(v21 - __bfloat162float(h21)));
            ql[ks][3] = pack_bf2(__float2bfloat16(v30 - __bfloat162float(h30)),
                                 __float2bfloat16(v31 - __bfloat162float(h31)));
        }
    }

    // replicated per-thread softmax state (identical across the 8 threads/row)
    float row_m0 = -CUDART_INF_F, row_m1 = -CUDART_INF_F;
    float row_l0 = 0.f, row_l1 = 0.f;

    float o[4][4];
    #pragma unroll
    for (int i = 0; i < 4; i++)
        #pragma unroll
        for (int j = 0; j < 4; j++) o[i][j] = 0.f;

    const int qg0 = q0 + r0, qg1 = q0 + r1;
    const int nkv = qi + 1;
    for (int it = 0; it < nkv; it++) {
        const int k0 = it * 64;
        if (it) __syncthreads();          // prev PV reads done -> safe to restage

        // ---- stage K/V tiles ----
        #pragma unroll
        for (int i = tid; i < 512; i += 256) {
            const int r = i >> 3, seg = (i & 7) * 8;
            const size_t gk = (size_t)(k0 + r) * HD + seg;
            *(uint4*)&sKh[r * KP + seg] = *(const uint4*)(kbh + gk);
            *(uint4*)&sKl[r * KP + seg] = *(const uint4*)(kbl + gk);
            const size_t gv = (size_t)r * TT + k0 + seg;
            *(uint4*)&sVh[r * KP + seg] = *(const uint4*)(vbh + gv);
            *(uint4*)&sVl[r * KP + seg] = *(const uint4*)(vbl + gv);
        }
        __syncthreads();                  // (1) tiles ready

        // ---- S = Q K^T (3xBF16), mask+scale in registers ----
        float sc[4][4];
        #pragma unroll
        for (int tn = 0; tn < 4; tn++)
            #pragma unroll
            for (int j = 0; j < 4; j++) sc[tn][j] = 0.f;

        #pragma unroll
        for (int ks = 0; ks < 4; ks++) {
            const int kt = ks * 16;
            #pragma unroll
            for (int tn = 0; tn < 4; tn++) {
                const int n = nw * 32 + tn * 8 + g;
                uint32_t bh0 = *(const uint32_t*)&sKh[n * KP + kt + 2 * t];
                uint32_t bh1 = *(const uint32_t*)&sKh[n * KP + kt + 2 * t + 8];
                uint32_t bl0 = *(const uint32_t*)&sKl[n * KP + kt + 2 * t];
                uint32_t bl1 = *(const uint32_t*)&sKl[n * KP + kt + 2 * t + 8];
                MMA_BF16(sc[tn], qh[ks][0], qh[ks][1], qh[ks][2], qh[ks][3], bh0, bh1);
                MMA_BF16(sc[tn], qh[ks][0], qh[ks][1], qh[ks][2], qh[ks][3], bl0, bl1);
                MMA_BF16(sc[tn], ql[ks][0], ql[ks][1], ql[ks][2], ql[ks][3], bh0, bh1);
            }
        }
        #pragma unroll
        for (int tn = 0; tn < 4; tn++) {
            const int col = nw * 32 + tn * 8 + 2 * t;
            const int kg0 = k0 + col, kg1 = kg0 + 1;
            sc[tn][0] = (kg0 <= qg0) ? sc[tn][0] * 0.125f : -CUDART_INF_F;
            sc[tn][1] = (kg1 <= qg0) ? sc[tn][1] * 0.125f : -CUDART_INF_F;
            sc[tn][2] = (kg0 <= qg1) ? sc[tn][2] * 0.125f : -CUDART_INF_F;
            sc[tn][3] = (kg1 <= qg1) ? sc[tn][3] * 0.125f : -CUDART_INF_F;
        }

        // ---- chunk max (8 cols/row/thread -> 32-col chunk via shfl over t) ----
        float m0 = sc[0][0], m1 = sc[0][2];
        #pragma unroll
        for (int tn = 0; tn < 4; tn++) {
            m0 = fmaxf(m0, fmaxf(sc[tn][0], sc[tn][1]));
            m1 = fmaxf(m1, fmaxf(sc[tn][2], sc[tn][3]));
        }
        m0 = fmaxf(m0, __shfl_xor_sync(0xffffffffu, m0, 1));
        m0 = fmaxf(m0, __shfl_xor_sync(0xffffffffu, m0, 2));
        m1 = fmaxf(m1, __shfl_xor_sync(0xffffffffu, m1, 1));
        m1 = fmaxf(m1, __shfl_xor_sync(0xffffffffu, m1, 2));
        if (t == 0) {
            s_mx[r0 * 2 + nw] = m0;
            s_mx[r1 * 2 + nw] = m1;
        }
        __syncthreads();                  // (2) chunk maxes visible

        const float M0 = fmaxf(row_m0, fmaxf(s_mx[r0 * 2], s_mx[r0 * 2 + 1]));
        const float M1 = fmaxf(row_m1, fmaxf(s_mx[r1 * 2], s_mx[r1 * 2 + 1]));
        const float a0 = __expf(row_m0 - M0);
        const float a1 = __expf(row_m1 - M1);
        row_m0 = M0;
        row_m1 = M1;

        // ---- exp + bf16 split in regs; packed P stores + chunk sums ----
        float ls0 = 0.f, ls1 = 0.f;
        #pragma unroll
        for (int tn = 0; tn < 4; tn++) {
            const int col = nw * 32 + tn * 8 + 2 * t;
            float e00 = __expf(sc[tn][0] - M0);
            float e01 = __expf(sc[tn][1] - M0);
            float e10 = __expf(sc[tn][2] - M1);
            float e11 = __expf(sc[tn][3] - M1);
            ls0 += e00 + e01;
            ls1 += e10 + e11;
            __nv_bfloat16 h00 = __float2bfloat16(e00), h01 = __float2bfloat16(e01);
            __nv_bfloat16 h10 = __float2bfloat16(e10), h11 = __float2bfloat16(e11);
            *(uint32_t*)&sPh[r0 * KP + col] = pack_bf2(h00, h01);
            *(uint32_t*)&sPh[r1 * KP + col] = pack_bf2(h10, h11);
            *(uint32_t*)&sPl[r0 * KP + col] =
                pack_bf2(__float2bfloat16(e00 - __bfloat162float(h00)),
                         __float2bfloat16(e01 - __bfloat162float(h01)));
            *(uint32_t*)&sPl[r1 * KP + col] =
                pack_bf2(__float2bfloat16(e10 - __bfloat162float(h10)),
                         __float2bfloat16(e11 - __bfloat162float(h11)));
        }
        ls0 += __shfl_xor_sync(0xffffffffu, ls0, 1);
        ls0 += __shfl_xor_sync(0xffffffffu, ls0, 2);
        ls1 += __shfl_xor_sync(0xffffffffu, ls1, 1);
        ls1 += __shfl_xor_sync(0xffffffffu, ls1, 2);
        if (t == 0) {
            s_lx[r0 * 2 + nw] = ls0;
            s_lx[r1 * 2 + nw] = ls1;
        }
        __syncthreads();                  // (3) P + chunk sums ready

        row_l0 = row_l0 * a0 + s_lx[r0 * 2] + s_lx[r0 * 2 + 1];
        row_l1 = row_l1 * a1 + s_lx[r1 * 2] + s_lx[r1 * 2 + 1];

        // ---- O rescale + O += P @ V (3xBF16) ----
        #pragma unroll
        for (int tn = 0; tn < 4; tn++) {
            o[tn][0] *= a0; o[tn][1] *= a0;
            o[tn][2] *= a1; o[tn][3] *= a1;
        }
        #pragma unroll
        for (int ks = 0; ks < 4; ks++) {
            const int kt = ks * 16;
            uint32_t p0h = *(const uint32_t*)&sPh[r0 * KP + kt + 2 * t];
            uint32_t p1h = *(const uint32_t*)&sPh[r1 * KP + kt + 2 * t];
            uint32_t p2h = *(const uint32_t*)&sPh[r0 * KP + kt + 2 * t + 8];
            uint32_t p3h = *(const uint32_t*)&sPh[r1 * KP + kt + 2 * t + 8];
            uint32_t p0l = *(const uint32_t*)&sPl[r0 * KP + kt + 2 * t];
            uint32_t p1l = *(const uint32_t*)&sPl[r1 * KP + kt + 2 * t];
            uint32_t p2l = *(const uint32_t*)&sPl[r0 * KP + kt + 2 * t + 8];
            uint32_t p3l = *(const uint32_t*)&sPl[r1 * KP + kt + 2 * t + 8];
            #pragma unroll
            for (int tn = 0; tn < 4; tn++) {
                const int n = nw * 32 + tn * 8 + g;
                uint32_t vh0 = *(const uint32_t*)&sVh[n * KP + kt + 2 * t];
                uint32_t vh1 = *(const uint32_t*)&sVh[n * KP + kt + 2 * t + 8];
                uint32_t vl0 = *(const uint32_t*)&sVl[n * KP + kt + 2 * t];
                uint32_t vl1 = *(const uint32_t*)&sVl[n * KP + kt + 2 * t + 8];
                MMA_BF16(o[tn], p0h, p1h, p2h, p3h, vh0, vh1);
                MMA_BF16(o[tn], p0h, p1h, p2h, p3h, vl0, vl1);
                MMA_BF16(o[tn], p0l, p1l, p2l, p3l, vh0, vh1);
            }
        }
    }

    // ---- normalize + write bf16 hi/lo output [B,T,QH*HD] (R14-validated) ----
    {
        const float inv0 = 1.0f / row_l0;
        const float inv1 = 1.0f / row_l1;
        const size_t row0 = (size_t)(b * TT + q0 + r0) * DM + h * HD;
        const size_t row1 = (size_t)(b * TT + q0 + r1) * DM + h * HD;
        #pragma unroll
        for (int tn = 0; tn < 4; tn++) {
            const int c = nw * 32 + tn * 8 + 2 * t;
            float v00 = o[tn][0] * inv0, v01 = o[tn][1] * inv0;
            float v10 = o[tn][2] * inv1, v11 = o[tn][3] * inv1;
            __nv_bfloat16 h00 = __float2bfloat16(v00), h01 = __float2bfloat16(v01);
            __nv_bfloat16 h10 = __float2bfloat16(v10), h11 = __float2bfloat16(v11);
            *(uint32_t*)(Oh + row0 + c) = pack_bf2(h00, h01);
            *(uint32_t*)(Oh + row1 + c) = pack_bf2(h10, h11);
            *(uint32_t*)(Ol + row0 + c) =
                pack_bf2(__float2bfloat16(v00 - __bfloat162float(h00)),
                         __float2bfloat16(v01 - __bfloat162float(h01)));
            *(uint32_t*)(Ol + row1 + c) =
                pack_bf2(__float2bfloat16(v10 - __bfloat162float(h10)),
                         __float2bfloat16(v11 - __bfloat162float(h11)));
        }
    }
}

// ============================================================================
// kernel_launch: graph-capturable launches, no allocations, no syncs.
// ============================================================================
extern "C" void kernel_launch(void* const* d_in, const int* in_sizes, int n_in,
                              void* d_out, int out_size)
{
    const float* x  = (const float*)d_in[0];
    const float* Wq = (const float*)d_in[1];
    const float* bq = (const float*)d_in[2];
    const float* Wk = (const float*)d_in[3];
    const float* bk = (const float*)d_in[4];
    const float* Wv = (const float*)d_in[5];
    const float* bv = (const float*)d_in[6];
    const float* Wo = (const float*)d_in[7];
    const float* bo = (const float*)d_in[8];
    float* out = (float*)d_out;

    float *q, *k, *v;
    cudaGetSymbolAddress((void**)&q, g_q);
    cudaGetSymbolAddress((void**)&k, g_k);
    cudaGetSymbolAddress((void**)&v, g_v);
    __nv_bfloat16 *wqh, *wql, *wkh, *wkl, *wvh, *wvl, *woh, *wol;
    cudaGetSymbolAddress((void**)&wqh, g_wqh);
    cudaGetSymbolAddress((void**)&wql, g_wql);
    cudaGetSymbolAddress((void**)&wkh, g_wkh);
    cudaGetSymbolAddress((void**)&wkl, g_wkl);
    cudaGetSymbolAddress((void**)&wvh, g_wvh);
    cudaGetSymbolAddress((void**)&wvl, g_wvl);
    cudaGetSymbolAddress((void**)&woh, g_woh);
    cudaGetSymbolAddress((void**)&wol, g_wol);
    __nv_bfloat16 *xh, *xl, *ath, *atl;
    cudaGetSymbolAddress((void**)&xh,  g_xh);
    cudaGetSymbolAddress((void**)&xl,  g_xl);
    cudaGetSymbolAddress((void**)&ath, g_ath);
    cudaGetSymbolAddress((void**)&atl, g_atl);
    __nv_bfloat16 *kbh, *kbl, *vbh, *vbl;
    cudaGetSymbolAddress((void**)&kbh, g_kbh);
    cudaGetSymbolAddress((void**)&kbl, g_kbl);
    cudaGetSymbolAddress((void**)&vbh, g_vbh);
    cudaGetSymbolAddress((void**)&vbl, g_vbl);

    cudaFuncSetAttribute(attn_bf16_kernel,
                         cudaFuncAttributeMaxDynamicSharedMemorySize, ATT_SMEM_BYTES);
    cudaFuncSetAttribute(gemm_bf3_cp_kernel,
                         cudaFuncAttributeMaxDynamicSharedMemorySize, GEMM_SMEM_BYTES);

    dim3 cblk(32, 8);
    dim3 blk(256);

    // weight pre-pass
    convert_w_kernel<<<dim3(DM / 32, DM / 32),  cblk>>>(Wq, wqh, wql, DM, DM);
    convert_w_kernel<<<dim3(NKV / 32, DM / 32), cblk>>>(Wk, wkh, wkl, DM, NKV);
    convert_w_kernel<<<dim3(NKV / 32, DM / 32), cblk>>>(Wv, wvh, wvl, DM, NKV);
    convert_w_kernel<<<dim3(DM / 32, DM / 32),  cblk>>>(Wo, woh, wol, DM, DM);

    // x pre-split
    convert_a_kernel<<<(MROWS * DM / 4) / 256, blk>>>(x, xh, xl);

    // projections (3xBF16, cp.async double-buffered)
    gemm_bf3_cp_kernel<<<dim3(DM / 128, MROWS / 128), blk, GEMM_SMEM_BYTES>>>(
        xh, xl, wqh, wql, bq, q, MROWS, DM, DM);
    gemm_bf3_cp_kernel<<<dim3(NKV / 128, MROWS / 128), blk, GEMM_SMEM_BYTES>>>(
        xh, xl, wkh, wkl, bk, k, MROWS, NKV, DM);
    gemm_bf3_cp_kernel<<<dim3(NKV / 128, MROWS / 128), blk, GEMM_SMEM_BYTES>>>(
        xh, xl, wvh, wvl, bv, v, MROWS, NKV, DM);

    // K/V pre-split for attention
    convert_k_kernel<<<(MROWS * NKV / 4) / 256, blk>>>(k, kbh, kbl);
    convert_vT_kernel<<<dim3(TT / 32, HD / 32, BB * KVH), cblk>>>(v, vbh, vbl);

    // causal GQA attention (register softmax; writes bf16 hi/lo output)
    attn_bf16_kernel<<<dim3(TT / 64, QH, BB), blk, ATT_SMEM_BYTES>>>(
        q, kbh, kbl, vbh, vbl, ath, atl);

    // output projection
    gemm_bf3_cp_kernel<<<dim3(DM / 128, MROWS / 128), blk, GEMM_SMEM_BYTES>>>(
        ath, atl, woh, wol, bo, out, MROWS, DM, DM);
}

// round 17
// speedup vs baseline: 3.7930x; 1.0340x over previous
#include <cuda_runtime.h>
#include <cuda_bf16.h>
#include <math_constants.h>
#include <stdint.h>

// ---------------- problem constants ----------------
#define DM    2048              // d_model
#define QH    32                // q heads
#define KVH   8                 // kv heads
#define HD    64                // head dim
#define BB    2                 // batch
#define TT    2048              // seq len
#define MROWS (BB * TT)         // 4096 rows for all GEMMs
#define NKV   (KVH * HD)        // 512

// ---------------- scratch (device globals; no allocation allowed) ----------------
__device__ __align__(16) float g_q[(size_t)MROWS * DM];
__device__ __align__(16) float g_k[(size_t)MROWS * NKV];
__device__ __align__(16) float g_v[(size_t)MROWS * NKV];
// transposed bf16 hi/lo weights: [N][K] layout, K = DM
__device__ __align__(16) __nv_bfloat16 g_wqh[(size_t)DM * DM],  g_wql[(size_t)DM * DM];
__device__ __align__(16) __nv_bfloat16 g_wkh[(size_t)NKV * DM], g_wkl[(size_t)NKV * DM];
__device__ __align__(16) __nv_bfloat16 g_wvh[(size_t)NKV * DM], g_wvl[(size_t)NKV * DM];
__device__ __align__(16) __nv_bfloat16 g_woh[(size_t)DM * DM],  g_wol[(size_t)DM * DM];
// pre-split GEMM A operands: [M][K] bf16 hi/lo
__device__ __align__(16) __nv_bfloat16 g_xh[(size_t)MROWS * DM],  g_xl[(size_t)MROWS * DM];
__device__ __align__(16) __nv_bfloat16 g_ath[(size_t)MROWS * DM], g_atl[(size_t)MROWS * DM];
// pre-split K/V for attention: K as [b,kvh][t][d] bf16 hi/lo; V TRANSPOSED [b,kvh][d][t]
__device__ __align__(16) __nv_bfloat16 g_kbh[(size_t)BB * KVH * TT * HD], g_kbl[(size_t)BB * KVH * TT * HD];
__device__ __align__(16) __nv_bfloat16 g_vbh[(size_t)BB * KVH * TT * HD], g_vbl[(size_t)BB * KVH * TT * HD];

#define MMA_BF16(cc, a0, a1, a2, a3, b0, b1)                               \
    asm volatile(                                                          \
        "mma.sync.aligned.m16n8k16.row.col.f32.bf16.bf16.f32 "             \
        "{%0,%1,%2,%3}, {%4,%5,%6,%7}, {%8,%9}, {%0,%1,%2,%3};"            \
        : "+f"(cc[0]), "+f"(cc[1]), "+f"(cc[2]), "+f"(cc[3])               \
        : "r"(a0), "r"(a1), "r"(a2), "r"(a3), "r"(b0), "r"(b1))

__device__ __forceinline__ uint32_t pack_bf2(__nv_bfloat16 a, __nv_bfloat16 b) {
    return (uint32_t)__bfloat16_as_ushort(a) | ((uint32_t)__bfloat16_as_ushort(b) << 16);
}

__device__ __forceinline__ uint32_t smem_u32(const void* p) {
    uint32_t a;
    asm("{ .reg .u64 t; cvta.to.shared.u64 t, %1; cvt.u32.u64 %0, t; }" : "=r"(a) : "l"(p));
    return a;
}

__device__ __forceinline__ void cp16(uint32_t saddr, const void* g) {
    asm volatile("cp.async.ca.shared.global [%0], [%1], 16;" :: "r"(saddr), "l"(g));
}
#define CP_COMMIT() asm volatile("cp.async.commit_group;" ::: "memory")
#define CP_WAIT0()  asm volatile("cp.async.wait_group 0;" ::: "memory")

// ============================================================================
// Pre-pass: W [K][N] fp32  ->  Wh/Wl [N][K] bf16 (hi/lo), tiled transpose.
// ============================================================================
__global__ void __launch_bounds__(256) convert_w_kernel(
    const float* __restrict__ W,
    __nv_bfloat16* __restrict__ Wh, __nv_bfloat16* __restrict__ Wl,
    int K, int N)
{
    __shared__ float ts[32][33];
    const int n0 = blockIdx.x * 32, k0 = blockIdx.y * 32;
    const int tx = threadIdx.x, ty = threadIdx.y;
    #pragma unroll
    for (int i = 0; i < 4; i++)
        ts[ty + i * 8][tx] = W[(size_t)(k0 + ty + i * 8) * N + n0 + tx];
    __syncthreads();
    #pragma unroll
    for (int i = 0; i < 4; i++) {
        float v = ts[tx][ty + i * 8];
        __nv_bfloat16 h = __float2bfloat16(v);
        __nv_bfloat16 l = __float2bfloat16(v - __bfloat162float(h));
        size_t o = (size_t)(n0 + ty + i * 8) * K + k0 + tx;
        Wh[o] = h;
        Wl[o] = l;
    }
}

// ============================================================================
// Pre-pass: A [M*K] fp32 -> bf16 hi/lo [M*K] (elementwise, no transpose).
// ============================================================================
__global__ void __launch_bounds__(256) convert_a_kernel(
    const float* __restrict__ src,
    __nv_bfloat16* __restrict__ dh, __nv_bfloat16* __restrict__ dl)
{
    size_t e0 = ((size_t)blockIdx.x * 256 + threadIdx.x) * 4;
    float4 v = *(const float4*)(src + e0);
    float vv[4] = {v.x, v.y, v.z, v.w};
    __nv_bfloat16 h[4], l[4];
    #pragma unroll
    for (int j = 0; j < 4; j++) {
        h[j] = __float2bfloat16(vv[j]);
        l[j] = __float2bfloat16(vv[j] - __bfloat162float(h[j]));
    }
    *(uint2*)(dh + e0) = make_uint2(pack_bf2(h[0], h[1]), pack_bf2(h[2], h[3]));
    *(uint2*)(dl + e0) = make_uint2(pack_bf2(l[0], l[1]), pack_bf2(l[2], l[3]));
}

// ============================================================================
// Pre-pass: K fp32 [b*TT+t][NKV] -> [b,kvh][t][d] bf16 hi/lo (reshape only).
// ============================================================================
__global__ void __launch_bounds__(256) convert_k_kernel(
    const float* __restrict__ src,
    __nv_bfloat16* __restrict__ dh, __nv_bfloat16* __restrict__ dl)
{
    size_t e0 = ((size_t)blockIdx.x * 256 + threadIdx.x) * 4;
    int row = (int)(e0 >> 9);
    int c   = (int)(e0 & 511);
    int kvh = c >> 6, d = c & 63;
    int b   = row >> 11, t = row & 2047;
    float4 v = *(const float4*)(src + e0);
    float vv[4] = {v.x, v.y, v.z, v.w};
    __nv_bfloat16 h[4], l[4];
    #pragma unroll
    for (int j = 0; j < 4; j++) {
        h[j] = __float2bfloat16(vv[j]);
        l[j] = __float2bfloat16(vv[j] - __bfloat162float(h[j]));
    }
    size_t o = ((size_t)(b * KVH + kvh) * TT + t) * HD + d;
    *(uint2*)(dh + o) = make_uint2(pack_bf2(h[0], h[1]), pack_bf2(h[2], h[3]));
    *(uint2*)(dl + o) = make_uint2(pack_bf2(l[0], l[1]), pack_bf2(l[2], l[3]));
}

// ============================================================================
// Pre-pass: V fp32 [b*TT+t][NKV] -> TRANSPOSED [b,kvh][d][t] bf16 hi/lo.
// ============================================================================
__global__ void __launch_bounds__(256) convert_vT_kernel(
    const float* __restrict__ src,
    __nv_bfloat16* __restrict__ dh, __nv_bfloat16* __restrict__ dl)
{
    __shared__ float ts[32][33];
    const int bz  = blockIdx.z;
    const int b   = bz >> 3, kvh = bz & 7;
    const int t0  = blockIdx.x * 32, d0 = blockIdx.y * 32;
    const int tx  = threadIdx.x, ty = threadIdx.y;
    #pragma unroll
    for (int i = 0; i < 4; i++)
        ts[ty + i * 8][tx] = src[((size_t)b * TT + t0 + ty + i * 8) * NKV + kvh * HD + d0 + tx];
    __syncthreads();
    #pragma unroll
    for (int i = 0; i < 4; i++) {
        float v = ts[tx][ty + i * 8];
        __nv_bfloat16 h = __float2bfloat16(v);
        __nv_bfloat16 l = __float2bfloat16(v - __bfloat162float(h));
        size_t o = ((size_t)(b * KVH + kvh) * HD + d0 + ty + i * 8) * TT + t0 + tx;
        dh[o] = h;
        dl[o] = l;
    }
}

// ============================================================================
// 3xBF16 GEMM (UNCHANGED from R12/R14/R16, validated): cp.async double-buffered.
// ============================================================================
#define GPITCH 40
#define GARR   (128 * GPITCH * 2)
#define GSTAGE (4 * GARR)
#define GEMM_SMEM_BYTES (2 * GSTAGE)

__global__ void __launch_bounds__(256) gemm_bf3_cp_kernel(
    const __nv_bfloat16* __restrict__ Ah_g, const __nv_bfloat16* __restrict__ Al_g,
    const __nv_bfloat16* __restrict__ Bh_g, const __nv_bfloat16* __restrict__ Bl_g,
    const float* __restrict__ bias, float* __restrict__ C,
    int M, int N, int K)
{
    extern __shared__ char smg[];
    const uint32_t sb = smem_u32(smg);

    const int tid  = threadIdx.x;
    const int lane = tid & 31;
    const int w    = tid >> 5;
    const int g    = lane >> 2;
    const int t    = lane & 3;
    const int mw   = (w >> 1) * 32;
    const int nw   = (w & 1) * 64;
    const int bRow0 = blockIdx.y * 128;
    const int bCol0 = blockIdx.x * 128;

    const int r0s   = tid >> 2;
    const int seg0  = (tid & 3) * 8;
    const int r1s   = (tid + 256) >> 2;
    const int seg1  = seg0;

    float acc[2][8][4];
    #pragma unroll
    for (int i = 0; i < 2; i++)
        #pragma unroll
        for (int j = 0; j < 8; j++)
            #pragma unroll
            for (int q = 0; q < 4; q++) acc[i][j][q] = 0.f;

    const int niter = K >> 5;

    {
        const uint32_t s0 = sb;
        uint32_t so0 = s0 + (uint32_t)(r0s * 80 + seg0 * 2);
        uint32_t so1 = s0 + (uint32_t)(r1s * 80 + seg1 * 2);
        size_t ga0 = (size_t)(bRow0 + r0s) * K + seg0;
        size_t ga1 = (size_t)(bRow0 + r1s) * K + seg1;
        size_t gb0 = (size_t)(bCol0 + r0s) * K + seg0;
        size_t gb1 = (size_t)(bCol0 + r1s) * K + seg1;
        cp16(so0 + 0 * GARR, Ah_g + ga0);  cp16(so1 + 0 * GARR, Ah_g + ga1);
        cp16(so0 + 1 * GARR, Al_g + ga0);  cp16(so1 + 1 * GARR, Al_g + ga1);
        cp16(so0 + 2 * GARR, Bh_g + gb0);  cp16(so1 + 2 * GARR, Bh_g + gb1);
        cp16(so0 + 3 * GARR, Bl_g + gb0);  cp16(so1 + 3 * GARR, Bl_g + gb1);
        CP_COMMIT();
    }

    for (int it = 0; it < niter; it++) {
        const int st = it & 1;
        CP_WAIT0();
        __syncthreads();

        if (it + 1 < niter) {
            const uint32_t s0 = sb + (uint32_t)((st ^ 1) * GSTAGE);
            const int kof = (it + 1) * 32;
            uint32_t so0 = s0 + (uint32_t)(r0s * 80 + seg0 * 2);
            uint32_t so1 = s0 + (uint32_t)(r1s * 80 + seg1 * 2);
            size_t ga0 = (size_t)(bRow0 + r0s) * K + kof + seg0;
            size_t ga1 = (size_t)(bRow0 + r1s) * K + kof + seg1;
            size_t gb0 = (size_t)(bCol0 + r0s) * K + kof + seg0;
            size_t gb1 = (size_t)(bCol0 + r1s) * K + kof + seg1;
            cp16(so0 + 0 * GARR, Ah_g + ga0);  cp16(so1 + 0 * GARR, Ah_g + ga1);
            cp16(so0 + 1 * GARR, Al_g + ga0);  cp16(so1 + 1 * GARR, Al_g + ga1);
            cp16(so0 + 2 * GARR, Bh_g + gb0);  cp16(so1 + 2 * GARR, Bh_g + gb1);
            cp16(so0 + 3 * GARR, Bl_g + gb0);  cp16(so1 + 3 * GARR, Bl_g + gb1);
            CP_COMMIT();
        }

        const __nv_bfloat16* Ah = (const __nv_bfloat16*)(smg + st * GSTAGE + 0 * GARR);
        const __nv_bfloat16* Al = (const __nv_bfloat16*)(smg + st * GSTAGE + 1 * GARR);
        const __nv_bfloat16* Bh = (const __nv_bfloat16*)(smg + st * GSTAGE + 2 * GARR);
        const __nv_bfloat16* Bl = (const __nv_bfloat16*)(smg + st * GSTAGE + 3 * GARR);

        #pragma unroll
        for (int ks = 0; ks < 2; ks++) {
            const int kc = ks * 16 + 2 * t;
            uint32_t ah[2][4], al_[2][4];
            #pragma unroll
            for (int mt = 0; mt < 2; mt++) {
                int r = mw + mt * 16 + g;
                ah[mt][0]  = *(const uint32_t*)&Ah[r * GPITCH + kc];
                ah[mt][1]  = *(const uint32_t*)&Ah[(r + 8) * GPITCH + kc];
                ah[mt][2]  = *(const uint32_t*)&Ah[r * GPITCH + kc + 8];
                ah[mt][3]  = *(const uint32_t*)&Ah[(r + 8) * GPITCH + kc + 8];
                al_[mt][0] = *(const uint32_t*)&Al[r * GPITCH + kc];
                al_[mt][1] = *(const uint32_t*)&Al[(r + 8) * GPITCH + kc];
                al_[mt][2] = *(const uint32_t*)&Al[r * GPITCH + kc + 8];
                al_[mt][3] = *(const uint32_t*)&Al[(r + 8) * GPITCH + kc + 8];
            }
            #pragma unroll
            for (int nt = 0; nt < 8; nt++) {
                int n = nw + nt * 8 + g;
                uint32_t bh0 = *(const uint32_t*)&Bh[n * GPITCH + kc];
                uint32_t bh1 = *(const uint32_t*)&Bh[n * GPITCH + kc + 8];
                uint32_t bl0 = *(const uint32_t*)&Bl[n * GPITCH + kc];
                uint32_t bl1 = *(const uint32_t*)&Bl[n * GPITCH + kc + 8];
                #pragma unroll
                for (int mt = 0; mt < 2; mt++) {
                    MMA_BF16(acc[mt][nt], ah[mt][0], ah[mt][1], ah[mt][2], ah[mt][3], bh0, bh1);
                    MMA_BF16(acc[mt][nt], ah[mt][0], ah[mt][1], ah[mt][2], ah[mt][3], bl0, bl1);
                    MMA_BF16(acc[mt][nt], al_[mt][0], al_[mt][1], al_[mt][2], al_[mt][3], bh0, bh1);
                }
            }
        }
    }

    #pragma unroll
    for (int mt = 0; mt < 2; mt++) {
        #pragma unroll
        for (int nt = 0; nt < 8; nt++) {
            int row = bRow0 + mw + mt * 16 + g;
            int col = bCol0 + nw + nt * 8 + 2 * t;
            float b0v = bias[col], b1v = bias[col + 1];
            float2 o0 = {acc[mt][nt][0] + b0v, acc[mt][nt][1] + b1v};
            float2 o1 = {acc[mt][nt][2] + b0v, acc[mt][nt][3] + b1v};
            *(float2*)(C + (size_t)row * N + col)       = o0;
            *(float2*)(C + (size_t)(row + 8) * N + col) = o1;
        }
    }
}

// ============================================================================
// Flash attention v5: GQA-shared KV tiles.
// Block = 32 q-rows x 4 q-heads sharing one kv-head (grid 64 x KVH x BB).
// 8 warps = 4 heads x 2 m16-halves; each warp owns full rows (m16 x n64):
//   - softmax fully warp-local (shfl over 4-lane row group, no cross-warp)
//   - P stays in REGISTERS (score lane == PV A-fragment lane; no smem P)
//   - KV staged once per tile for all 4 heads (staging & gmem traffic / 4)
// 2 syncs/tile (staging only). Direct bf16 hi/lo output (R14-validated).
// ============================================================================
#define KP   72
#define BKH  0
#define BKL  (BKH + 64 * KP * 2)
#define BVH  (BKL + 64 * KP * 2)
#define BVL  (BVH + 64 * KP * 2)
#define ATT_SMEM_BYTES (BVL + 64 * KP * 2)

__global__ void __launch_bounds__(256, 2) attn_bf16_kernel(
    const float* __restrict__ Q,
    const __nv_bfloat16* __restrict__ Kbh, const __nv_bfloat16* __restrict__ Kbl,
    const __nv_bfloat16* __restrict__ Vbh, const __nv_bfloat16* __restrict__ Vbl,
    __nv_bfloat16* __restrict__ Oh, __nv_bfloat16* __restrict__ Ol)
{
    extern __shared__ char smc[];
    __nv_bfloat16* sKh = (__nv_bfloat16*)(smc + BKH);
    __nv_bfloat16* sKl = (__nv_bfloat16*)(smc + BKL);
    __nv_bfloat16* sVh = (__nv_bfloat16*)(smc + BVH);
    __nv_bfloat16* sVl = (__nv_bfloat16*)(smc + BVL);

    const int qi  = blockIdx.x;           // 32-row q tile
    const int kvh = blockIdx.y;           // kv head == q-head group
    const int b   = blockIdx.z;
    const int tid = threadIdx.x;
    const int q0  = qi * 32;

    const int lane = tid & 31;
    const int w    = tid >> 5;
    const int g    = lane >> 2;
    const int t    = lane & 3;
    const int hg   = w >> 1;              // head-in-group (0..3)
    const int mw   = (w & 1) * 16;        // m16 half of the 32-row tile
    const int h    = kvh * 4 + hg;        // global q head (h>>2 == kvh ✓)
    const int r0   = mw + g;
    const int r1   = r0 + 8;

    const __nv_bfloat16* kbh = Kbh + (size_t)(b * KVH + kvh) * TT * HD;
    const __nv_bfloat16* kbl = Kbl + (size_t)(b * KVH + kvh) * TT * HD;
    const __nv_bfloat16* vbh = Vbh + (size_t)(b * KVH + kvh) * HD * TT;
    const __nv_bfloat16* vbl = Vbl + (size_t)(b * KVH + kvh) * HD * TT;

    // ---- Q fragments: rows q0+r0 / q0+r1 of head h ----
    uint32_t qh[4][4], ql[4][4];
    {
        const float* q0p = Q + (size_t)(b * TT + q0 + r0) * DM + h * HD;
        const float* q1p = Q + (size_t)(b * TT + q0 + r1) * DM + h * HD;
        #pragma unroll
        for (int ks = 0; ks < 4; ks++) {
            const int kt = ks * 16;
            float v00 = q0p[kt + 2 * t],     v01 = q0p[kt + 2 * t + 1];
            float v10 = q1p[kt + 2 * t],     v11 = q1p[kt + 2 * t + 1];
            float v20 = q0p[kt + 2 * t + 8], v21 = q0p[kt + 2 * t + 9];
            float v30 = q1p[kt + 2 * t + 8], v31 = q1p[kt + 2 * t + 9];
            __nv_bfloat16 h00 = __float2bfloat16(v00), h01 = __float2bfloat16(v01);
            __nv_bfloat16 h10 = __float2bfloat16(v10), h11 = __float2bfloat16(v11);
            __nv_bfloat16 h20 = __float2bfloat16(v20), h21 = __float2bfloat16(v21);
            __nv_bfloat16 h30 = __float2bfloat16(v30), h31 = __float2bfloat16(v31);
            qh[ks][0] = pack_bf2(h00, h01);
            qh[ks][1] = pack_bf2(h10, h11);
            qh[ks][2] = pack_bf2(h20, h21);
            qh[ks][3] = pack_bf2(h30, h31);
            ql[ks][0] = pack_bf2(__float2bfloat16(v00 - __bfloat162float(h00)),
                                 __float2bfloat16(v01 - __bfloat162float(h01)));
            ql[ks][1] = pack_bf2(__float2bfloat16(v10 - __bfloat162float(h10)),
                                 __float2bfloat16(v11 - __bfloat162float(h11)));
            ql[ks][2] = pack_bf2(__float2bfloat16(v20 - __bfloat162float(h20)),
                                 __float2bfloat16(v21 - __bfloat162float(h21)));
            ql[ks][3] = pack_bf2(__float2bfloat16(v30 - __bfloat162float(h30)),
                                 __float2bfloat16(v31 - __bfloat162float(h31)));
        }
    }

    // per-thread softmax state (replicated across the 4 lanes of the row group)
    float row_m0 = -CUDART_INF_F, row_m1 = -CUDART_INF_F;
    float row_l0 = 0.f, row_l1 = 0.f;

    float o[8][4];                        // m16 x n64 output accum (32 regs)
    #pragma unroll
    for (int i = 0; i < 8; i++)
        #pragma unroll
        for (int j = 0; j < 4; j++) o[i][j] = 0.f;

    const int qg0 = q0 + r0, qg1 = q0 + r1;
    const int nkv = (q0 + 31) / 64 + 1;   // causal: need kv cols <= q0+31
    for (int it = 0; it < nkv; it++) {
        const int k0 = it * 64;
        if (it) __syncthreads();          // prev compute done -> safe to restage

        // ---- stage K/V tiles (shared by all 4 heads) ----
        #pragma unroll
        for (int i = tid; i < 512; i += 256) {
            const int r = i >> 3, seg = (i & 7) * 8;
            const size_t gk = (size_t)(k0 + r) * HD + seg;
            *(uint4*)&sKh[r * KP + seg] = *(const uint4*)(kbh + gk);
            *(uint4*)&sKl[r * KP + seg] = *(const uint4*)(kbl + gk);
            const size_t gv = (size_t)r * TT + k0 + seg;
            *(uint4*)&sVh[r * KP + seg] = *(const uint4*)(vbh + gv);
            *(uint4*)&sVl[r * KP + seg] = *(const uint4*)(vbl + gv);
        }
        __syncthreads();                  // tiles ready

        // ---- S = Q K^T (3xBF16), warp-owned m16 x n64 ----
        float sc[8][4];
        #pragma unroll
        for (int tn = 0; tn < 8; tn++)
            #pragma unroll
            for (int j = 0; j < 4; j++) sc[tn][j] = 0.f;

        #pragma unroll
        for (int ks = 0; ks < 4; ks++) {
            const int kt = ks * 16;
            #pragma unroll
            for (int tn = 0; tn < 8; tn++) {
                const int n = tn * 8 + g;
                uint32_t bh0 = *(const uint32_t*)&sKh[n * KP + kt + 2 * t];
                uint32_t bh1 = *(const uint32_t*)&sKh[n * KP + kt + 2 * t + 8];
                uint32_t bl0 = *(const uint32_t*)&sKl[n * KP + kt + 2 * t];
                uint32_t bl1 = *(const uint32_t*)&sKl[n * KP + kt + 2 * t + 8];
                MMA_BF16(sc[tn], qh[ks][0], qh[ks][1], qh[ks][2], qh[ks][3], bh0, bh1);
                MMA_BF16(sc[tn], qh[ks][0], qh[ks][1], qh[ks][2], qh[ks][3], bl0, bl1);
                MMA_BF16(sc[tn], ql[ks][0], ql[ks][1], ql[ks][2], ql[ks][3], bh0, bh1);
            }
        }
        #pragma unroll
        for (int tn = 0; tn < 8; tn++) {
            const int col = tn * 8 + 2 * t;
            const int kg0 = k0 + col, kg1 = kg0 + 1;
            sc[tn][0] = (kg0 <= qg0) ? sc[tn][0] * 0.125f : -CUDART_INF_F;
            sc[tn][1] = (kg1 <= qg0) ? sc[tn][1] * 0.125f : -CUDART_INF_F;
            sc[tn][2] = (kg0 <= qg1) ? sc[tn][2] * 0.125f : -CUDART_INF_F;
            sc[tn][3] = (kg1 <= qg1) ? sc[tn][3] * 0.125f : -CUDART_INF_F;
        }

        // ---- warp-local row max (shfl over the 4-lane row group) ----
        float m0 = sc[0][0], m1 = sc[0][2];
        #pragma unroll
        for (int tn = 0; tn < 8; tn++) {
            m0 = fmaxf(m0, fmaxf(sc[tn][0], sc[tn][1]));
            m1 = fmaxf(m1, fmaxf(sc[tn][2], sc[tn][3]));
        }
        m0 = fmaxf(m0, __shfl_xor_sync(0xffffffffu, m0, 1));
        m0 = fmaxf(m0, __shfl_xor_sync(0xffffffffu, m0, 2));
        m1 = fmaxf(m1, __shfl_xor_sync(0xffffffffu, m1, 1));
        m1 = fmaxf(m1, __shfl_xor_sync(0xffffffffu, m1, 2));

        const float M0 = fmaxf(row_m0, m0);
        const float M1 = fmaxf(row_m1, m1);
        const float a0 = __expf(row_m0 - M0);
        const float a1 = __expf(row_m1 - M1);
        row_m0 = M0;
        row_m1 = M1;

        // ---- exp + bf16 split entirely in registers (P never hits smem) ----
        uint32_t ph0[8], ph1[8], pl0[8], pl1[8];
        float ls0 = 0.f, ls1 = 0.f;
        #pragma unroll
        for (int tn = 0; tn < 8; tn++) {
            float e00 = __expf(sc[tn][0] - M0);
            float e01 = __expf(sc[tn][1] - M0);
            float e10 = __expf(sc[tn][2] - M1);
            float e11 = __expf(sc[tn][3] - M1);
            ls0 += e00 + e01;
            ls1 += e10 + e11;
            __nv_bfloat16 h00 = __float2bfloat16(e00), h01 = __float2bfloat16(e01);
            __nv_bfloat16 h10 = __float2bfloat16(e10), h11 = __float2bfloat16(e11);
            ph0[tn] = pack_bf2(h00, h01);
            ph1[tn] = pack_bf2(h10, h11);
            pl0[tn] = pack_bf2(__float2bfloat16(e00 - __bfloat162float(h00)),
                               __float2bfloat16(e01 - __bfloat162float(h01)));
            pl1[tn] = pack_bf2(__float2bfloat16(e10 - __bfloat162float(h10)),
                               __float2bfloat16(e11 - __bfloat162float(h11)));
        }
        ls0 += __shfl_xor_sync(0xffffffffu, ls0, 1);
        ls0 += __shfl_xor_sync(0xffffffffu, ls0, 2);
        ls1 += __shfl_xor_sync(0xffffffffu, ls1, 1);
        ls1 += __shfl_xor_sync(0xffffffffu, ls1, 2);
        row_l0 = row_l0 * a0 + ls0;
        row_l1 = row_l1 * a1 + ls1;

        // ---- O rescale + O += P @ V (3xBF16, register A-fragments) ----
        #pragma unroll
        for (int tn = 0; tn < 8; tn++) {
            o[tn][0] *= a0; o[tn][1] *= a0;
            o[tn][2] *= a1; o[tn][3] *= a1;
        }
        #pragma unroll
        for (int ks = 0; ks < 4; ks++) {
            const int kt = ks * 16;
            // A fragment: cols kt+2t (tn=2ks) and kt+8+2t (tn=2ks+1) — same lane!
            const uint32_t pa0h = ph0[2 * ks],     pa1h = ph1[2 * ks];
            const uint32_t pa2h = ph0[2 * ks + 1], pa3h = ph1[2 * ks + 1];
            const uint32_t pa0l = pl0[2 * ks],     pa1l = pl1[2 * ks];
            const uint32_t pa2l = pl0[2 * ks + 1], pa3l = pl1[2 * ks + 1];
            #pragma unroll
            for (int tn = 0; tn < 8; tn++) {
                const int n = tn * 8 + g;
                uint32_t vh0 = *(const uint32_t*)&sVh[n * KP + kt + 2 * t];
                uint32_t vh1 = *(const uint32_t*)&sVh[n * KP + kt + 2 * t + 8];
                uint32_t vl0 = *(const uint32_t*)&sVl[n * KP + kt + 2 * t];
                uint32_t vl1 = *(const uint32_t*)&sVl[n * KP + kt + 2 * t + 8];
                MMA_BF16(o[tn], pa0h, pa1h, pa2h, pa3h, vh0, vh1);
                MMA_BF16(o[tn], pa0h, pa1h, pa2h, pa3h, vl0, vl1);
                MMA_BF16(o[tn], pa0l, pa1l, pa2l, pa3l, vh0, vh1);
            }
        }
    }

    // ---- normalize + write bf16 hi/lo output [B,T,QH*HD] ----
    {
        const float inv0 = 1.0f / row_l0;
        const float inv1 = 1.0f / row_l1;
        const size_t row0 = (size_t)(b * TT + q0 + r0) * DM + h * HD;
        const size_t row1 = (size_t)(b * TT + q0 + r1) * DM + h * HD;
        #pragma unroll
        for (int tn = 0; tn < 8; tn++) {
            const int c = tn * 8 + 2 * t;
            float v00 = o[tn][0] * inv0, v01 = o[tn][1] * inv0;
            float v10 = o[tn][2] * inv1, v11 = o[tn][3] * inv1;
            __nv_bfloat16 h00 = __float2bfloat16(v00), h01 = __float2bfloat16(v01);
            __nv_bfloat16 h10 = __float2bfloat16(v10), h11 = __float2bfloat16(v11);
            *(uint32_t*)(Oh + row0 + c) = pack_bf2(h00, h01);
            *(uint32_t*)(Oh + row1 + c) = pack_bf2(h10, h11);
            *(uint32_t*)(Ol + row0 + c) =
                pack_bf2(__float2bfloat16(v00 - __bfloat162float(h00)),
                         __float2bfloat16(v01 - __bfloat162float(h01)));
            *(uint32_t*)(Ol + row1 + c) =
                pack_bf2(__float2bfloat16(v10 - __bfloat162float(h10)),
                         __float2bfloat16(v11 - __bfloat162float(h11)));
        }
    }
}

// ============================================================================
// kernel_launch: graph-capturable launches, no allocations, no syncs.
// ============================================================================
extern "C" void kernel_launch(void* const* d_in, const int* in_sizes, int n_in,
                              void* d_out, int out_size)
{
    const float* x  = (const float*)d_in[0];
    const float* Wq = (const float*)d_in[1];
    const float* bq = (const float*)d_in[2];
    const float* Wk = (const float*)d_in[3];
    const float* bk = (const float*)d_in[4];
    const float* Wv = (const float*)d_in[5];
    const float* bv = (const float*)d_in[6];
    const float* Wo = (const float*)d_in[7];
    const float* bo = (const float*)d_in[8];
    float* out = (float*)d_out;

    float *q, *k, *v;
    cudaGetSymbolAddress((void**)&q, g_q);
    cudaGetSymbolAddress((void**)&k, g_k);
    cudaGetSymbolAddress((void**)&v, g_v);
    __nv_bfloat16 *wqh, *wql, *wkh, *wkl, *wvh, *wvl, *woh, *wol;
    cudaGetSymbolAddress((void**)&wqh, g_wqh);
    cudaGetSymbolAddress((void**)&wql, g_wql);
    cudaGetSymbolAddress((void**)&wkh, g_wkh);
    cudaGetSymbolAddress((void**)&wkl, g_wkl);
    cudaGetSymbolAddress((void**)&wvh, g_wvh);
    cudaGetSymbolAddress((void**)&wvl, g_wvl);
    cudaGetSymbolAddress((void**)&woh, g_woh);
    cudaGetSymbolAddress((void**)&wol, g_wol);
    __nv_bfloat16 *xh, *xl, *ath, *atl;
    cudaGetSymbolAddress((void**)&xh,  g_xh);
    cudaGetSymbolAddress((void**)&xl,  g_xl);
    cudaGetSymbolAddress((void**)&ath, g_ath);
    cudaGetSymbolAddress((void**)&atl, g_atl);
    __nv_bfloat16 *kbh, *kbl, *vbh, *vbl;
    cudaGetSymbolAddress((void**)&kbh, g_kbh);
    cudaGetSymbolAddress((void**)&kbl, g_kbl);
    cudaGetSymbolAddress((void**)&vbh, g_vbh);
    cudaGetSymbolAddress((void**)&vbl, g_vbl);

    cudaFuncSetAttribute(attn_bf16_kernel,
                         cudaFuncAttributeMaxDynamicSharedMemorySize, ATT_SMEM_BYTES);
    cudaFuncSetAttribute(gemm_bf3_cp_kernel,
                         cudaFuncAttributeMaxDynamicSharedMemorySize, GEMM_SMEM_BYTES);

    dim3 cblk(32, 8);
    dim3 blk(256);

    // weight pre-pass
    convert_w_kernel<<<dim3(DM / 32, DM / 32),  cblk>>>(Wq, wqh, wql, DM, DM);
    convert_w_kernel<<<dim3(NKV / 32, DM / 32), cblk>>>(Wk, wkh, wkl, DM, NKV);
    convert_w_kernel<<<dim3(NKV / 32, DM / 32), cblk>>>(Wv, wvh, wvl, DM, NKV);
    convert_w_kernel<<<dim3(DM / 32, DM / 32),  cblk>>>(Wo, woh, wol, DM, DM);

    // x pre-split
    convert_a_kernel<<<(MROWS * DM / 4) / 256, blk>>>(x, xh, xl);

    // projections (3xBF16, cp.async double-buffered)
    gemm_bf3_cp_kernel<<<dim3(DM / 128, MROWS / 128), blk, GEMM_SMEM_BYTES>>>(
        xh, xl, wqh, wql, bq, q, MROWS, DM, DM);
    gemm_bf3_cp_kernel<<<dim3(NKV / 128, MROWS / 128), blk, GEMM_SMEM_BYTES>>>(
        xh, xl, wkh, wkl, bk, k, MROWS, NKV, DM);
    gemm_bf3_cp_kernel<<<dim3(NKV / 128, MROWS / 128), blk, GEMM_SMEM_BYTES>>>(
        xh, xl, wvh, wvl, bv, v, MROWS, NKV, DM);

    // K/V pre-split for attention
    convert_k_kernel<<<(MROWS * NKV / 4) / 256, blk>>>(k, kbh, kbl);
    convert_vT_kernel<<<dim3(TT / 32, HD / 32, BB * KVH), cblk>>>(v, vbh, vbl);

    // causal GQA attention (shared-KV, warp-local softmax, register P)
    attn_bf16_kernel<<<dim3(TT / 32, KVH, BB), blk, ATT_SMEM_BYTES>>>(
        q, kbh, kbl, vbh, vbl, ath, atl);

    // output projection
    gemm_bf3_cp_kernel<<<dim3(DM / 128, MROWS / 128), blk, GEMM_SMEM_BYTES>>>(
        ath, atl, woh, wol, bo, out, MROWS, DM, DM);
}